// round 2
// baseline (speedup 1.0000x reference)
#include <cuda_runtime.h>
#include <cstdint>

// Problem constants (fixed by setup_inputs)
#define BB 4
#define CC 64
#define HH 192
#define WW 192
#define HWW (HH*WW)
#define DG 8
#define CG 8          // CC / DG
#define KK 9
#define NPIX (BB*HWW) // 147456

#define TW 32
#define TH 8
#define NTHR 256
#define CIN_CHUNK 8

// ---------------- packed f32x2 helpers (sm_103a FFMA2 path) ----------------
typedef unsigned long long f32x2_t;

__device__ __forceinline__ f32x2_t pack2(float lo, float hi) {
    f32x2_t r;
    asm("mov.b64 %0, {%1, %2};" : "=l"(r) : "f"(lo), "f"(hi));
    return r;
}
__device__ __forceinline__ void unpack2(f32x2_t v, float& lo, float& hi) {
    asm("mov.b64 {%0, %1}, %2;" : "=f"(lo), "=f"(hi) : "l"(v));
}
// d = a*b + d   (two independent fp32 FMAs in one instruction)
__device__ __forceinline__ void fma2(f32x2_t& d, f32x2_t a, f32x2_t b) {
    asm("fma.rn.f32x2 %0, %1, %2, %3;" : "=l"(d) : "l"(a), "l"(b), "l"(d));
}

// ---------------- scratch (static device globals; no allocs) ----------------
__device__ float g_buf1[(size_t)CC * NPIX];
__device__ float g_buf2[(size_t)CC * NPIX];
__device__ float g_buf3[(size_t)CC * NPIX];
__device__ float g_buf4[(size_t)CC * NPIX];
__device__ float g_off [(size_t)216 * NPIX];
__device__ float g_xt  [(size_t)CC * NPIX];   // x transposed to (B, DG, H, W, CG)

// ---------------- direct 3x3 conv, stride 1, pad 1 ----------------
// in0: (B, C0, H, W). in1 (optional): (B, Cin-C0, H, W) -> logical cat on channel dim.
// wgt: (Cout, Cin, 3, 3), bias: (Cout).
// Each block computes a TWxTH pixel tile for OCB output channels (gridDim.z = B * Cout/OCB).
template<int OCB, bool LRELU>
__global__ __launch_bounds__(NTHR, 2)
void conv3x3_kernel(const float* __restrict__ in0,
                    const float* __restrict__ in1, int C0, int Cin,
                    const float* __restrict__ wgt,
                    const float* __restrict__ bias,
                    float* __restrict__ out, int Cout)
{
    __shared__ __align__(16) float sIn[CIN_CHUNK][TH + 2][TW + 2];
    __shared__ __align__(16) float sW[CIN_CHUNK * 9 * OCB];

    const int nOcb  = Cout / OCB;
    const int b     = blockIdx.z / nOcb;
    const int ocb   = blockIdx.z % nOcb;
    const int ocBase = ocb * OCB;

    const int tid = threadIdx.x;
    const int tx  = tid % TW;
    const int ty  = tid / TW;

    const int gx0 = blockIdx.x * TW - 1;
    const int gy0 = blockIdx.y * TH - 1;

    f32x2_t acc2[OCB / 2];
#pragma unroll
    for (int i = 0; i < OCB / 2; ++i) acc2[i] = pack2(0.f, 0.f);

    for (int cb = 0; cb < Cin; cb += CIN_CHUNK) {
        __syncthreads();
        // load input tile (halo'd) for CIN_CHUNK channels
        for (int i = tid; i < CIN_CHUNK * (TH + 2) * (TW + 2); i += NTHR) {
            int col = i % (TW + 2);
            int r2  = i / (TW + 2);
            int row = r2 % (TH + 2);
            int ci  = r2 / (TH + 2);
            int gy = gy0 + row, gx = gx0 + col;
            int c  = cb + ci;
            float v = 0.f;
            if (gy >= 0 && gy < HH && gx >= 0 && gx < WW) {
                const float* src = (c < C0)
                    ? in0 + ((size_t)(b * C0 + c)) * HWW
                    : in1 + ((size_t)(b * (Cin - C0) + (c - C0))) * HWW;
                v = src[gy * WW + gx];
            }
            sIn[ci][row][col] = v;
        }
        // load weights for this cin chunk: sW[(ci*9+k)*OCB + oc]
        for (int i = tid; i < CIN_CHUNK * 9 * OCB; i += NTHR) {
            int oc = i % OCB;
            int r  = i / OCB;
            int k  = r % 9;
            int ci = r / 9;
            sW[i] = wgt[(size_t)(ocBase + oc) * (Cin * 9) + (cb + ci) * 9 + k];
        }
        __syncthreads();

        for (int ci = 0; ci < CIN_CHUNK; ++ci) {
            float v[9];
#pragma unroll
            for (int kh = 0; kh < 3; ++kh)
#pragma unroll
                for (int kw = 0; kw < 3; ++kw)
                    v[kh * 3 + kw] = sIn[ci][ty + kh][tx + kw];

            const ulonglong2* wrow =
                reinterpret_cast<const ulonglong2*>(&sW[ci * 9 * OCB]);
#pragma unroll
            for (int k = 0; k < 9; ++k) {
                f32x2_t vv = pack2(v[k], v[k]);
#pragma unroll
                for (int o4 = 0; o4 < OCB / 4; ++o4) {
                    ulonglong2 w = wrow[k * (OCB / 4) + o4];   // 4 consecutive oc weights
                    fma2(acc2[o4 * 2 + 0], w.x, vv);
                    fma2(acc2[o4 * 2 + 1], w.y, vv);
                }
            }
        }
    }

    const int gy = blockIdx.y * TH + ty;
    const int gx = blockIdx.x * TW + tx;
#pragma unroll
    for (int o2 = 0; o2 < OCB / 2; ++o2) {
        float r0, r1;
        unpack2(acc2[o2], r0, r1);
        r0 += __ldg(&bias[ocBase + 2 * o2 + 0]);
        r1 += __ldg(&bias[ocBase + 2 * o2 + 1]);
        if (LRELU) {
            r0 = (r0 >= 0.f) ? r0 : 0.1f * r0;
            r1 = (r1 >= 0.f) ? r1 : 0.1f * r1;
        }
        size_t pix = (size_t)gy * WW + gx;
        out[((size_t)(b * Cout + ocBase + 2 * o2 + 0)) * HWW + pix] = r0;
        out[((size_t)(b * Cout + ocBase + 2 * o2 + 1)) * HWW + pix] = r1;
    }
}

// ---------------- transpose x: (B,64,H,W) -> (B,DG,H,W,CG) ----------------
__global__ void transpose_kernel(const float* __restrict__ in, float* __restrict__ out)
{
    int idx = blockIdx.x * blockDim.x + threadIdx.x;   // over B*DG*H*W
    if (idx >= BB * DG * HWW) return;
    int x = idx % WW;
    int r = idx / WW;
    int y = r % HH; r /= HH;
    int dg = r % DG;
    int b  = r / DG;
    const float* src = in + ((size_t)(b * CC + dg * CG)) * HWW + y * WW + x;
    float4 v0, v1;
    v0.x = src[0 * HWW]; v0.y = src[1 * HWW]; v0.z = src[2 * HWW]; v0.w = src[3 * HWW];
    v1.x = src[4 * HWW]; v1.y = src[5 * HWW]; v1.z = src[6 * HWW]; v1.w = src[7 * HWW];
    float4* dst = reinterpret_cast<float4*>(out + (size_t)idx * 8);
    dst[0] = v0; dst[1] = v1;
}

// ---------------- modulated deformable conv (DCNv2) ----------------
// xt:  (B, DG, H, W, CG) channel-last-transposed input
// off: (B, 216, H, W) raw conv output; ch [0,144)=offsets (dg*18+2k+{y,x}), [144,216)=mask logits
// wgt: (64, 64, 3, 3) -> w[o][dg*8+cg][kh][kw]
template<bool LRELU>
__global__ __launch_bounds__(NTHR, 2)
void dcn_kernel(const float* __restrict__ xt,
                const float* __restrict__ off,
                const float* __restrict__ wgt,
                const float* __restrict__ bias,
                float* __restrict__ out)
{
    __shared__ __align__(16) float sW[CG * 9 * 64];   // [(cg*9+k)*64 + oc]

    const int tid = threadIdx.x;
    const int tx  = tid % TW;
    const int ty  = tid / TW;
    const int b   = blockIdx.z;
    const int gx  = blockIdx.x * TW + tx;
    const int gy  = blockIdx.y * TH + ty;

    f32x2_t acc2[32];
#pragma unroll
    for (int i = 0; i < 32; ++i) acc2[i] = pack2(0.f, 0.f);

    const float* offB = off + (size_t)b * 216 * HWW + gy * WW + gx;

    for (int dg = 0; dg < DG; ++dg) {
        __syncthreads();
        for (int i = tid; i < CG * 9 * 64; i += NTHR) {
            int oc = i % 64;
            int r  = i / 64;
            int k  = r % 9;
            int cg = r / 9;
            sW[i] = wgt[(size_t)oc * (CC * 9) + (dg * CG + cg) * 9 + k];
        }
        __syncthreads();

        const float* xdg = xt + ((size_t)(b * DG + dg)) * HWW * CG;

        for (int k = 0; k < 9; ++k) {
            float dy = offB[(size_t)(dg * 18 + 2 * k + 0) * HWW];
            float dx = offB[(size_t)(dg * 18 + 2 * k + 1) * HWW];
            float ml = offB[(size_t)(144 + dg * 9 + k) * HWW];
            float m  = 1.f / (1.f + __expf(-ml));

            float py = (float)gy - 1.f + (float)(k / 3) + dy;
            float px = (float)gx - 1.f + (float)(k % 3) + dx;
            float y0f = floorf(py), x0f = floorf(px);
            float wy = py - y0f, wx = px - x0f;
            int y0 = (int)y0f, x0 = (int)x0f;

            float cw00 = (1.f - wy) * (1.f - wx);
            float cw01 = (1.f - wy) * wx;
            float cw10 = wy * (1.f - wx);
            float cw11 = wy * wx;

            f32x2_t sv2[4];
#pragma unroll
            for (int i = 0; i < 4; ++i) sv2[i] = pack2(0.f, 0.f);

#pragma unroll
            for (int cy = 0; cy < 2; ++cy) {
#pragma unroll
                for (int cx = 0; cx < 2; ++cx) {
                    int yy = y0 + cy, xx = x0 + cx;
                    float cwv = (cy == 0) ? ((cx == 0) ? cw00 : cw01)
                                          : ((cx == 0) ? cw10 : cw11);
                    if (yy >= 0 && yy < HH && xx >= 0 && xx < WW) {
                        const ulonglong2* p = reinterpret_cast<const ulonglong2*>(
                            xdg + ((size_t)yy * WW + xx) * CG);
                        ulonglong2 a = __ldg(&p[0]);   // ch 0..3
                        ulonglong2 c = __ldg(&p[1]);   // ch 4..7
                        f32x2_t cw2 = pack2(cwv, cwv);
                        fma2(sv2[0], a.x, cw2);
                        fma2(sv2[1], a.y, cw2);
                        fma2(sv2[2], c.x, cw2);
                        fma2(sv2[3], c.y, cw2);
                    }
                }
            }

            float sv[8];
#pragma unroll
            for (int i = 0; i < 4; ++i) unpack2(sv2[i], sv[2 * i], sv[2 * i + 1]);

#pragma unroll
            for (int cg = 0; cg < CG; ++cg) {
                float s = sv[cg] * m;
                f32x2_t ss = pack2(s, s);
                const ulonglong2* wr =
                    reinterpret_cast<const ulonglong2*>(&sW[(cg * 9 + k) * 64]);
#pragma unroll
                for (int o4 = 0; o4 < 16; ++o4) {
                    ulonglong2 w = wr[o4];
                    fma2(acc2[o4 * 2 + 0], w.x, ss);
                    fma2(acc2[o4 * 2 + 1], w.y, ss);
                }
            }
        }
    }

#pragma unroll
    for (int o2 = 0; o2 < 32; ++o2) {
        float r0, r1;
        unpack2(acc2[o2], r0, r1);
        r0 += __ldg(&bias[2 * o2 + 0]);
        r1 += __ldg(&bias[2 * o2 + 1]);
        if (LRELU) {
            r0 = (r0 >= 0.f) ? r0 : 0.1f * r0;
            r1 = (r1 >= 0.f) ? r1 : 0.1f * r1;
        }
        size_t pix = (size_t)gy * WW + gx;
        out[((size_t)(b * CC + 2 * o2 + 0)) * HWW + pix] = r0;
        out[((size_t)(b * CC + 2 * o2 + 1)) * HWW + pix] = r1;
    }
}

// ---------------- launch ----------------
extern "C" void kernel_launch(void* const* d_in, const int* in_sizes, int n_in,
                              void* d_out, int out_size)
{
    const float* nbr     = (const float*)d_in[0];
    const float* ref     = (const float*)d_in[1];
    const float* oc1_w   = (const float*)d_in[2];
    const float* oc1_b   = (const float*)d_in[3];
    const float* oc2_w   = (const float*)d_in[4];
    const float* oc2_b   = (const float*)d_in[5];
    const float* d1off_w = (const float*)d_in[6];
    const float* d1off_b = (const float*)d_in[7];
    const float* dcn1_w  = (const float*)d_in[8];
    const float* dcn1_b  = (const float*)d_in[9];
    const float* fc_w    = (const float*)d_in[10];
    const float* fc_b    = (const float*)d_in[11];
    const float* cas1_w  = (const float*)d_in[12];
    const float* cas1_b  = (const float*)d_in[13];
    const float* cas2_w  = (const float*)d_in[14];
    const float* cas2_b  = (const float*)d_in[15];
    const float* cdoff_w = (const float*)d_in[16];
    const float* cdoff_b = (const float*)d_in[17];
    const float* casd_w  = (const float*)d_in[18];
    const float* casd_b  = (const float*)d_in[19];
    float* outp = (float*)d_out;

    float *buf1, *buf2, *buf3, *buf4, *offb, *xt;
    cudaGetSymbolAddress((void**)&buf1, g_buf1);
    cudaGetSymbolAddress((void**)&buf2, g_buf2);
    cudaGetSymbolAddress((void**)&buf3, g_buf3);
    cudaGetSymbolAddress((void**)&buf4, g_buf4);
    cudaGetSymbolAddress((void**)&offb, g_off);
    cudaGetSymbolAddress((void**)&xt,   g_xt);

    dim3 gC(WW / TW, HH / TH, BB);         // 64-out convs / dcn
    dim3 gO(WW / TW, HH / TH, BB * 3);     // 216-out convs (3 blocks of 72)
    int tpGrid = (BB * DG * HWW + NTHR - 1) / NTHR;

    // 1) offset = lrelu(conv(cat(nbr, ref), oc1))
    conv3x3_kernel<64, true ><<<gC, NTHR>>>(nbr, ref, CC, 2 * CC, oc1_w, oc1_b, buf1, 64);
    // 2) offset = lrelu(conv(offset, oc2))
    conv3x3_kernel<64, true ><<<gC, NTHR>>>(buf1, nullptr, CC, CC, oc2_w, oc2_b, buf2, 64);
    // 3) dcn1 offset/mask conv (216 ch, raw)
    conv3x3_kernel<72, false><<<gO, NTHR>>>(buf2, nullptr, CC, CC, d1off_w, d1off_b, offb, 216);
    // 4) transpose nbr for gathers
    transpose_kernel<<<tpGrid, NTHR>>>(nbr, xt);
    // 5) feat = dcn(nbr, off)
    dcn_kernel<false><<<gC, NTHR>>>(xt, offb, dcn1_w, dcn1_b, buf3);
    // 6) feat = conv(feat, fc)
    conv3x3_kernel<64, false><<<gC, NTHR>>>(buf3, nullptr, CC, CC, fc_w, fc_b, buf4, 64);
    // 7) offset = lrelu(conv(cat(feat, ref), cas1))
    conv3x3_kernel<64, true ><<<gC, NTHR>>>(buf4, ref, CC, 2 * CC, cas1_w, cas1_b, buf1, 64);
    // 8) offset = lrelu(conv(offset, cas2))
    conv3x3_kernel<64, true ><<<gC, NTHR>>>(buf1, nullptr, CC, CC, cas2_w, cas2_b, buf2, 64);
    // 9) casd offset/mask conv
    conv3x3_kernel<72, false><<<gO, NTHR>>>(buf2, nullptr, CC, CC, cdoff_w, cdoff_b, offb, 216);
    // 10) transpose feat
    transpose_kernel<<<tpGrid, NTHR>>>(buf4, xt);
    // 11) out = lrelu(dcn(feat, off))
    dcn_kernel<true><<<gC, NTHR>>>(xt, offb, casd_w, casd_b, outp);

    (void)in_sizes; (void)n_in; (void)out_size;
}

// round 3
// speedup vs baseline: 1.5948x; 1.5948x over previous
#include <cuda_runtime.h>
#include <cstdint>

// Problem constants (fixed by setup_inputs)
#define BB 4
#define CC 64
#define HH 192
#define WW 192
#define HWW (HH*WW)
#define DG 8
#define CG 8          // CC / DG
#define NPIX (BB*HWW) // 147456

#define TW 32
#define TH 8
#define NTHR 256
#define CHUNK 8       // input channels per smem stage

// ---------------- scratch (static device globals; no allocs) ----------------
__device__ float g_buf1[(size_t)CC * NPIX];
__device__ float g_buf2[(size_t)CC * NPIX];
__device__ float g_buf3[(size_t)CC * NPIX];
__device__ float g_buf4[(size_t)CC * NPIX];
__device__ float g_off [(size_t)216 * NPIX];
__device__ float g_xt  [(size_t)CC * NPIX];   // x transposed to (B, DG, H, W, CG)

// ---------------- direct 3x3 conv, stride 1, pad 1, double-buffered ----------------
// in0: (B, C0, H, W). in1 (optional): (B, Cin-C0, H, W) -> logical cat on channel dim.
// wgt: (Cout, Cin, 3, 3), bias: (Cout).
// Each block computes a TWxTH pixel tile for OCB output channels.
// Dynamic smem: sIn[2][CHUNK][TH+2][TW+2] then sW[2][CHUNK*9*OCB].
template<int OCB, bool LRELU>
__global__ __launch_bounds__(NTHR, 2)
void conv3x3_kernel(const float* __restrict__ in0,
                    const float* __restrict__ in1, int C0, int Cin,
                    const float* __restrict__ wgt,
                    const float* __restrict__ bias,
                    float* __restrict__ out, int Cout)
{
    extern __shared__ __align__(16) float smem[];
    const int IN_STAGE = CHUNK * (TH + 2) * (TW + 2);   // 2720
    const int W_STAGE  = CHUNK * 9 * OCB;
    float* sIn = smem;                    // [2][IN_STAGE]
    float* sW  = smem + 2 * IN_STAGE;     // [2][W_STAGE]

    const int nOcb  = Cout / OCB;
    const int b     = blockIdx.z / nOcb;
    const int ocb   = blockIdx.z % nOcb;
    const int ocBase = ocb * OCB;

    const int tid = threadIdx.x;
    const int tx  = tid % TW;
    const int ty  = tid / TW;

    const int gx0 = blockIdx.x * TW - 1;
    const int gy0 = blockIdx.y * TH - 1;

    float acc[OCB];
#pragma unroll
    for (int i = 0; i < OCB; ++i) acc[i] = 0.f;

    // ---- stage loader ----
    auto load_stage = [&](int cb, int sel) {
        float* dIn = sIn + sel * IN_STAGE;
        float* dW  = sW  + sel * W_STAGE;
        // whole chunk comes from one tensor (cb is a multiple of CHUNK, C0 too)
        const float* src = (cb < C0)
            ? in0 + ((size_t)(b * C0 + cb)) * HWW
            : in1 + ((size_t)(b * (Cin - C0) + (cb - C0))) * HWW;
        for (int i = tid; i < IN_STAGE; i += NTHR) {
            int col = i % (TW + 2);
            int r2  = i / (TW + 2);
            int row = r2 % (TH + 2);
            int ci  = r2 / (TH + 2);
            int gy = gy0 + row, gx = gx0 + col;
            float v = 0.f;
            if (gy >= 0 && gy < HH && gx >= 0 && gx < WW)
                v = src[(size_t)ci * HWW + gy * WW + gx];
            dIn[i] = v;
        }
        for (int i = tid; i < W_STAGE; i += NTHR) {
            int oc = i % OCB;
            int r  = i / OCB;
            int k  = r % 9;
            int ci = r / 9;
            dW[i] = wgt[(size_t)(ocBase + oc) * (Cin * 9) + (cb + ci) * 9 + k];
        }
    };

    load_stage(0, 0);
    __syncthreads();

    int sel = 0;
    for (int cb = 0; cb < Cin; cb += CHUNK) {
        if (cb + CHUNK < Cin) load_stage(cb + CHUNK, sel ^ 1);

        const float* cIn = sIn + sel * IN_STAGE;
        const float* cW  = sW  + sel * W_STAGE;

        for (int ci = 0; ci < CHUNK; ++ci) {
            float v[9];
#pragma unroll
            for (int kh = 0; kh < 3; ++kh)
#pragma unroll
                for (int kw = 0; kw < 3; ++kw)
                    v[kh * 3 + kw] = cIn[(ci * (TH + 2) + ty + kh) * (TW + 2) + tx + kw];

            const float4* wrow = reinterpret_cast<const float4*>(cW + ci * 9 * OCB);
#pragma unroll
            for (int k = 0; k < 9; ++k) {
#pragma unroll
                for (int o4 = 0; o4 < OCB / 4; ++o4) {
                    float4 w = wrow[k * (OCB / 4) + o4];
                    acc[o4 * 4 + 0] += w.x * v[k];
                    acc[o4 * 4 + 1] += w.y * v[k];
                    acc[o4 * 4 + 2] += w.z * v[k];
                    acc[o4 * 4 + 3] += w.w * v[k];
                }
            }
        }
        __syncthreads();
        sel ^= 1;
    }

    const int gy = blockIdx.y * TH + ty;
    const int gx = blockIdx.x * TW + tx;
#pragma unroll
    for (int oc = 0; oc < OCB; ++oc) {
        float r = acc[oc] + __ldg(&bias[ocBase + oc]);
        if (LRELU) r = (r >= 0.f) ? r : 0.1f * r;
        out[((size_t)(b * Cout + ocBase + oc)) * HWW + gy * WW + gx] = r;
    }
}

// ---------------- transpose x: (B,64,H,W) -> (B,DG,H,W,CG) ----------------
__global__ void transpose_kernel(const float* __restrict__ in, float* __restrict__ out)
{
    int idx = blockIdx.x * blockDim.x + threadIdx.x;   // over B*DG*H*W
    if (idx >= BB * DG * HWW) return;
    int x = idx % WW;
    int r = idx / WW;
    int y = r % HH; r /= HH;
    int dg = r % DG;
    int b  = r / DG;
    const float* src = in + ((size_t)(b * CC + dg * CG)) * HWW + y * WW + x;
    float4 v0, v1;
    v0.x = src[0 * HWW]; v0.y = src[1 * HWW]; v0.z = src[2 * HWW]; v0.w = src[3 * HWW];
    v1.x = src[4 * HWW]; v1.y = src[5 * HWW]; v1.z = src[6 * HWW]; v1.w = src[7 * HWW];
    float4* dst = reinterpret_cast<float4*>(out + (size_t)idx * 8);
    dst[0] = v0; dst[1] = v1;
}

// ---------------- modulated deformable conv (DCNv2), double-buffered weights ----------------
// xt:  (B, DG, H, W, CG) channel-last-transposed input
// off: (B, 216, H, W) raw conv output; ch [0,144)=offsets (dg*18+2k+{y,x}), [144,216)=mask logits
// wgt: (64, 64, 3, 3) -> w[o][dg*8+cg][kh][kw]
template<bool LRELU>
__global__ __launch_bounds__(NTHR, 2)
void dcn_kernel(const float* __restrict__ xt,
                const float* __restrict__ off,
                const float* __restrict__ wgt,
                const float* __restrict__ bias,
                float* __restrict__ out)
{
    __shared__ __align__(16) float sW[2][CG * 9 * 64];   // [(cg*9+k)*64 + oc]

    const int tid = threadIdx.x;
    const int tx  = tid % TW;
    const int ty  = tid / TW;
    const int b   = blockIdx.z;
    const int gx  = blockIdx.x * TW + tx;
    const int gy  = blockIdx.y * TH + ty;

    float acc[64];
#pragma unroll
    for (int i = 0; i < 64; ++i) acc[i] = 0.f;

    const float* offB = off + (size_t)b * 216 * HWW + gy * WW + gx;

    auto load_w = [&](int dg, int sel) {
        for (int i = tid; i < CG * 9 * 64; i += NTHR) {
            int oc = i % 64;
            int r  = i / 64;
            int k  = r % 9;
            int cg = r / 9;
            sW[sel][i] = wgt[(size_t)oc * (CC * 9) + (dg * CG + cg) * 9 + k];
        }
    };

    load_w(0, 0);
    __syncthreads();

    int sel = 0;
    for (int dg = 0; dg < DG; ++dg) {
        if (dg + 1 < DG) load_w(dg + 1, sel ^ 1);

        const float* xdg = xt + ((size_t)(b * DG + dg)) * HWW * CG;
        const float* cW  = sW[sel];

        for (int k = 0; k < 9; ++k) {
            float dy = offB[(size_t)(dg * 18 + 2 * k + 0) * HWW];
            float dx = offB[(size_t)(dg * 18 + 2 * k + 1) * HWW];
            float ml = offB[(size_t)(144 + dg * 9 + k) * HWW];
            float m  = 1.f / (1.f + __expf(-ml));

            float py = (float)gy - 1.f + (float)(k / 3) + dy;
            float px = (float)gx - 1.f + (float)(k % 3) + dx;
            float y0f = floorf(py), x0f = floorf(px);
            float wy = py - y0f, wx = px - x0f;
            int y0 = (int)y0f, x0 = (int)x0f;

            float cw00 = (1.f - wy) * (1.f - wx);
            float cw01 = (1.f - wy) * wx;
            float cw10 = wy * (1.f - wx);
            float cw11 = wy * wx;

            float sv[8];
#pragma unroll
            for (int i = 0; i < 8; ++i) sv[i] = 0.f;

#pragma unroll
            for (int cy = 0; cy < 2; ++cy) {
#pragma unroll
                for (int cx = 0; cx < 2; ++cx) {
                    int yy = y0 + cy, xx = x0 + cx;
                    float cwv = (cy == 0) ? ((cx == 0) ? cw00 : cw01)
                                          : ((cx == 0) ? cw10 : cw11);
                    if (yy >= 0 && yy < HH && xx >= 0 && xx < WW) {
                        const float4* p = reinterpret_cast<const float4*>(
                            xdg + ((size_t)yy * WW + xx) * CG);
                        float4 a = __ldg(&p[0]);
                        float4 c = __ldg(&p[1]);
                        sv[0] += cwv * a.x; sv[1] += cwv * a.y;
                        sv[2] += cwv * a.z; sv[3] += cwv * a.w;
                        sv[4] += cwv * c.x; sv[5] += cwv * c.y;
                        sv[6] += cwv * c.z; sv[7] += cwv * c.w;
                    }
                }
            }

#pragma unroll
            for (int cg = 0; cg < CG; ++cg) {
                float s = sv[cg] * m;
                const float4* wr = reinterpret_cast<const float4*>(cW + (cg * 9 + k) * 64);
#pragma unroll
                for (int o4 = 0; o4 < 16; ++o4) {
                    float4 w = wr[o4];
                    acc[o4 * 4 + 0] += w.x * s;
                    acc[o4 * 4 + 1] += w.y * s;
                    acc[o4 * 4 + 2] += w.z * s;
                    acc[o4 * 4 + 3] += w.w * s;
                }
            }
        }
        __syncthreads();
        sel ^= 1;
    }

#pragma unroll
    for (int oc = 0; oc < 64; ++oc) {
        float r = acc[oc] + __ldg(&bias[oc]);
        if (LRELU) r = (r >= 0.f) ? r : 0.1f * r;
        out[((size_t)(b * CC + oc)) * HWW + gy * WW + gx] = r;
    }
}

// ---------------- launch ----------------
extern "C" void kernel_launch(void* const* d_in, const int* in_sizes, int n_in,
                              void* d_out, int out_size)
{
    const float* nbr     = (const float*)d_in[0];
    const float* ref     = (const float*)d_in[1];
    const float* oc1_w   = (const float*)d_in[2];
    const float* oc1_b   = (const float*)d_in[3];
    const float* oc2_w   = (const float*)d_in[4];
    const float* oc2_b   = (const float*)d_in[5];
    const float* d1off_w = (const float*)d_in[6];
    const float* d1off_b = (const float*)d_in[7];
    const float* dcn1_w  = (const float*)d_in[8];
    const float* dcn1_b  = (const float*)d_in[9];
    const float* fc_w    = (const float*)d_in[10];
    const float* fc_b    = (const float*)d_in[11];
    const float* cas1_w  = (const float*)d_in[12];
    const float* cas1_b  = (const float*)d_in[13];
    const float* cas2_w  = (const float*)d_in[14];
    const float* cas2_b  = (const float*)d_in[15];
    const float* cdoff_w = (const float*)d_in[16];
    const float* cdoff_b = (const float*)d_in[17];
    const float* casd_w  = (const float*)d_in[18];
    const float* casd_b  = (const float*)d_in[19];
    float* outp = (float*)d_out;

    float *buf1, *buf2, *buf3, *buf4, *offb, *xt;
    cudaGetSymbolAddress((void**)&buf1, g_buf1);
    cudaGetSymbolAddress((void**)&buf2, g_buf2);
    cudaGetSymbolAddress((void**)&buf3, g_buf3);
    cudaGetSymbolAddress((void**)&buf4, g_buf4);
    cudaGetSymbolAddress((void**)&offb, g_off);
    cudaGetSymbolAddress((void**)&xt,   g_xt);

    const int IN_STAGE = CHUNK * (TH + 2) * (TW + 2);
    const int smem64 = (2 * IN_STAGE + 2 * CHUNK * 9 * 64) * sizeof(float);
    const int smem72 = (2 * IN_STAGE + 2 * CHUNK * 9 * 72) * sizeof(float);

    static bool attr_done = false;
    if (!attr_done) {
        cudaFuncSetAttribute(conv3x3_kernel<64, true >, cudaFuncAttributeMaxDynamicSharedMemorySize, smem64);
        cudaFuncSetAttribute(conv3x3_kernel<64, false>, cudaFuncAttributeMaxDynamicSharedMemorySize, smem64);
        cudaFuncSetAttribute(conv3x3_kernel<72, false>, cudaFuncAttributeMaxDynamicSharedMemorySize, smem72);
        attr_done = true;
    }

    dim3 gC(WW / TW, HH / TH, BB);         // 64-out convs / dcn
    dim3 gO(WW / TW, HH / TH, BB * 3);     // 216-out convs (3 blocks of 72)
    int tpGrid = (BB * DG * HWW + NTHR - 1) / NTHR;

    // 1) offset = lrelu(conv(cat(nbr, ref), oc1))
    conv3x3_kernel<64, true ><<<gC, NTHR, smem64>>>(nbr, ref, CC, 2 * CC, oc1_w, oc1_b, buf1, 64);
    // 2) offset = lrelu(conv(offset, oc2))
    conv3x3_kernel<64, true ><<<gC, NTHR, smem64>>>(buf1, nullptr, CC, CC, oc2_w, oc2_b, buf2, 64);
    // 3) dcn1 offset/mask conv (216 ch, raw)
    conv3x3_kernel<72, false><<<gO, NTHR, smem72>>>(buf2, nullptr, CC, CC, d1off_w, d1off_b, offb, 216);
    // 4) transpose nbr for gathers
    transpose_kernel<<<tpGrid, NTHR>>>(nbr, xt);
    // 5) feat = dcn(nbr, off)
    dcn_kernel<false><<<gC, NTHR>>>(xt, offb, dcn1_w, dcn1_b, buf3);
    // 6) feat = conv(feat, fc)
    conv3x3_kernel<64, false><<<gC, NTHR, smem64>>>(buf3, nullptr, CC, CC, fc_w, fc_b, buf4, 64);
    // 7) offset = lrelu(conv(cat(feat, ref), cas1))
    conv3x3_kernel<64, true ><<<gC, NTHR, smem64>>>(buf4, ref, CC, 2 * CC, cas1_w, cas1_b, buf1, 64);
    // 8) offset = lrelu(conv(offset, cas2))
    conv3x3_kernel<64, true ><<<gC, NTHR, smem64>>>(buf1, nullptr, CC, CC, cas2_w, cas2_b, buf2, 64);
    // 9) casd offset/mask conv
    conv3x3_kernel<72, false><<<gO, NTHR, smem72>>>(buf2, nullptr, CC, CC, cdoff_w, cdoff_b, offb, 216);
    // 10) transpose feat
    transpose_kernel<<<tpGrid, NTHR>>>(buf4, xt);
    // 11) out = lrelu(dcn(feat, off))
    dcn_kernel<true><<<gC, NTHR>>>(xt, offb, casd_w, casd_b, outp);

    (void)in_sizes; (void)n_in; (void)out_size;
}

// round 5
// speedup vs baseline: 2.3268x; 1.4590x over previous
#include <cuda_runtime.h>
#include <cuda_bf16.h>
#include <cstdint>

// ---------------- problem constants ----------------
#define BB 4
#define CC 64
#define HH 192
#define WW 192
#define HWW (HH*WW)
#define DG 8
#define CG 8
#define PW 194                      // padded width/height (H+2)
#define PIMG (PW*PW)                // 37636 padded pixels per image
#define MROWS (BB*PIMG)             // 150544 total padded pixels
#define GUARD 512                   // zero guard rows front
#define ROWSA (GUARD + MROWS + 1024)
#define NTILES ((MROWS + 127)/128)  // 1177

// ---------------- scratch (static device globals; zero-initialized) ----------------
__device__ __align__(256) float g_xnbr[(size_t)ROWSA * 64];          // padded NHWC fp32 (dcn1 gather)
__device__ __align__(256) float g_xfc [(size_t)ROWSA * 64];          // fc out fp32 (dcn2 gather)
__device__ __align__(256) float g_offb[(size_t)ROWSA * 216];         // offset conv out (NHWC)
__device__ __align__(256) __nv_bfloat16 g_nbr_h[(size_t)ROWSA*64], g_nbr_l[(size_t)ROWSA*64];
__device__ __align__(256) __nv_bfloat16 g_ref_h[(size_t)ROWSA*64], g_ref_l[(size_t)ROWSA*64];
__device__ __align__(256) __nv_bfloat16 g_b1_h [(size_t)ROWSA*64], g_b1_l [(size_t)ROWSA*64];
__device__ __align__(256) __nv_bfloat16 g_b2_h [(size_t)ROWSA*64], g_b2_l [(size_t)ROWSA*64];
__device__ __align__(256) __nv_bfloat16 g_b3_h [(size_t)ROWSA*64], g_b3_l [(size_t)ROWSA*64];
__device__ __align__(256) __nv_bfloat16 g_b4_h [(size_t)ROWSA*64], g_b4_l [(size_t)ROWSA*64];
__device__ __align__(256) __nv_bfloat16 g_w_h[9*2*216*64], g_w_l[9*2*216*64];  // prepped weights

// ---------------- PTX helpers (all baseline ISA, compute_103-legal) ----------------
__device__ __forceinline__ uint32_t smem_u32(const void* p) {
    uint32_t a;
    asm("{ .reg .u64 t; cvta.to.shared.u64 t, %1; cvt.u32.u64 %0, t; }" : "=r"(a) : "l"(p));
    return a;
}
__device__ __forceinline__ void ldsm_x4(uint32_t* r, uint32_t a) {
    asm volatile("ldmatrix.sync.aligned.m8n8.x4.shared.b16 {%0,%1,%2,%3}, [%4];"
        : "=r"(r[0]), "=r"(r[1]), "=r"(r[2]), "=r"(r[3]) : "r"(a));
}
__device__ __forceinline__ void ldsm_x2(uint32_t* r, uint32_t a) {
    asm volatile("ldmatrix.sync.aligned.m8n8.x2.shared.b16 {%0,%1}, [%2];"
        : "=r"(r[0]), "=r"(r[1]) : "r"(a));
}
__device__ __forceinline__ void mma_bf16(float* c, const uint32_t* a, const uint32_t* b) {
    asm volatile(
        "mma.sync.aligned.m16n8k16.row.col.f32.bf16.bf16.f32 "
        "{%0,%1,%2,%3}, {%4,%5,%6,%7}, {%8,%9}, {%0,%1,%2,%3};"
        : "+f"(c[0]), "+f"(c[1]), "+f"(c[2]), "+f"(c[3])
        : "r"(a[0]), "r"(a[1]), "r"(a[2]), "r"(a[3]), "r"(b[0]), "r"(b[1]));
}

// ---------------- input conversion: NCHW fp32 -> padded NHWC (fp32 opt + bf16 hi/lo) ----------------
template<bool F32OUT>
__global__ void convert_in_kernel(const float* __restrict__ in, float* __restrict__ outF,
                                  __nv_bfloat16* __restrict__ hi, __nv_bfloat16* __restrict__ lo)
{
    int p = blockIdx.x * blockDim.x + threadIdx.x;
    if (p >= BB * HWW) return;
    int x = p % WW; int t = p / WW; int y = t % HH; int b = t / HH;
    size_t g = (size_t)GUARD + (size_t)b * PIMG + (size_t)(y + 1) * PW + (x + 1);
#pragma unroll
    for (int c = 0; c < 64; ++c) {
        float v = in[((size_t)(b * 64 + c)) * HWW + (size_t)y * WW + x];
        if (F32OUT) outF[g * 64 + c] = v;
        __nv_bfloat16 h = __float2bfloat16(v);
        hi[g * 64 + c] = h;
        lo[g * 64 + c] = __float2bfloat16(v - __bfloat162float(h));
    }
}

// ---------------- weight prep: OIHW fp32 -> [tap][seg][n][64k] bf16 hi/lo ----------------
__global__ void weight_prep_kernel(const float* __restrict__ w, int O, int Cin,
                                   __nv_bfloat16* __restrict__ whi, __nv_bfloat16* __restrict__ wlo)
{
    int idx = blockIdx.x * blockDim.x + threadIdx.x;
    if (idx >= O * Cin * 9) return;
    int tap = idx % 9; int t = idx / 9; int ci = t % Cin; int o = t / Cin;
    float v = w[idx];
    int seg = ci >> 6, k = ci & 63;
    size_t dst = (((size_t)tap * (Cin >> 6) + seg) * O + o) * 64 + k;
    __nv_bfloat16 h = __float2bfloat16(v);
    whi[dst] = h;
    wlo[dst] = __float2bfloat16(v - __bfloat162float(h));
}

// ---------------- conv as shifted-window implicit GEMM on mma.sync (bf16 3-term) ----------------
// One CTA: M=128 pixel rows (padded-linear), NT output channels (blockIdx.y = channel tile).
// 4 warps x (m=32, n=NT). Per (tap,seg): stage A(128x64 hi/lo) + W(NTx64 hi/lo) in
// SW128-swizzled smem; 4x k16 chunks of ldmatrix + mma. fp32 accum in registers.
template<int NT, int NTOT, int SEGS, bool EPI_F32, bool EPI_BF16, bool LRELU>
__global__ __launch_bounds__(128)
void conv_mma_kernel(const __nv_bfloat16* __restrict__ Ahi0, const __nv_bfloat16* __restrict__ Alo0,
                     const __nv_bfloat16* __restrict__ Ahi1, const __nv_bfloat16* __restrict__ Alo1,
                     const __nv_bfloat16* __restrict__ Whi, const __nv_bfloat16* __restrict__ Wlo,
                     const float* __restrict__ bias,
                     float* __restrict__ outF,
                     __nv_bfloat16* __restrict__ outHi, __nv_bfloat16* __restrict__ outLo)
{
    extern __shared__ __align__(1024) char smem[];
    constexpr int OFF_AHI = 1024;
    constexpr int OFF_ALO = 1024 + 16384;
    constexpr int OFF_BHI = 33792;
    constexpr int OFF_BLO = 33792 + NT * 128;
    constexpr int NB = NT / 8;

    float* sBias = (float*)smem;
    const uint32_t sb = smem_u32(smem);

    const int tid  = threadIdx.x;
    const int lane = tid & 31;
    const int warp = tid >> 5;
    const int ocb  = blockIdx.y;
    const long m0  = (long)blockIdx.x * 128;

    for (int i = tid; i < NT; i += 128) sBias[i] = bias[ocb * NT + i];

    float acc[2][NB][4];
#pragma unroll
    for (int mt = 0; mt < 2; ++mt)
#pragma unroll
        for (int nb = 0; nb < NB; ++nb)
#pragma unroll
            for (int j = 0; j < 4; ++j) acc[mt][nb][j] = 0.f;

    // ldmatrix per-lane address components (swizzle xor is lane&7 for both A and B)
    const int l7 = lane & 7;
    const uint32_t aRow = (uint32_t)(warp * 32 + ((lane >> 3) & 1) * 8 + l7);
    const int aU = (lane >> 4) & 1;          // k-halfchunk select for A groups
    const int bU = (lane >> 3) & 1;          // k-halfchunk select for B groups

    for (int tap = 0; tap < 9; ++tap) {
        const int dy = tap / 3 - 1, dx = tap % 3 - 1;
        const long shift = (long)GUARD + m0 + (long)dy * PW + dx;
        for (int seg = 0; seg < SEGS; ++seg) {
            const __nv_bfloat16* ah = (seg == 0) ? Ahi0 : Ahi1;
            const __nv_bfloat16* al = (seg == 0) ? Alo0 : Alo1;
            // ---- stage A: one 128B row per thread, SW128 swizzle ----
            {
                const uint4* srch = (const uint4*)(ah + (size_t)(shift + tid) * 64);
                const uint4* srcl = (const uint4*)(al + (size_t)(shift + tid) * 64);
                uint32_t ro = (uint32_t)tid * 128;
                uint32_t sx = ((uint32_t)tid & 7) * 16;
#pragma unroll
                for (int i = 0; i < 8; ++i) {
                    uint32_t o = ro + (((uint32_t)i * 16) ^ sx);
                    *(uint4*)(smem + OFF_AHI + o) = srch[i];
                    *(uint4*)(smem + OFF_ALO + o) = srcl[i];
                }
            }
            // ---- stage W: NT rows ----
            const size_t wbase = (((size_t)tap * SEGS + seg) * NTOT + (size_t)ocb * NT);
            for (int n = tid; n < NT; n += 128) {
                const uint4* swh = (const uint4*)(Whi + (wbase + n) * 64);
                const uint4* swl = (const uint4*)(Wlo + (wbase + n) * 64);
                uint32_t ro = (uint32_t)n * 128;
                uint32_t sx = ((uint32_t)n & 7) * 16;
#pragma unroll
                for (int i = 0; i < 8; ++i) {
                    uint32_t o = ro + (((uint32_t)i * 16) ^ sx);
                    *(uint4*)(smem + OFF_BHI + o) = swh[i];
                    *(uint4*)(smem + OFF_BLO + o) = swl[i];
                }
            }
            __syncthreads();

            // ---- compute: 4 k16 chunks ----
#pragma unroll
            for (int c = 0; c < 4; ++c) {
                uint32_t ahf[2][4], alf[2][4];
#pragma unroll
                for (int mt = 0; mt < 2; ++mt) {
                    uint32_t row = aRow + mt * 16;
                    uint32_t off = row * 128 + ((uint32_t)((2 * c + aU) ^ l7)) * 16;
                    ldsm_x4(ahf[mt], sb + OFF_AHI + off);
                    ldsm_x4(alf[mt], sb + OFF_ALO + off);
                }
#pragma unroll
                for (int nb = 0; nb < NB; ++nb) {
                    uint32_t rb = (uint32_t)(nb * 8 + l7);
                    uint32_t offb = rb * 128 + ((uint32_t)((2 * c + bU) ^ l7)) * 16;
                    uint32_t bh[2], bl[2];
                    ldsm_x2(bh, sb + OFF_BHI + offb);
                    ldsm_x2(bl, sb + OFF_BLO + offb);
                    mma_bf16(acc[0][nb], ahf[0], bh);
                    mma_bf16(acc[1][nb], ahf[1], bh);
                    mma_bf16(acc[0][nb], ahf[0], bl);
                    mma_bf16(acc[1][nb], ahf[1], bl);
                    mma_bf16(acc[0][nb], alf[0], bh);
                    mma_bf16(acc[1][nb], alf[1], bh);
                }
            }
            __syncthreads();
        }
    }

    // ---- epilogue: c-frag mapping: rows lane/4 (+8), cols 2*(lane%4)+{0,1} ----
    const long gbase = m0 + warp * 32;
    const int ncol0 = 2 * (lane & 3);
#pragma unroll
    for (int mt = 0; mt < 2; ++mt) {
#pragma unroll
        for (int half = 0; half < 2; ++half) {
            long g = gbase + mt * 16 + (lane >> 2) + half * 8;
            bool valid = (g < MROWS);
            if (valid) {
                long q = g % PIMG;
                int py = (int)(q / PW), px = (int)(q % PW);
                valid = (py >= 1) && (py < PW - 1) && (px >= 1) && (px < PW - 1);
            }
            if (!valid) continue;
            const size_t orow = (size_t)(GUARD + g);
#pragma unroll
            for (int nb = 0; nb < NB; ++nb) {
                float v0 = acc[mt][nb][half * 2 + 0] + sBias[nb * 8 + ncol0];
                float v1 = acc[mt][nb][half * 2 + 1] + sBias[nb * 8 + ncol0 + 1];
                if (LRELU) {
                    v0 = (v0 >= 0.f) ? v0 : 0.1f * v0;
                    v1 = (v1 >= 0.f) ? v1 : 0.1f * v1;
                }
                const size_t col = (size_t)ocb * NT + nb * 8 + ncol0;
                if (EPI_F32) {
                    outF[orow * NTOT + col]     = v0;
                    outF[orow * NTOT + col + 1] = v1;
                }
                if (EPI_BF16) {
                    __nv_bfloat16 h0 = __float2bfloat16(v0);
                    __nv_bfloat16 h1 = __float2bfloat16(v1);
                    outHi[orow * NTOT + col]     = h0;
                    outHi[orow * NTOT + col + 1] = h1;
                    outLo[orow * NTOT + col]     = __float2bfloat16(v0 - __bfloat162float(h0));
                    outLo[orow * NTOT + col + 1] = __float2bfloat16(v1 - __bfloat162float(h1));
                }
            }
        }
    }
}

// ---------------- modulated deformable conv (DCNv2), NHWC in/out ----------------
template<bool LRELU, bool NCHW_OUT>
__global__ __launch_bounds__(256, 2)
void dcn_kernel(const float* __restrict__ xf,
                const float* __restrict__ off,
                const float* __restrict__ wgt,
                const float* __restrict__ bias,
                float* __restrict__ outF,
                __nv_bfloat16* __restrict__ outHi, __nv_bfloat16* __restrict__ outLo)
{
    __shared__ __align__(16) float sW[2][CG * 9 * 64];

    const int tid = threadIdx.x;
    const int tx  = tid % 32;
    const int ty  = tid / 32;
    const int b   = blockIdx.z;
    const int gx  = blockIdx.x * 32 + tx;
    const int gy  = blockIdx.y * 8 + ty;

    float acc[64];
#pragma unroll
    for (int i = 0; i < 64; ++i) acc[i] = 0.f;

    const size_t prow = (size_t)GUARD + (size_t)b * PIMG + (size_t)(gy + 1) * PW + (gx + 1);
    const float* offP = off + prow * 216;

    auto load_w = [&](int dg, int sel) {
        for (int i = tid; i < CG * 9 * 64; i += 256) {
            int oc = i % 64;
            int r  = i / 64;
            int k  = r % 9;
            int cg = r / 9;
            sW[sel][i] = wgt[(size_t)oc * (CC * 9) + (dg * CG + cg) * 9 + k];
        }
    };

    load_w(0, 0);
    __syncthreads();

    int sel = 0;
    for (int dg = 0; dg < DG; ++dg) {
        if (dg + 1 < DG) load_w(dg + 1, sel ^ 1);
        const float* cW = sW[sel];

        for (int k = 0; k < 9; ++k) {
            float dy = offP[dg * 18 + 2 * k + 0];
            float dx = offP[dg * 18 + 2 * k + 1];
            float ml = offP[144 + dg * 9 + k];
            float m  = 1.f / (1.f + __expf(-ml));

            float py = (float)gy - 1.f + (float)(k / 3) + dy;
            float px = (float)gx - 1.f + (float)(k % 3) + dx;
            float y0f = floorf(py), x0f = floorf(px);
            float wy = py - y0f, wx = px - x0f;
            int y0 = (int)y0f, x0 = (int)x0f;

            float cw00 = (1.f - wy) * (1.f - wx);
            float cw01 = (1.f - wy) * wx;
            float cw10 = wy * (1.f - wx);
            float cw11 = wy * wx;

            float sv[8];
#pragma unroll
            for (int i = 0; i < 8; ++i) sv[i] = 0.f;

#pragma unroll
            for (int cy = 0; cy < 2; ++cy) {
#pragma unroll
                for (int cx = 0; cx < 2; ++cx) {
                    int yy = y0 + cy, xx = x0 + cx;
                    float cwv = (cy == 0) ? ((cx == 0) ? cw00 : cw01)
                                          : ((cx == 0) ? cw10 : cw11);
                    if (yy >= 0 && yy < HH && xx >= 0 && xx < WW) {
                        const float4* p = reinterpret_cast<const float4*>(
                            xf + ((size_t)GUARD + (size_t)b * PIMG
                                  + (size_t)(yy + 1) * PW + (xx + 1)) * 64 + dg * 8);
                        float4 a = __ldg(&p[0]);
                        float4 c = __ldg(&p[1]);
                        sv[0] += cwv * a.x; sv[1] += cwv * a.y;
                        sv[2] += cwv * a.z; sv[3] += cwv * a.w;
                        sv[4] += cwv * c.x; sv[5] += cwv * c.y;
                        sv[6] += cwv * c.z; sv[7] += cwv * c.w;
                    }
                }
            }

#pragma unroll
            for (int cg = 0; cg < CG; ++cg) {
                float s = sv[cg] * m;
                const float4* wr = reinterpret_cast<const float4*>(cW + (cg * 9 + k) * 64);
#pragma unroll
                for (int o4 = 0; o4 < 16; ++o4) {
                    float4 w = wr[o4];
                    acc[o4 * 4 + 0] += w.x * s;
                    acc[o4 * 4 + 1] += w.y * s;
                    acc[o4 * 4 + 2] += w.z * s;
                    acc[o4 * 4 + 3] += w.w * s;
                }
            }
        }
        __syncthreads();
        sel ^= 1;
    }

#pragma unroll
    for (int oc = 0; oc < 64; ++oc) {
        float v = acc[oc] + __ldg(&bias[oc]);
        if (LRELU) v = (v >= 0.f) ? v : 0.1f * v;
        if (NCHW_OUT) {
            outF[((size_t)(b * CC + oc)) * HWW + (size_t)gy * WW + gx] = v;
        } else {
            __nv_bfloat16 h = __float2bfloat16(v);
            outHi[prow * 64 + oc] = h;
            outLo[prow * 64 + oc] = __float2bfloat16(v - __bfloat162float(h));
        }
    }
}

// ---------------- launch ----------------
extern "C" void kernel_launch(void* const* d_in, const int* in_sizes, int n_in,
                              void* d_out, int out_size)
{
    const float* nbr     = (const float*)d_in[0];
    const float* ref     = (const float*)d_in[1];
    const float* oc1_w   = (const float*)d_in[2];
    const float* oc1_b   = (const float*)d_in[3];
    const float* oc2_w   = (const float*)d_in[4];
    const float* oc2_b   = (const float*)d_in[5];
    const float* d1off_w = (const float*)d_in[6];
    const float* d1off_b = (const float*)d_in[7];
    const float* dcn1_w  = (const float*)d_in[8];
    const float* dcn1_b  = (const float*)d_in[9];
    const float* fc_w    = (const float*)d_in[10];
    const float* fc_b    = (const float*)d_in[11];
    const float* cas1_w  = (const float*)d_in[12];
    const float* cas1_b  = (const float*)d_in[13];
    const float* cas2_w  = (const float*)d_in[14];
    const float* cas2_b  = (const float*)d_in[15];
    const float* cdoff_w = (const float*)d_in[16];
    const float* cdoff_b = (const float*)d_in[17];
    const float* casd_w  = (const float*)d_in[18];
    const float* casd_b  = (const float*)d_in[19];
    float* outp = (float*)d_out;

    float *xnbr, *xfc, *offb;
    __nv_bfloat16 *nh, *nl, *rh, *rl, *b1h, *b1l, *b2h, *b2l, *b3h, *b3l, *b4h, *b4l, *wh, *wl;
    cudaGetSymbolAddress((void**)&xnbr, g_xnbr);
    cudaGetSymbolAddress((void**)&xfc,  g_xfc);
    cudaGetSymbolAddress((void**)&offb, g_offb);
    cudaGetSymbolAddress((void**)&nh,  g_nbr_h); cudaGetSymbolAddress((void**)&nl, g_nbr_l);
    cudaGetSymbolAddress((void**)&rh,  g_ref_h); cudaGetSymbolAddress((void**)&rl, g_ref_l);
    cudaGetSymbolAddress((void**)&b1h, g_b1_h);  cudaGetSymbolAddress((void**)&b1l, g_b1_l);
    cudaGetSymbolAddress((void**)&b2h, g_b2_h);  cudaGetSymbolAddress((void**)&b2l, g_b2_l);
    cudaGetSymbolAddress((void**)&b3h, g_b3_h);  cudaGetSymbolAddress((void**)&b3l, g_b3_l);
    cudaGetSymbolAddress((void**)&b4h, g_b4_h);  cudaGetSymbolAddress((void**)&b4l, g_b4_l);
    cudaGetSymbolAddress((void**)&wh,  g_w_h);   cudaGetSymbolAddress((void**)&wl,  g_w_l);

    // kernel variants
    auto C64S2 = conv_mma_kernel<64, 64, 2, false, true,  true >;   // oc1, cas1 (Cin=128)
    auto C64S1 = conv_mma_kernel<64, 64, 1, false, true,  true >;   // oc2, cas2
    auto C216  = conv_mma_kernel<72, 216, 1, true,  false, false>;  // offset convs (3 ch-tiles)
    auto CFC   = conv_mma_kernel<64, 64, 1, true,  true,  false>;   // fc

    const int smem64  = 33792 + 64 * 256;   // 50176
    const int smem72  = 33792 + 72 * 256;   // 52224
    cudaFuncSetAttribute(C64S2, cudaFuncAttributeMaxDynamicSharedMemorySize, smem64);
    cudaFuncSetAttribute(C64S1, cudaFuncAttributeMaxDynamicSharedMemorySize, smem64);
    cudaFuncSetAttribute(CFC,   cudaFuncAttributeMaxDynamicSharedMemorySize, smem64);
    cudaFuncSetAttribute(C216,  cudaFuncAttributeMaxDynamicSharedMemorySize, smem72);

    const int cvtGrid = (BB * HWW + 255) / 256;
    dim3 g64(NTILES, 1), g216(NTILES, 3);
    dim3 gDcn(WW / 32, HH / 8, BB);

    // 0) conversions
    convert_in_kernel<true ><<<cvtGrid, 256>>>(nbr, xnbr, nh, nl);
    convert_in_kernel<false><<<cvtGrid, 256>>>(ref, nullptr, rh, rl);

    // 1) offset = lrelu(conv(cat(nbr, ref), oc1))
    weight_prep_kernel<<<(64 * 128 * 9 + 255) / 256, 256>>>(oc1_w, 64, 128, wh, wl);
    C64S2<<<g64, 128, smem64>>>(nh, nl, rh, rl, wh, wl, oc1_b, nullptr, b1h, b1l);
    // 2) offset = lrelu(conv(offset, oc2))
    weight_prep_kernel<<<(64 * 64 * 9 + 255) / 256, 256>>>(oc2_w, 64, 64, wh, wl);
    C64S1<<<g64, 128, smem64>>>(b1h, b1l, nullptr, nullptr, wh, wl, oc2_b, nullptr, b2h, b2l);
    // 3) dcn1 offset/mask conv (216 ch, raw)
    weight_prep_kernel<<<(216 * 64 * 9 + 255) / 256, 256>>>(d1off_w, 216, 64, wh, wl);
    C216<<<g216, 128, smem72>>>(b2h, b2l, nullptr, nullptr, wh, wl, d1off_b, offb, nullptr, nullptr);
    // 4) feat = dcn(nbr, off)  -> bf16 hi/lo NHWC
    dcn_kernel<false, false><<<gDcn, 256>>>(xnbr, offb, dcn1_w, dcn1_b, nullptr, b3h, b3l);
    // 5) feat = conv(feat, fc) -> fp32 NHWC (gather src) + bf16 hi/lo
    weight_prep_kernel<<<(64 * 64 * 9 + 255) / 256, 256>>>(fc_w, 64, 64, wh, wl);
    CFC<<<g64, 128, smem64>>>(b3h, b3l, nullptr, nullptr, wh, wl, fc_b, xfc, b4h, b4l);
    // 6) offset = lrelu(conv(cat(feat, ref), cas1))
    weight_prep_kernel<<<(64 * 128 * 9 + 255) / 256, 256>>>(cas1_w, 64, 128, wh, wl);
    C64S2<<<g64, 128, smem64>>>(b4h, b4l, rh, rl, wh, wl, cas1_b, nullptr, b1h, b1l);
    // 7) offset = lrelu(conv(offset, cas2))
    weight_prep_kernel<<<(64 * 64 * 9 + 255) / 256, 256>>>(cas2_w, 64, 64, wh, wl);
    C64S1<<<g64, 128, smem64>>>(b1h, b1l, nullptr, nullptr, wh, wl, cas2_b, nullptr, b2h, b2l);
    // 8) casd offset/mask conv
    weight_prep_kernel<<<(216 * 64 * 9 + 255) / 256, 256>>>(cdoff_w, 216, 64, wh, wl);
    C216<<<g216, 128, smem72>>>(b2h, b2l, nullptr, nullptr, wh, wl, cdoff_b, offb, nullptr, nullptr);
    // 9) out = lrelu(dcn(feat, off)) -> NCHW fp32
    dcn_kernel<true, true><<<gDcn, 256>>>(xfc, offb, casd_w, casd_b, outp, nullptr, nullptr);

    (void)in_sizes; (void)n_in; (void)out_size;
}

// round 6
// speedup vs baseline: 2.4414x; 1.0492x over previous
#include <cuda_runtime.h>
#include <cuda_bf16.h>
#include <cstdint>

// ---------------- problem constants ----------------
#define BB 4
#define CC 64
#define HH 192
#define WW 192
#define HWW (HH*WW)
#define DG 8
#define CG 8
#define PW 194                      // padded width/height (H+2)
#define PIMG (PW*PW)                // 37636 padded pixels per image
#define MROWS (BB*PIMG)             // 150544 total padded pixels
#define GUARD 512                   // zero guard rows front
#define ROWSA (GUARD + MROWS + 1024)
#define NTILES ((MROWS + 127)/128)  // 1177

// ---------------- scratch (static device globals; zero-initialized) ----------------
__device__ __align__(256) float g_xnbr[(size_t)ROWSA * 64];          // padded NHWC fp32 (dcn1 gather)
__device__ __align__(256) float g_xfc [(size_t)ROWSA * 64];          // fc out fp32 (dcn2 gather)
__device__ __align__(256) float g_offb[(size_t)ROWSA * 216];         // offset conv out (NHWC)
__device__ __align__(256) __nv_bfloat16 g_nbr_h[(size_t)ROWSA*64], g_nbr_l[(size_t)ROWSA*64];
__device__ __align__(256) __nv_bfloat16 g_ref_h[(size_t)ROWSA*64], g_ref_l[(size_t)ROWSA*64];
__device__ __align__(256) __nv_bfloat16 g_b1_h [(size_t)ROWSA*64], g_b1_l [(size_t)ROWSA*64];
__device__ __align__(256) __nv_bfloat16 g_b2_h [(size_t)ROWSA*64], g_b2_l [(size_t)ROWSA*64];
__device__ __align__(256) __nv_bfloat16 g_b3_h [(size_t)ROWSA*64], g_b3_l [(size_t)ROWSA*64];
__device__ __align__(256) __nv_bfloat16 g_b4_h [(size_t)ROWSA*64], g_b4_l [(size_t)ROWSA*64];
// per-conv prepped weights (hi/lo), laid out back-to-back
#define WOFF_OC1   0
#define WOFF_OC2   (WOFF_OC1 + 9*2*64*64)
#define WOFF_D1OFF (WOFF_OC2 + 9*1*64*64)
#define WOFF_FC    (WOFF_D1OFF + 9*1*216*64)
#define WOFF_CAS1  (WOFF_FC + 9*1*64*64)
#define WOFF_CAS2  (WOFF_CAS1 + 9*2*64*64)
#define WOFF_CDOFF (WOFF_CAS2 + 9*1*64*64)
#define WTOT       (WOFF_CDOFF + 9*1*216*64)
__device__ __align__(256) __nv_bfloat16 g_w_h[WTOT], g_w_l[WTOT];

// ---------------- PTX helpers (baseline ISA, compute_103-legal) ----------------
__device__ __forceinline__ uint32_t smem_u32(const void* p) {
    uint32_t a;
    asm("{ .reg .u64 t; cvta.to.shared.u64 t, %1; cvt.u32.u64 %0, t; }" : "=r"(a) : "l"(p));
    return a;
}
__device__ __forceinline__ void ldsm_x4(uint32_t* r, uint32_t a) {
    asm volatile("ldmatrix.sync.aligned.m8n8.x4.shared.b16 {%0,%1,%2,%3}, [%4];"
        : "=r"(r[0]), "=r"(r[1]), "=r"(r[2]), "=r"(r[3]) : "r"(a));
}
__device__ __forceinline__ void ldsm_x2(uint32_t* r, uint32_t a) {
    asm volatile("ldmatrix.sync.aligned.m8n8.x2.shared.b16 {%0,%1}, [%2];"
        : "=r"(r[0]), "=r"(r[1]) : "r"(a));
}
__device__ __forceinline__ void mma_bf16(float* c, const uint32_t* a, const uint32_t* b) {
    asm volatile(
        "mma.sync.aligned.m16n8k16.row.col.f32.bf16.bf16.f32 "
        "{%0,%1,%2,%3}, {%4,%5,%6,%7}, {%8,%9}, {%0,%1,%2,%3};"
        : "+f"(c[0]), "+f"(c[1]), "+f"(c[2]), "+f"(c[3])
        : "r"(a[0]), "r"(a[1]), "r"(a[2]), "r"(a[3]), "r"(b[0]), "r"(b[1]));
}
__device__ __forceinline__ void cpasync16(uint32_t dst, const void* src) {
    asm volatile("cp.async.cg.shared.global [%0], [%1], 16;" :: "r"(dst), "l"(src));
}
__device__ __forceinline__ void cpcommit() { asm volatile("cp.async.commit_group;" ::: "memory"); }
__device__ __forceinline__ void cpwait1()  { asm volatile("cp.async.wait_group 1;" ::: "memory"); }
__device__ __forceinline__ void cpwait0()  { asm volatile("cp.async.wait_group 0;" ::: "memory"); }

// ---------------- input conversion: NCHW fp32 -> padded NHWC (fp32 opt + bf16 hi/lo) ----------------
template<bool F32OUT>
__global__ void convert_in_kernel(const float* __restrict__ in, float* __restrict__ outF,
                                  __nv_bfloat16* __restrict__ hi, __nv_bfloat16* __restrict__ lo)
{
    int p = blockIdx.x * blockDim.x + threadIdx.x;
    if (p >= BB * HWW) return;
    int x = p % WW; int t = p / WW; int y = t % HH; int b = t / HH;
    size_t g = (size_t)GUARD + (size_t)b * PIMG + (size_t)(y + 1) * PW + (x + 1);
#pragma unroll
    for (int c = 0; c < 64; ++c) {
        float v = in[((size_t)(b * 64 + c)) * HWW + (size_t)y * WW + x];
        if (F32OUT) outF[g * 64 + c] = v;
        __nv_bfloat16 h = __float2bfloat16(v);
        hi[g * 64 + c] = h;
        lo[g * 64 + c] = __float2bfloat16(v - __bfloat162float(h));
    }
}

// ---------------- weight prep: OIHW fp32 -> [tap][seg][n][64k] bf16 hi/lo at offset ----------------
__global__ void weight_prep_kernel(const float* __restrict__ w, int O, int Cin, size_t woff,
                                   __nv_bfloat16* __restrict__ whi, __nv_bfloat16* __restrict__ wlo)
{
    int idx = blockIdx.x * blockDim.x + threadIdx.x;
    if (idx >= O * Cin * 9) return;
    int tap = idx % 9; int t = idx / 9; int ci = t % Cin; int o = t / Cin;
    float v = w[idx];
    int seg = ci >> 6, k = ci & 63;
    size_t dst = woff + (((size_t)tap * (Cin >> 6) + seg) * O + o) * 64 + k;
    __nv_bfloat16 h = __float2bfloat16(v);
    whi[dst] = h;
    wlo[dst] = __float2bfloat16(v - __bfloat162float(h));
}

// ---------------- conv as shifted-window implicit GEMM (bf16 3-term, cp.async pipelined) ----------------
// One CTA: M=128 pixel rows, NT output channels (blockIdx.y = channel tile). 4 warps, m=32 each.
// Double-buffered stages: per (tap,seg) stage A(128x64 hi/lo) + W(NTx64 hi/lo) staged via
// cp.async.cg into SW128-swizzled smem; compute overlaps next stage's loads.
template<int NT, int NTOT, int SEGS, bool EPI_F32, bool EPI_BF16, bool LRELU>
__global__ __launch_bounds__(128)
void conv_mma_kernel(const __nv_bfloat16* __restrict__ Ahi0, const __nv_bfloat16* __restrict__ Alo0,
                     const __nv_bfloat16* __restrict__ Ahi1, const __nv_bfloat16* __restrict__ Alo1,
                     const __nv_bfloat16* __restrict__ Whi, const __nv_bfloat16* __restrict__ Wlo,
                     const float* __restrict__ bias,
                     float* __restrict__ outF,
                     __nv_bfloat16* __restrict__ outHi, __nv_bfloat16* __restrict__ outLo)
{
    extern __shared__ __align__(1024) char smem[];
    constexpr int STAGE = 32768 + NT * 256;       // Ahi(16K) Alo(16K) Bhi Blo
    constexpr int OFF_ALO = 16384;
    constexpr int OFF_BHI = 32768;
    constexpr int OFF_BLO = 32768 + NT * 128;
    constexpr int NB  = NT / 8;
    constexpr int NBP = NB / 2;
    constexpr bool NBODD = (NB & 1) != 0;
    constexpr int NST = 9 * SEGS;

    float* sBias = (float*)smem;                  // [0,1024)
    const uint32_t sb = smem_u32(smem);

    const int tid  = threadIdx.x;
    const int lane = tid & 31;
    const int warp = tid >> 5;
    const int ocb  = blockIdx.y;
    const long m0  = (long)blockIdx.x * 128;

    for (int i = tid; i < NT; i += 128) sBias[i] = bias[ocb * NT + i];

    float acc[2][NB][4];
#pragma unroll
    for (int mt = 0; mt < 2; ++mt)
#pragma unroll
        for (int nb = 0; nb < NB; ++nb)
#pragma unroll
            for (int j = 0; j < 4; ++j) acc[mt][nb][j] = 0.f;

    const int l7 = lane & 7;
    const uint32_t aRow = (uint32_t)(warp * 32 + ((lane >> 3) & 1) * 8 + l7);
    const int aU = (lane >> 4) & 1;
    const int bKh = (lane >> 3) & 1;
    const int bNs = (lane >> 4) & 1;

    // ---- stage loader: cp.async.cg, SW128-swizzled destinations ----
    auto load_stage = [&](int s, int buf) {
        const int tap = s / SEGS, seg = s % SEGS;
        const int dy = tap / 3 - 1, dx = tap % 3 - 1;
        const long shift = (long)GUARD + m0 + (long)dy * PW + dx;
        const uint32_t stb = sb + 1024 + buf * STAGE;
        const __nv_bfloat16* ah = (seg == 0) ? Ahi0 : Ahi1;
        const __nv_bfloat16* al = (seg == 0) ? Alo0 : Alo1;
        // A: one 128B row (64 bf16) per thread, hi+lo
        {
            const char* srch = (const char*)(ah + (size_t)(shift + tid) * 64);
            const char* srcl = (const char*)(al + (size_t)(shift + tid) * 64);
            uint32_t ro = (uint32_t)tid * 128;
            uint32_t sx = ((uint32_t)tid & 7) * 16;
#pragma unroll
            for (int i = 0; i < 8; ++i) {
                uint32_t o = ro + (((uint32_t)i * 16) ^ sx);
                cpasync16(stb + o, srch + i * 16);
                cpasync16(stb + OFF_ALO + o, srcl + i * 16);
            }
        }
        // B: NT rows
        const size_t wbase = (((size_t)tap * SEGS + seg) * NTOT + (size_t)ocb * NT);
        for (int n = tid; n < NT; n += 128) {
            const char* swh = (const char*)(Whi + (wbase + n) * 64);
            const char* swl = (const char*)(Wlo + (wbase + n) * 64);
            uint32_t ro = (uint32_t)n * 128;
            uint32_t sx = ((uint32_t)n & 7) * 16;
#pragma unroll
            for (int i = 0; i < 8; ++i) {
                uint32_t o = ro + (((uint32_t)i * 16) ^ sx);
                cpasync16(stb + OFF_BHI + o, swh + i * 16);
                cpasync16(stb + OFF_BLO + o, swl + i * 16);
            }
        }
        cpcommit();
    };

    load_stage(0, 0);

    for (int s = 0; s < NST; ++s) {
        const int buf = s & 1;
        if (s + 1 < NST) { load_stage(s + 1, buf ^ 1); cpwait1(); }
        else             { cpwait0(); }
        __syncthreads();   // stage s visible to all warps

        const uint32_t stb = sb + 1024 + buf * STAGE;
#pragma unroll
        for (int c = 0; c < 4; ++c) {
            uint32_t ahf[2][4], alf[2][4];
#pragma unroll
            for (int mt = 0; mt < 2; ++mt) {
                uint32_t row = aRow + mt * 16;
                uint32_t off = row * 128 + ((uint32_t)((2 * c + aU) ^ l7)) * 16;
                ldsm_x4(ahf[mt], stb + off);
                ldsm_x4(alf[mt], stb + OFF_ALO + off);
            }
#pragma unroll
            for (int nbp = 0; nbp < NBP; ++nbp) {
                uint32_t row = (uint32_t)((nbp * 2 + bNs) * 8 + l7);
                uint32_t offb = row * 128 + ((uint32_t)((2 * c + bKh) ^ l7)) * 16;
                uint32_t bh[4], bl[4];
                ldsm_x4(bh, stb + OFF_BHI + offb);
                ldsm_x4(bl, stb + OFF_BLO + offb);
#pragma unroll
                for (int half = 0; half < 2; ++half) {
                    const int nb = nbp * 2 + half;
                    mma_bf16(acc[0][nb], ahf[0], bh + 2 * half);
                    mma_bf16(acc[1][nb], ahf[1], bh + 2 * half);
                    mma_bf16(acc[0][nb], ahf[0], bl + 2 * half);
                    mma_bf16(acc[1][nb], ahf[1], bl + 2 * half);
                    mma_bf16(acc[0][nb], alf[0], bh + 2 * half);
                    mma_bf16(acc[1][nb], alf[1], bh + 2 * half);
                }
            }
            if (NBODD) {
                const int nb = NB - 1;
                uint32_t row = (uint32_t)(nb * 8 + l7);
                uint32_t offb = row * 128 + ((uint32_t)((2 * c + bKh) ^ l7)) * 16;
                uint32_t bh[2], bl[2];
                ldsm_x2(bh, stb + OFF_BHI + offb);
                ldsm_x2(bl, stb + OFF_BLO + offb);
                mma_bf16(acc[0][nb], ahf[0], bh);
                mma_bf16(acc[1][nb], ahf[1], bh);
                mma_bf16(acc[0][nb], ahf[0], bl);
                mma_bf16(acc[1][nb], ahf[1], bl);
                mma_bf16(acc[0][nb], alf[0], bh);
                mma_bf16(acc[1][nb], alf[1], bh);
            }
        }
        __syncthreads();   // reads done before buf is overwritten by stage s+2
    }

    // ---- epilogue: c-frag rows lane/4 (+8), cols 2*(lane%4)+{0,1} ----
    const long gbase = m0 + warp * 32;
    const int ncol0 = 2 * (lane & 3);
#pragma unroll
    for (int mt = 0; mt < 2; ++mt) {
#pragma unroll
        for (int half = 0; half < 2; ++half) {
            long g = gbase + mt * 16 + (lane >> 2) + half * 8;
            bool valid = (g < MROWS);
            if (valid) {
                long q = g % PIMG;
                int py = (int)(q / PW), px = (int)(q % PW);
                valid = (py >= 1) && (py < PW - 1) && (px >= 1) && (px < PW - 1);
            }
            if (!valid) continue;
            const size_t orow = (size_t)(GUARD + g);
#pragma unroll
            for (int nb = 0; nb < NB; ++nb) {
                float v0 = acc[mt][nb][half * 2 + 0] + sBias[nb * 8 + ncol0];
                float v1 = acc[mt][nb][half * 2 + 1] + sBias[nb * 8 + ncol0 + 1];
                if (LRELU) {
                    v0 = (v0 >= 0.f) ? v0 : 0.1f * v0;
                    v1 = (v1 >= 0.f) ? v1 : 0.1f * v1;
                }
                const size_t col = (size_t)ocb * NT + nb * 8 + ncol0;
                if (EPI_F32) {
                    outF[orow * NTOT + col]     = v0;
                    outF[orow * NTOT + col + 1] = v1;
                }
                if (EPI_BF16) {
                    __nv_bfloat16 h0 = __float2bfloat16(v0);
                    __nv_bfloat16 h1 = __float2bfloat16(v1);
                    outHi[orow * NTOT + col]     = h0;
                    outHi[orow * NTOT + col + 1] = h1;
                    outLo[orow * NTOT + col]     = __float2bfloat16(v0 - __bfloat162float(h0));
                    outLo[orow * NTOT + col + 1] = __float2bfloat16(v1 - __bfloat162float(h1));
                }
            }
        }
    }
}

// ---------------- modulated deformable conv (DCNv2), NHWC in/out ----------------
template<bool LRELU, bool NCHW_OUT>
__global__ __launch_bounds__(256, 2)
void dcn_kernel(const float* __restrict__ xf,
                const float* __restrict__ off,
                const float* __restrict__ wgt,
                const float* __restrict__ bias,
                float* __restrict__ outF,
                __nv_bfloat16* __restrict__ outHi, __nv_bfloat16* __restrict__ outLo)
{
    __shared__ __align__(16) float sW[2][CG * 9 * 64];

    const int tid = threadIdx.x;
    const int tx  = tid % 32;
    const int ty  = tid / 32;
    const int b   = blockIdx.z;
    const int gx  = blockIdx.x * 32 + tx;
    const int gy  = blockIdx.y * 8 + ty;

    float acc[64];
#pragma unroll
    for (int i = 0; i < 64; ++i) acc[i] = 0.f;

    const size_t prow = (size_t)GUARD + (size_t)b * PIMG + (size_t)(gy + 1) * PW + (gx + 1);
    const float* offP = off + prow * 216;

    auto load_w = [&](int dg, int sel) {
        for (int i = tid; i < CG * 9 * 64; i += 256) {
            int oc = i % 64;
            int r  = i / 64;
            int k  = r % 9;
            int cg = r / 9;
            sW[sel][i] = wgt[(size_t)oc * (CC * 9) + (dg * CG + cg) * 9 + k];
        }
    };

    load_w(0, 0);
    __syncthreads();

    int sel = 0;
    for (int dg = 0; dg < DG; ++dg) {
        if (dg + 1 < DG) load_w(dg + 1, sel ^ 1);
        const float* cW = sW[sel];

        for (int k = 0; k < 9; ++k) {
            float dy = offP[dg * 18 + 2 * k + 0];
            float dx = offP[dg * 18 + 2 * k + 1];
            float ml = offP[144 + dg * 9 + k];
            float m  = 1.f / (1.f + __expf(-ml));

            float py = (float)gy - 1.f + (float)(k / 3) + dy;
            float px = (float)gx - 1.f + (float)(k % 3) + dx;
            float y0f = floorf(py), x0f = floorf(px);
            float wy = py - y0f, wx = px - x0f;
            int y0 = (int)y0f, x0 = (int)x0f;

            float cw00 = (1.f - wy) * (1.f - wx);
            float cw01 = (1.f - wy) * wx;
            float cw10 = wy * (1.f - wx);
            float cw11 = wy * wx;

            float sv[8];
#pragma unroll
            for (int i = 0; i < 8; ++i) sv[i] = 0.f;

#pragma unroll
            for (int cy = 0; cy < 2; ++cy) {
#pragma unroll
                for (int cx = 0; cx < 2; ++cx) {
                    int yy = y0 + cy, xx = x0 + cx;
                    float cwv = (cy == 0) ? ((cx == 0) ? cw00 : cw01)
                                          : ((cx == 0) ? cw10 : cw11);
                    if (yy >= 0 && yy < HH && xx >= 0 && xx < WW) {
                        const float4* p = reinterpret_cast<const float4*>(
                            xf + ((size_t)GUARD + (size_t)b * PIMG
                                  + (size_t)(yy + 1) * PW + (xx + 1)) * 64 + dg * 8);
                        float4 a = __ldg(&p[0]);
                        float4 c = __ldg(&p[1]);
                        sv[0] += cwv * a.x; sv[1] += cwv * a.y;
                        sv[2] += cwv * a.z; sv[3] += cwv * a.w;
                        sv[4] += cwv * c.x; sv[5] += cwv * c.y;
                        sv[6] += cwv * c.z; sv[7] += cwv * c.w;
                    }
                }
            }

#pragma unroll
            for (int cg = 0; cg < CG; ++cg) {
                float s = sv[cg] * m;
                const float4* wr = reinterpret_cast<const float4*>(cW + (cg * 9 + k) * 64);
#pragma unroll
                for (int o4 = 0; o4 < 16; ++o4) {
                    float4 w = wr[o4];
                    acc[o4 * 4 + 0] += w.x * s;
                    acc[o4 * 4 + 1] += w.y * s;
                    acc[o4 * 4 + 2] += w.z * s;
                    acc[o4 * 4 + 3] += w.w * s;
                }
            }
        }
        __syncthreads();
        sel ^= 1;
    }

#pragma unroll
    for (int oc = 0; oc < 64; ++oc) {
        float v = acc[oc] + __ldg(&bias[oc]);
        if (LRELU) v = (v >= 0.f) ? v : 0.1f * v;
        if (NCHW_OUT) {
            outF[((size_t)(b * CC + oc)) * HWW + (size_t)gy * WW + gx] = v;
        } else {
            __nv_bfloat16 h = __float2bfloat16(v);
            outHi[prow * 64 + oc] = h;
            outLo[prow * 64 + oc] = __float2bfloat16(v - __bfloat162float(h));
        }
    }
}

// ---------------- launch ----------------
extern "C" void kernel_launch(void* const* d_in, const int* in_sizes, int n_in,
                              void* d_out, int out_size)
{
    const float* nbr     = (const float*)d_in[0];
    const float* ref     = (const float*)d_in[1];
    const float* oc1_w   = (const float*)d_in[2];
    const float* oc1_b   = (const float*)d_in[3];
    const float* oc2_w   = (const float*)d_in[4];
    const float* oc2_b   = (const float*)d_in[5];
    const float* d1off_w = (const float*)d_in[6];
    const float* d1off_b = (const float*)d_in[7];
    const float* dcn1_w  = (const float*)d_in[8];
    const float* dcn1_b  = (const float*)d_in[9];
    const float* fc_w    = (const float*)d_in[10];
    const float* fc_b    = (const float*)d_in[11];
    const float* cas1_w  = (const float*)d_in[12];
    const float* cas1_b  = (const float*)d_in[13];
    const float* cas2_w  = (const float*)d_in[14];
    const float* cas2_b  = (const float*)d_in[15];
    const float* cdoff_w = (const float*)d_in[16];
    const float* cdoff_b = (const float*)d_in[17];
    const float* casd_w  = (const float*)d_in[18];
    const float* casd_b  = (const float*)d_in[19];
    float* outp = (float*)d_out;

    float *xnbr, *xfc, *offb;
    __nv_bfloat16 *nh, *nl, *rh, *rl, *b1h, *b1l, *b2h, *b2l, *b3h, *b3l, *b4h, *b4l, *wh, *wl;
    cudaGetSymbolAddress((void**)&xnbr, g_xnbr);
    cudaGetSymbolAddress((void**)&xfc,  g_xfc);
    cudaGetSymbolAddress((void**)&offb, g_offb);
    cudaGetSymbolAddress((void**)&nh,  g_nbr_h); cudaGetSymbolAddress((void**)&nl, g_nbr_l);
    cudaGetSymbolAddress((void**)&rh,  g_ref_h); cudaGetSymbolAddress((void**)&rl, g_ref_l);
    cudaGetSymbolAddress((void**)&b1h, g_b1_h);  cudaGetSymbolAddress((void**)&b1l, g_b1_l);
    cudaGetSymbolAddress((void**)&b2h, g_b2_h);  cudaGetSymbolAddress((void**)&b2l, g_b2_l);
    cudaGetSymbolAddress((void**)&b3h, g_b3_h);  cudaGetSymbolAddress((void**)&b3l, g_b3_l);
    cudaGetSymbolAddress((void**)&b4h, g_b4_h);  cudaGetSymbolAddress((void**)&b4l, g_b4_l);
    cudaGetSymbolAddress((void**)&wh,  g_w_h);   cudaGetSymbolAddress((void**)&wl,  g_w_l);

    auto C64S2 = conv_mma_kernel<64, 64, 2, false, true,  true >;   // oc1, cas1 (Cin=128)
    auto C64S1 = conv_mma_kernel<64, 64, 1, false, true,  true >;   // oc2, cas2
    auto C216  = conv_mma_kernel<72, 216, 1, true,  false, false>;  // offset convs (3 ch-tiles)
    auto CFC   = conv_mma_kernel<64, 64, 1, true,  true,  false>;   // fc

    const int smem64 = 1024 + 2 * (32768 + 64 * 256);   // 99328
    const int smem72 = 1024 + 2 * (32768 + 72 * 256);   // 103424
    cudaFuncSetAttribute(C64S2, cudaFuncAttributeMaxDynamicSharedMemorySize, smem64);
    cudaFuncSetAttribute(C64S1, cudaFuncAttributeMaxDynamicSharedMemorySize, smem64);
    cudaFuncSetAttribute(CFC,   cudaFuncAttributeMaxDynamicSharedMemorySize, smem64);
    cudaFuncSetAttribute(C216,  cudaFuncAttributeMaxDynamicSharedMemorySize, smem72);

    const int cvtGrid = (BB * HWW + 255) / 256;
    dim3 g64(NTILES, 1), g216(NTILES, 3);
    dim3 gDcn(WW / 32, HH / 8, BB);

    // 0) conversions + ALL weight preps up front (no inter-conv dependencies)
    convert_in_kernel<true ><<<cvtGrid, 256>>>(nbr, xnbr, nh, nl);
    convert_in_kernel<false><<<cvtGrid, 256>>>(ref, nullptr, rh, rl);
    weight_prep_kernel<<<(64 * 128 * 9 + 255) / 256, 256>>>(oc1_w,   64, 128, WOFF_OC1,   wh, wl);
    weight_prep_kernel<<<(64 * 64 * 9 + 255) / 256, 256>>>(oc2_w,    64, 64,  WOFF_OC2,   wh, wl);
    weight_prep_kernel<<<(216 * 64 * 9 + 255) / 256, 256>>>(d1off_w, 216, 64, WOFF_D1OFF, wh, wl);
    weight_prep_kernel<<<(64 * 64 * 9 + 255) / 256, 256>>>(fc_w,     64, 64,  WOFF_FC,    wh, wl);
    weight_prep_kernel<<<(64 * 128 * 9 + 255) / 256, 256>>>(cas1_w,  64, 128, WOFF_CAS1,  wh, wl);
    weight_prep_kernel<<<(64 * 64 * 9 + 255) / 256, 256>>>(cas2_w,   64, 64,  WOFF_CAS2,  wh, wl);
    weight_prep_kernel<<<(216 * 64 * 9 + 255) / 256, 256>>>(cdoff_w, 216, 64, WOFF_CDOFF, wh, wl);

    // 1) offset = lrelu(conv(cat(nbr, ref), oc1))
    C64S2<<<g64, 128, smem64>>>(nh, nl, rh, rl, wh + WOFF_OC1, wl + WOFF_OC1, oc1_b, nullptr, b1h, b1l);
    // 2) offset = lrelu(conv(offset, oc2))
    C64S1<<<g64, 128, smem64>>>(b1h, b1l, nullptr, nullptr, wh + WOFF_OC2, wl + WOFF_OC2, oc2_b, nullptr, b2h, b2l);
    // 3) dcn1 offset/mask conv (216 ch, raw)
    C216<<<g216, 128, smem72>>>(b2h, b2l, nullptr, nullptr, wh + WOFF_D1OFF, wl + WOFF_D1OFF, d1off_b, offb, nullptr, nullptr);
    // 4) feat = dcn(nbr, off)  -> bf16 hi/lo NHWC
    dcn_kernel<false, false><<<gDcn, 256>>>(xnbr, offb, dcn1_w, dcn1_b, nullptr, b3h, b3l);
    // 5) feat = conv(feat, fc) -> fp32 NHWC (gather src) + bf16 hi/lo
    CFC<<<g64, 128, smem64>>>(b3h, b3l, nullptr, nullptr, wh + WOFF_FC, wl + WOFF_FC, fc_b, xfc, b4h, b4l);
    // 6) offset = lrelu(conv(cat(feat, ref), cas1))
    C64S2<<<g64, 128, smem64>>>(b4h, b4l, rh, rl, wh + WOFF_CAS1, wl + WOFF_CAS1, cas1_b, nullptr, b1h, b1l);
    // 7) offset = lrelu(conv(offset, cas2))
    C64S1<<<g64, 128, smem64>>>(b1h, b1l, nullptr, nullptr, wh + WOFF_CAS2, wl + WOFF_CAS2, cas2_b, nullptr, b2h, b2l);
    // 8) casd offset/mask conv
    C216<<<g216, 128, smem72>>>(b2h, b2l, nullptr, nullptr, wh + WOFF_CDOFF, wl + WOFF_CDOFF, cdoff_b, offb, nullptr, nullptr);
    // 9) out = lrelu(dcn(feat, off)) -> NCHW fp32
    dcn_kernel<true, true><<<gDcn, 256>>>(xfc, offb, casd_w, casd_b, outp, nullptr, nullptr);

    (void)in_sizes; (void)n_in; (void)out_size;
}

// round 7
// speedup vs baseline: 2.4719x; 1.0125x over previous
#include <cuda_runtime.h>
#include <cuda_bf16.h>
#include <cstdint>

// ---------------- problem constants ----------------
#define BB 4
#define CC 64
#define HH 192
#define WW 192
#define HWW (HH*WW)
#define DG 8
#define CG 8
#define PW 194                      // padded width/height (H+2)
#define PIMG (PW*PW)                // 37636 padded pixels per image
#define MROWS (BB*PIMG)             // 150544 total padded pixels
#define GUARD 512                   // zero guard rows front
#define ROWSA (GUARD + MROWS + 1024)
#define NTIL256 ((MROWS + 255)/256) // 589

// ---------------- scratch (static device globals; zero-initialized) ----------------
__device__ __align__(256) float g_xnbr[(size_t)ROWSA * 64];          // padded NHWC fp32 (dcn1 gather)
__device__ __align__(256) float g_xfc [(size_t)ROWSA * 64];          // fc out fp32 (dcn2 gather)
__device__ __align__(256) float g_offb[(size_t)ROWSA * 216];         // offset conv out (NHWC)
__device__ __align__(256) __nv_bfloat16 g_nbr_h[(size_t)ROWSA*64], g_nbr_l[(size_t)ROWSA*64];
__device__ __align__(256) __nv_bfloat16 g_ref_h[(size_t)ROWSA*64], g_ref_l[(size_t)ROWSA*64];
__device__ __align__(256) __nv_bfloat16 g_b1_h [(size_t)ROWSA*64], g_b1_l [(size_t)ROWSA*64];
__device__ __align__(256) __nv_bfloat16 g_b2_h [(size_t)ROWSA*64], g_b2_l [(size_t)ROWSA*64];
__device__ __align__(256) __nv_bfloat16 g_b3_h [(size_t)ROWSA*64], g_b3_l [(size_t)ROWSA*64];
__device__ __align__(256) __nv_bfloat16 g_b4_h [(size_t)ROWSA*64], g_b4_l [(size_t)ROWSA*64];
// per-conv prepped weights (hi/lo), laid out back-to-back
#define WOFF_OC1   0
#define WOFF_OC2   (WOFF_OC1 + 9*2*64*64)
#define WOFF_D1OFF (WOFF_OC2 + 9*1*64*64)
#define WOFF_FC    (WOFF_D1OFF + 9*1*216*64)
#define WOFF_CAS1  (WOFF_FC + 9*1*64*64)
#define WOFF_CAS2  (WOFF_CAS1 + 9*2*64*64)
#define WOFF_CDOFF (WOFF_CAS2 + 9*1*64*64)
#define WTOT       (WOFF_CDOFF + 9*1*216*64)
__device__ __align__(256) __nv_bfloat16 g_w_h[WTOT], g_w_l[WTOT];

// ---------------- PTX helpers (baseline ISA, compute_103-legal) ----------------
__device__ __forceinline__ uint32_t smem_u32(const void* p) {
    uint32_t a;
    asm("{ .reg .u64 t; cvta.to.shared.u64 t, %1; cvt.u32.u64 %0, t; }" : "=r"(a) : "l"(p));
    return a;
}
__device__ __forceinline__ void ldsm_x4(uint32_t* r, uint32_t a) {
    asm volatile("ldmatrix.sync.aligned.m8n8.x4.shared.b16 {%0,%1,%2,%3}, [%4];"
        : "=r"(r[0]), "=r"(r[1]), "=r"(r[2]), "=r"(r[3]) : "r"(a));
}
__device__ __forceinline__ void ldsm_x2(uint32_t* r, uint32_t a) {
    asm volatile("ldmatrix.sync.aligned.m8n8.x2.shared.b16 {%0,%1}, [%2];"
        : "=r"(r[0]), "=r"(r[1]) : "r"(a));
}
__device__ __forceinline__ void mma_bf16(float* c, const uint32_t* a, const uint32_t* b) {
    asm volatile(
        "mma.sync.aligned.m16n8k16.row.col.f32.bf16.bf16.f32 "
        "{%0,%1,%2,%3}, {%4,%5,%6,%7}, {%8,%9}, {%0,%1,%2,%3};"
        : "+f"(c[0]), "+f"(c[1]), "+f"(c[2]), "+f"(c[3])
        : "r"(a[0]), "r"(a[1]), "r"(a[2]), "r"(a[3]), "r"(b[0]), "r"(b[1]));
}
__device__ __forceinline__ void cpasync16(uint32_t dst, const void* src) {
    asm volatile("cp.async.cg.shared.global [%0], [%1], 16;" :: "r"(dst), "l"(src));
}
__device__ __forceinline__ void cpcommit() { asm volatile("cp.async.commit_group;" ::: "memory"); }
__device__ __forceinline__ void cpwait1()  { asm volatile("cp.async.wait_group 1;" ::: "memory"); }
__device__ __forceinline__ void cpwait0()  { asm volatile("cp.async.wait_group 0;" ::: "memory"); }

// ---------------- input conversion: NCHW fp32 -> padded NHWC (fp32 opt + bf16 hi/lo) ----------------
template<bool F32OUT>
__global__ void convert_in_kernel(const float* __restrict__ in, float* __restrict__ outF,
                                  __nv_bfloat16* __restrict__ hi, __nv_bfloat16* __restrict__ lo)
{
    int p = blockIdx.x * blockDim.x + threadIdx.x;
    if (p >= BB * HWW) return;
    int x = p % WW; int t = p / WW; int y = t % HH; int b = t / HH;
    size_t g = (size_t)GUARD + (size_t)b * PIMG + (size_t)(y + 1) * PW + (x + 1);
#pragma unroll
    for (int c = 0; c < 64; ++c) {
        float v = in[((size_t)(b * 64 + c)) * HWW + (size_t)y * WW + x];
        if (F32OUT) outF[g * 64 + c] = v;
        __nv_bfloat16 h = __float2bfloat16(v);
        hi[g * 64 + c] = h;
        lo[g * 64 + c] = __float2bfloat16(v - __bfloat162float(h));
    }
}

// ---------------- weight prep: OIHW fp32 -> [tap][seg][n][64k] bf16 hi/lo at offset ----------------
__global__ void weight_prep_kernel(const float* __restrict__ w, int O, int Cin, size_t woff,
                                   __nv_bfloat16* __restrict__ whi, __nv_bfloat16* __restrict__ wlo)
{
    int idx = blockIdx.x * blockDim.x + threadIdx.x;
    if (idx >= O * Cin * 9) return;
    int tap = idx % 9; int t = idx / 9; int ci = t % Cin; int o = t / Cin;
    float v = w[idx];
    int seg = ci >> 6, k = ci & 63;
    size_t dst = woff + (((size_t)tap * (Cin >> 6) + seg) * O + o) * 64 + k;
    __nv_bfloat16 h = __float2bfloat16(v);
    whi[dst] = h;
    wlo[dst] = __float2bfloat16(v - __bfloat162float(h));
}

// ---------------- conv as shifted-window implicit GEMM (bf16 3-term, cp.async pipelined) ----------------
// One CTA: M=256 pixel rows, 8 warps (m=32 each), NT output channels (blockIdx.y = ch tile).
// Double-buffered (tap,seg) stages staged via cp.async.cg into SW128-swizzled smem.
template<int NT, int NTOT, int SEGS, bool EPI_F32, bool EPI_BF16, bool LRELU>
__global__ __launch_bounds__(256)
void conv_mma_kernel(const __nv_bfloat16* __restrict__ Ahi0, const __nv_bfloat16* __restrict__ Alo0,
                     const __nv_bfloat16* __restrict__ Ahi1, const __nv_bfloat16* __restrict__ Alo1,
                     const __nv_bfloat16* __restrict__ Whi, const __nv_bfloat16* __restrict__ Wlo,
                     const float* __restrict__ bias,
                     float* __restrict__ outF,
                     __nv_bfloat16* __restrict__ outHi, __nv_bfloat16* __restrict__ outLo)
{
    extern __shared__ __align__(1024) char smem[];
    constexpr int OFF_ALO = 32768;                // A hi: 256*128 = 32768
    constexpr int OFF_BHI = 65536;
    constexpr int OFF_BLO = 65536 + NT * 128;
    constexpr int STAGE   = 65536 + NT * 256;     // Ahi Alo Bhi Blo
    constexpr int NB  = NT / 8;
    constexpr int NBP = NB / 2;
    constexpr bool NBODD = (NB & 1) != 0;
    constexpr int NST = 9 * SEGS;

    float* sBias = (float*)smem;                  // [0,1024)
    const uint32_t sb = smem_u32(smem);

    const int tid  = threadIdx.x;
    const int lane = tid & 31;
    const int warp = tid >> 5;
    const int ocb  = blockIdx.y;
    const long m0  = (long)blockIdx.x * 256;

    for (int i = tid; i < NT; i += 256) sBias[i] = bias[ocb * NT + i];

    float acc[2][NB][4];
#pragma unroll
    for (int mt = 0; mt < 2; ++mt)
#pragma unroll
        for (int nb = 0; nb < NB; ++nb)
#pragma unroll
            for (int j = 0; j < 4; ++j) acc[mt][nb][j] = 0.f;

    const int l7 = lane & 7;
    const uint32_t aRow = (uint32_t)(warp * 32 + ((lane >> 3) & 1) * 8 + l7);
    const int aU = (lane >> 4) & 1;
    const int bKh = (lane >> 3) & 1;
    const int bNs = (lane >> 4) & 1;

    // ---- stage loader: cp.async.cg, SW128-swizzled destinations ----
    auto load_stage = [&](int s, int buf) {
        const int tap = s / SEGS, seg = s % SEGS;
        const int dy = tap / 3 - 1, dx = tap % 3 - 1;
        const long shift = (long)GUARD + m0 + (long)dy * PW + dx;
        const uint32_t stb = sb + 1024 + buf * STAGE;
        const __nv_bfloat16* ah = (seg == 0) ? Ahi0 : Ahi1;
        const __nv_bfloat16* al = (seg == 0) ? Alo0 : Alo1;
        // A: one 128B row (64 bf16) per thread, hi+lo (256 rows)
        {
            const char* srch = (const char*)(ah + (size_t)(shift + tid) * 64);
            const char* srcl = (const char*)(al + (size_t)(shift + tid) * 64);
            uint32_t ro = (uint32_t)tid * 128;
            uint32_t sx = ((uint32_t)tid & 7) * 16;
#pragma unroll
            for (int i = 0; i < 8; ++i) {
                uint32_t o = ro + (((uint32_t)i * 16) ^ sx);
                cpasync16(stb + o, srch + i * 16);
                cpasync16(stb + OFF_ALO + o, srcl + i * 16);
            }
        }
        // B: NT rows
        const size_t wbase = (((size_t)tap * SEGS + seg) * NTOT + (size_t)ocb * NT);
        for (int n = tid; n < NT; n += 256) {
            const char* swh = (const char*)(Whi + (wbase + n) * 64);
            const char* swl = (const char*)(Wlo + (wbase + n) * 64);
            uint32_t ro = (uint32_t)n * 128;
            uint32_t sx = ((uint32_t)n & 7) * 16;
#pragma unroll
            for (int i = 0; i < 8; ++i) {
                uint32_t o = ro + (((uint32_t)i * 16) ^ sx);
                cpasync16(stb + OFF_BHI + o, swh + i * 16);
                cpasync16(stb + OFF_BLO + o, swl + i * 16);
            }
        }
        cpcommit();
    };

    load_stage(0, 0);

    for (int s = 0; s < NST; ++s) {
        const int buf = s & 1;
        if (s + 1 < NST) { load_stage(s + 1, buf ^ 1); cpwait1(); }
        else             { cpwait0(); }
        __syncthreads();   // stage s visible to all warps

        const uint32_t stb = sb + 1024 + buf * STAGE;
#pragma unroll
        for (int c = 0; c < 4; ++c) {
            uint32_t ahf[2][4], alf[2][4];
#pragma unroll
            for (int mt = 0; mt < 2; ++mt) {
                uint32_t row = aRow + mt * 16;
                uint32_t off = row * 128 + ((uint32_t)((2 * c + aU) ^ l7)) * 16;
                ldsm_x4(ahf[mt], stb + off);
                ldsm_x4(alf[mt], stb + OFF_ALO + off);
            }
#pragma unroll
            for (int nbp = 0; nbp < NBP; ++nbp) {
                uint32_t row = (uint32_t)((nbp * 2 + bNs) * 8 + l7);
                uint32_t offb = row * 128 + ((uint32_t)((2 * c + bKh) ^ l7)) * 16;
                uint32_t bh[4], bl[4];
                ldsm_x4(bh, stb + OFF_BHI + offb);
                ldsm_x4(bl, stb + OFF_BLO + offb);
#pragma unroll
                for (int half = 0; half < 2; ++half) {
                    const int nb = nbp * 2 + half;
                    mma_bf16(acc[0][nb], ahf[0], bh + 2 * half);
                    mma_bf16(acc[1][nb], ahf[1], bh + 2 * half);
                    mma_bf16(acc[0][nb], ahf[0], bl + 2 * half);
                    mma_bf16(acc[1][nb], ahf[1], bl + 2 * half);
                    mma_bf16(acc[0][nb], alf[0], bh + 2 * half);
                    mma_bf16(acc[1][nb], alf[1], bh + 2 * half);
                }
            }
            if (NBODD) {
                const int nb = NB - 1;
                uint32_t row = (uint32_t)(nb * 8 + l7);
                uint32_t offb = row * 128 + ((uint32_t)((2 * c + bKh) ^ l7)) * 16;
                uint32_t bh[2], bl[2];
                ldsm_x2(bh, stb + OFF_BHI + offb);
                ldsm_x2(bl, stb + OFF_BLO + offb);
                mma_bf16(acc[0][nb], ahf[0], bh);
                mma_bf16(acc[1][nb], ahf[1], bh);
                mma_bf16(acc[0][nb], ahf[0], bl);
                mma_bf16(acc[1][nb], ahf[1], bl);
                mma_bf16(acc[0][nb], alf[0], bh);
                mma_bf16(acc[1][nb], alf[1], bh);
            }
        }
        __syncthreads();   // reads done before buf is overwritten by stage s+2
    }

    // ---- epilogue: c-frag rows lane/4 (+8), cols 2*(lane%4)+{0,1} ----
    const long gbase = m0 + warp * 32;
    const int ncol0 = 2 * (lane & 3);
#pragma unroll
    for (int mt = 0; mt < 2; ++mt) {
#pragma unroll
        for (int half = 0; half < 2; ++half) {
            long g = gbase + mt * 16 + (lane >> 2) + half * 8;
            bool valid = (g < MROWS);
            if (valid) {
                long q = g % PIMG;
                int py = (int)(q / PW), px = (int)(q % PW);
                valid = (py >= 1) && (py < PW - 1) && (px >= 1) && (px < PW - 1);
            }
            if (!valid) continue;
            const size_t orow = (size_t)(GUARD + g);
#pragma unroll
            for (int nb = 0; nb < NB; ++nb) {
                float v0 = acc[mt][nb][half * 2 + 0] + sBias[nb * 8 + ncol0];
                float v1 = acc[mt][nb][half * 2 + 1] + sBias[nb * 8 + ncol0 + 1];
                if (LRELU) {
                    v0 = (v0 >= 0.f) ? v0 : 0.1f * v0;
                    v1 = (v1 >= 0.f) ? v1 : 0.1f * v1;
                }
                const size_t col = (size_t)ocb * NT + nb * 8 + ncol0;
                if (EPI_F32) {
                    outF[orow * NTOT + col]     = v0;
                    outF[orow * NTOT + col + 1] = v1;
                }
                if (EPI_BF16) {
                    __nv_bfloat16 h0 = __float2bfloat16(v0);
                    __nv_bfloat16 h1 = __float2bfloat16(v1);
                    outHi[orow * NTOT + col]     = h0;
                    outHi[orow * NTOT + col + 1] = h1;
                    outLo[orow * NTOT + col]     = __float2bfloat16(v0 - __bfloat162float(h0));
                    outLo[orow * NTOT + col + 1] = __float2bfloat16(v1 - __bfloat162float(h1));
                }
            }
        }
    }
}

// ---------------- modulated deformable conv (DCNv2), NHWC in/out ----------------
template<bool LRELU, bool NCHW_OUT>
__global__ __launch_bounds__(256, 2)
void dcn_kernel(const float* __restrict__ xf,
                const float* __restrict__ off,
                const float* __restrict__ wgt,
                const float* __restrict__ bias,
                float* __restrict__ outF,
                __nv_bfloat16* __restrict__ outHi, __nv_bfloat16* __restrict__ outLo)
{
    __shared__ __align__(16) float sW[2][CG * 9 * 64];

    const int tid = threadIdx.x;
    const int tx  = tid % 32;
    const int ty  = tid / 32;
    const int b   = blockIdx.z;
    const int gx  = blockIdx.x * 32 + tx;
    const int gy  = blockIdx.y * 8 + ty;

    float acc[64];
#pragma unroll
    for (int i = 0; i < 64; ++i) acc[i] = 0.f;

    const size_t prow = (size_t)GUARD + (size_t)b * PIMG + (size_t)(gy + 1) * PW + (gx + 1);
    const float* offP = off + prow * 216;

    auto load_w = [&](int dg, int sel) {
        for (int i = tid; i < CG * 9 * 64; i += 256) {
            int oc = i % 64;
            int r  = i / 64;
            int k  = r % 9;
            int cg = r / 9;
            sW[sel][i] = wgt[(size_t)oc * (CC * 9) + (dg * CG + cg) * 9 + k];
        }
    };

    load_w(0, 0);
    __syncthreads();

    int sel = 0;
    for (int dg = 0; dg < DG; ++dg) {
        if (dg + 1 < DG) load_w(dg + 1, sel ^ 1);
        const float* cW = sW[sel];

        for (int k = 0; k < 9; ++k) {
            float dy = offP[dg * 18 + 2 * k + 0];
            float dx = offP[dg * 18 + 2 * k + 1];
            float ml = offP[144 + dg * 9 + k];
            float m  = 1.f / (1.f + __expf(-ml));

            float py = (float)gy - 1.f + (float)(k / 3) + dy;
            float px = (float)gx - 1.f + (float)(k % 3) + dx;
            float y0f = floorf(py), x0f = floorf(px);
            float wy = py - y0f, wx = px - x0f;
            int y0 = (int)y0f, x0 = (int)x0f;

            float cw00 = (1.f - wy) * (1.f - wx);
            float cw01 = (1.f - wy) * wx;
            float cw10 = wy * (1.f - wx);
            float cw11 = wy * wx;

            float sv[8];
#pragma unroll
            for (int i = 0; i < 8; ++i) sv[i] = 0.f;

#pragma unroll
            for (int cy = 0; cy < 2; ++cy) {
#pragma unroll
                for (int cx = 0; cx < 2; ++cx) {
                    int yy = y0 + cy, xx = x0 + cx;
                    float cwv = (cy == 0) ? ((cx == 0) ? cw00 : cw01)
                                          : ((cx == 0) ? cw10 : cw11);
                    if (yy >= 0 && yy < HH && xx >= 0 && xx < WW) {
                        const float4* p = reinterpret_cast<const float4*>(
                            xf + ((size_t)GUARD + (size_t)b * PIMG
                                  + (size_t)(yy + 1) * PW + (xx + 1)) * 64 + dg * 8);
                        float4 a = __ldg(&p[0]);
                        float4 c = __ldg(&p[1]);
                        sv[0] += cwv * a.x; sv[1] += cwv * a.y;
                        sv[2] += cwv * a.z; sv[3] += cwv * a.w;
                        sv[4] += cwv * c.x; sv[5] += cwv * c.y;
                        sv[6] += cwv * c.z; sv[7] += cwv * c.w;
                    }
                }
            }

#pragma unroll
            for (int cg = 0; cg < CG; ++cg) {
                float s = sv[cg] * m;
                const float4* wr = reinterpret_cast<const float4*>(cW + (cg * 9 + k) * 64);
#pragma unroll
                for (int o4 = 0; o4 < 16; ++o4) {
                    float4 w = wr[o4];
                    acc[o4 * 4 + 0] += w.x * s;
                    acc[o4 * 4 + 1] += w.y * s;
                    acc[o4 * 4 + 2] += w.z * s;
                    acc[o4 * 4 + 3] += w.w * s;
                }
            }
        }
        __syncthreads();
        sel ^= 1;
    }

#pragma unroll
    for (int oc = 0; oc < 64; ++oc) {
        float v = acc[oc] + __ldg(&bias[oc]);
        if (LRELU) v = (v >= 0.f) ? v : 0.1f * v;
        if (NCHW_OUT) {
            outF[((size_t)(b * CC + oc)) * HWW + (size_t)gy * WW + gx] = v;
        } else {
            __nv_bfloat16 h = __float2bfloat16(v);
            outHi[prow * 64 + oc] = h;
            outLo[prow * 64 + oc] = __float2bfloat16(v - __bfloat162float(h));
        }
    }
}

// ---------------- launch ----------------
extern "C" void kernel_launch(void* const* d_in, const int* in_sizes, int n_in,
                              void* d_out, int out_size)
{
    const float* nbr     = (const float*)d_in[0];
    const float* ref     = (const float*)d_in[1];
    const float* oc1_w   = (const float*)d_in[2];
    const float* oc1_b   = (const float*)d_in[3];
    const float* oc2_w   = (const float*)d_in[4];
    const float* oc2_b   = (const float*)d_in[5];
    const float* d1off_w = (const float*)d_in[6];
    const float* d1off_b = (const float*)d_in[7];
    const float* dcn1_w  = (const float*)d_in[8];
    const float* dcn1_b  = (const float*)d_in[9];
    const float* fc_w    = (const float*)d_in[10];
    const float* fc_b    = (const float*)d_in[11];
    const float* cas1_w  = (const float*)d_in[12];
    const float* cas1_b  = (const float*)d_in[13];
    const float* cas2_w  = (const float*)d_in[14];
    const float* cas2_b  = (const float*)d_in[15];
    const float* cdoff_w = (const float*)d_in[16];
    const float* cdoff_b = (const float*)d_in[17];
    const float* casd_w  = (const float*)d_in[18];
    const float* casd_b  = (const float*)d_in[19];
    float* outp = (float*)d_out;

    float *xnbr, *xfc, *offb;
    __nv_bfloat16 *nh, *nl, *rh, *rl, *b1h, *b1l, *b2h, *b2l, *b3h, *b3l, *b4h, *b4l, *wh, *wl;
    cudaGetSymbolAddress((void**)&xnbr, g_xnbr);
    cudaGetSymbolAddress((void**)&xfc,  g_xfc);
    cudaGetSymbolAddress((void**)&offb, g_offb);
    cudaGetSymbolAddress((void**)&nh,  g_nbr_h); cudaGetSymbolAddress((void**)&nl, g_nbr_l);
    cudaGetSymbolAddress((void**)&rh,  g_ref_h); cudaGetSymbolAddress((void**)&rl, g_ref_l);
    cudaGetSymbolAddress((void**)&b1h, g_b1_h);  cudaGetSymbolAddress((void**)&b1l, g_b1_l);
    cudaGetSymbolAddress((void**)&b2h, g_b2_h);  cudaGetSymbolAddress((void**)&b2l, g_b2_l);
    cudaGetSymbolAddress((void**)&b3h, g_b3_h);  cudaGetSymbolAddress((void**)&b3l, g_b3_l);
    cudaGetSymbolAddress((void**)&b4h, g_b4_h);  cudaGetSymbolAddress((void**)&b4l, g_b4_l);
    cudaGetSymbolAddress((void**)&wh,  g_w_h);   cudaGetSymbolAddress((void**)&wl,  g_w_l);

    auto C64S2 = conv_mma_kernel<64, 64, 2, false, true,  true >;   // oc1, cas1 (Cin=128)
    auto C64S1 = conv_mma_kernel<64, 64, 1, false, true,  true >;   // oc2, cas2
    auto C216  = conv_mma_kernel<72, 216, 1, true,  false, false>;  // offset convs (3 ch-tiles)
    auto CFC   = conv_mma_kernel<64, 64, 1, true,  true,  false>;   // fc

    const int smem64 = 1024 + 2 * (65536 + 64 * 256);   // 164864
    const int smem72 = 1024 + 2 * (65536 + 72 * 256);   // 169984... (72*256=18432)*2+131072+1024 = 168960+... 
    cudaFuncSetAttribute(C64S2, cudaFuncAttributeMaxDynamicSharedMemorySize, smem64);
    cudaFuncSetAttribute(C64S1, cudaFuncAttributeMaxDynamicSharedMemorySize, smem64);
    cudaFuncSetAttribute(CFC,   cudaFuncAttributeMaxDynamicSharedMemorySize, smem64);
    cudaFuncSetAttribute(C216,  cudaFuncAttributeMaxDynamicSharedMemorySize, smem72);

    const int cvtGrid = (BB * HWW + 255) / 256;
    dim3 g64(NTIL256, 1), g216(NTIL256, 3);
    dim3 gDcn(WW / 32, HH / 8, BB);

    // 0) conversions + ALL weight preps up front (no inter-conv dependencies)
    convert_in_kernel<true ><<<cvtGrid, 256>>>(nbr, xnbr, nh, nl);
    convert_in_kernel<false><<<cvtGrid, 256>>>(ref, nullptr, rh, rl);
    weight_prep_kernel<<<(64 * 128 * 9 + 255) / 256, 256>>>(oc1_w,   64, 128, WOFF_OC1,   wh, wl);
    weight_prep_kernel<<<(64 * 64 * 9 + 255) / 256, 256>>>(oc2_w,    64, 64,  WOFF_OC2,   wh, wl);
    weight_prep_kernel<<<(216 * 64 * 9 + 255) / 256, 256>>>(d1off_w, 216, 64, WOFF_D1OFF, wh, wl);
    weight_prep_kernel<<<(64 * 64 * 9 + 255) / 256, 256>>>(fc_w,     64, 64,  WOFF_FC,    wh, wl);
    weight_prep_kernel<<<(64 * 128 * 9 + 255) / 256, 256>>>(cas1_w,  64, 128, WOFF_CAS1,  wh, wl);
    weight_prep_kernel<<<(64 * 64 * 9 + 255) / 256, 256>>>(cas2_w,   64, 64,  WOFF_CAS2,  wh, wl);
    weight_prep_kernel<<<(216 * 64 * 9 + 255) / 256, 256>>>(cdoff_w, 216, 64, WOFF_CDOFF, wh, wl);

    // 1) offset = lrelu(conv(cat(nbr, ref), oc1))
    C64S2<<<g64, 256, smem64>>>(nh, nl, rh, rl, wh + WOFF_OC1, wl + WOFF_OC1, oc1_b, nullptr, b1h, b1l);
    // 2) offset = lrelu(conv(offset, oc2))
    C64S1<<<g64, 256, smem64>>>(b1h, b1l, nullptr, nullptr, wh + WOFF_OC2, wl + WOFF_OC2, oc2_b, nullptr, b2h, b2l);
    // 3) dcn1 offset/mask conv (216 ch, raw)
    C216<<<g216, 256, smem72>>>(b2h, b2l, nullptr, nullptr, wh + WOFF_D1OFF, wl + WOFF_D1OFF, d1off_b, offb, nullptr, nullptr);
    // 4) feat = dcn(nbr, off)  -> bf16 hi/lo NHWC
    dcn_kernel<false, false><<<gDcn, 256>>>(xnbr, offb, dcn1_w, dcn1_b, nullptr, b3h, b3l);
    // 5) feat = conv(feat, fc) -> fp32 NHWC (gather src) + bf16 hi/lo
    CFC<<<g64, 256, smem64>>>(b3h, b3l, nullptr, nullptr, wh + WOFF_FC, wl + WOFF_FC, fc_b, xfc, b4h, b4l);
    // 6) offset = lrelu(conv(cat(feat, ref), cas1))
    C64S2<<<g64, 256, smem64>>>(b4h, b4l, rh, rl, wh + WOFF_CAS1, wl + WOFF_CAS1, cas1_b, nullptr, b1h, b1l);
    // 7) offset = lrelu(conv(offset, cas2))
    C64S1<<<g64, 256, smem64>>>(b1h, b1l, nullptr, nullptr, wh + WOFF_CAS2, wl + WOFF_CAS2, cas2_b, nullptr, b2h, b2l);
    // 8) casd offset/mask conv
    C216<<<g216, 256, smem72>>>(b2h, b2l, nullptr, nullptr, wh + WOFF_CDOFF, wl + WOFF_CDOFF, cdoff_b, offb, nullptr, nullptr);
    // 9) out = lrelu(dcn(feat, off)) -> NCHW fp32
    dcn_kernel<true, true><<<gDcn, 256>>>(xfc, offb, casd_w, casd_b, outp, nullptr, nullptr);

    (void)in_sizes; (void)n_in; (void)out_size;
}

// round 8
// speedup vs baseline: 2.9558x; 1.1958x over previous
#include <cuda_runtime.h>
#include <cuda_bf16.h>
#include <cstdint>

// ---------------- problem constants ----------------
#define BB 4
#define CC 64
#define HH 192
#define WW 192
#define HWW (HH*WW)
#define DG 8
#define CG 8
#define PW 194                      // padded width/height (H+2)
#define PIMG (PW*PW)                // 37636 padded pixels per image
#define MROWS (BB*PIMG)             // 150544 total padded pixels
#define GUARD 512                   // zero guard rows front
#define ROWSA (GUARD + MROWS + 1024)
#define NTIL256 ((MROWS + 255)/256) // 589

// ---------------- scratch (static device globals; zero-initialized) ----------------
__device__ __align__(256) float g_xnbr[(size_t)ROWSA * 64];          // padded NHWC fp32 (dcn1 gather)
__device__ __align__(256) float g_xfc [(size_t)ROWSA * 64];          // fc out fp32 (dcn2 gather)
__device__ __align__(256) float g_offb[(size_t)ROWSA * 216];         // offset conv out (NHWC)
__device__ __align__(256) __nv_bfloat16 g_nbr_h[(size_t)ROWSA*64], g_nbr_l[(size_t)ROWSA*64];
__device__ __align__(256) __nv_bfloat16 g_ref_h[(size_t)ROWSA*64], g_ref_l[(size_t)ROWSA*64];
__device__ __align__(256) __nv_bfloat16 g_b1_h [(size_t)ROWSA*64], g_b1_l [(size_t)ROWSA*64];
__device__ __align__(256) __nv_bfloat16 g_b2_h [(size_t)ROWSA*64], g_b2_l [(size_t)ROWSA*64];
__device__ __align__(256) __nv_bfloat16 g_b3_h [(size_t)ROWSA*64], g_b3_l [(size_t)ROWSA*64];
__device__ __align__(256) __nv_bfloat16 g_b4_h [(size_t)ROWSA*64], g_b4_l [(size_t)ROWSA*64];
// per-conv prepped weights (hi/lo), laid out back-to-back
#define WOFF_OC1   0
#define WOFF_OC2   (WOFF_OC1 + 9*2*64*64)
#define WOFF_D1OFF (WOFF_OC2 + 9*1*64*64)
#define WOFF_FC    (WOFF_D1OFF + 9*1*216*64)
#define WOFF_CAS1  (WOFF_FC + 9*1*64*64)
#define WOFF_CAS2  (WOFF_CAS1 + 9*2*64*64)
#define WOFF_CDOFF (WOFF_CAS2 + 9*1*64*64)
#define WTOT       (WOFF_CDOFF + 9*1*216*64)
__device__ __align__(256) __nv_bfloat16 g_w_h[WTOT], g_w_l[WTOT];

// ---------------- PTX helpers (baseline ISA, compute_103-legal) ----------------
__device__ __forceinline__ uint32_t smem_u32(const void* p) {
    uint32_t a;
    asm("{ .reg .u64 t; cvta.to.shared.u64 t, %1; cvt.u32.u64 %0, t; }" : "=r"(a) : "l"(p));
    return a;
}
__device__ __forceinline__ void ldsm_x4(uint32_t* r, uint32_t a) {
    asm volatile("ldmatrix.sync.aligned.m8n8.x4.shared.b16 {%0,%1,%2,%3}, [%4];"
        : "=r"(r[0]), "=r"(r[1]), "=r"(r[2]), "=r"(r[3]) : "r"(a));
}
__device__ __forceinline__ void ldsm_x2(uint32_t* r, uint32_t a) {
    asm volatile("ldmatrix.sync.aligned.m8n8.x2.shared.b16 {%0,%1}, [%2];"
        : "=r"(r[0]), "=r"(r[1]) : "r"(a));
}
__device__ __forceinline__ void mma_bf16(float* c, const uint32_t* a, const uint32_t* b) {
    asm volatile(
        "mma.sync.aligned.m16n8k16.row.col.f32.bf16.bf16.f32 "
        "{%0,%1,%2,%3}, {%4,%5,%6,%7}, {%8,%9}, {%0,%1,%2,%3};"
        : "+f"(c[0]), "+f"(c[1]), "+f"(c[2]), "+f"(c[3])
        : "r"(a[0]), "r"(a[1]), "r"(a[2]), "r"(a[3]), "r"(b[0]), "r"(b[1]));
}
__device__ __forceinline__ void cpasync16(uint32_t dst, const void* src) {
    asm volatile("cp.async.cg.shared.global [%0], [%1], 16;" :: "r"(dst), "l"(src));
}
__device__ __forceinline__ void cpcommit() { asm volatile("cp.async.commit_group;" ::: "memory"); }
__device__ __forceinline__ void cpwait1()  { asm volatile("cp.async.wait_group 1;" ::: "memory"); }

// ---------------- input conversion: NCHW fp32 -> padded NHWC (fp32 opt + bf16 hi/lo) ----------------
template<bool F32OUT>
__global__ void convert_in_kernel(const float* __restrict__ in, float* __restrict__ outF,
                                  __nv_bfloat16* __restrict__ hi, __nv_bfloat16* __restrict__ lo)
{
    int p = blockIdx.x * blockDim.x + threadIdx.x;
    if (p >= BB * HWW) return;
    int x = p % WW; int t = p / WW; int y = t % HH; int b = t / HH;
    size_t g = (size_t)GUARD + (size_t)b * PIMG + (size_t)(y + 1) * PW + (x + 1);
#pragma unroll
    for (int c = 0; c < 64; ++c) {
        float v = in[((size_t)(b * 64 + c)) * HWW + (size_t)y * WW + x];
        if (F32OUT) outF[g * 64 + c] = v;
        __nv_bfloat16 h = __float2bfloat16(v);
        hi[g * 64 + c] = h;
        lo[g * 64 + c] = __float2bfloat16(v - __bfloat162float(h));
    }
}

// ---------------- weight prep: OIHW fp32 -> [tap][seg][n][64k] bf16 hi/lo at offset ----------------
__global__ void weight_prep_kernel(const float* __restrict__ w, int O, int Cin, size_t woff,
                                   __nv_bfloat16* __restrict__ whi, __nv_bfloat16* __restrict__ wlo)
{
    int idx = blockIdx.x * blockDim.x + threadIdx.x;
    if (idx >= O * Cin * 9) return;
    int tap = idx % 9; int t = idx / 9; int ci = t % Cin; int o = t / Cin;
    float v = w[idx];
    int seg = ci >> 6, k = ci & 63;
    size_t dst = woff + (((size_t)tap * (Cin >> 6) + seg) * O + o) * 64 + k;
    __nv_bfloat16 h = __float2bfloat16(v);
    whi[dst] = h;
    wlo[dst] = __float2bfloat16(v - __bfloat162float(h));
}

// ---------------- conv as shifted-window implicit GEMM (bf16 3-term) ----------------
// One CTA: M=256 pixel rows, 8 warps (m=32 each), NT channels (blockIdx.y = ch tile).
// A staged ONCE per (dy,seg) superstage as a 258-row panel (double-buffered, two half
// commits); the three dx taps read it via a +dx ldmatrix row offset. B staged per tap
// (triple-buffered, prefetch distance 2). One commit/wait/sync per tap stage.
template<int NT, int NTOT, int SEGS, bool EPI_F32, bool EPI_BF16, bool LRELU>
__global__ __launch_bounds__(256)
void conv_mma_kernel(const __nv_bfloat16* __restrict__ Ahi0, const __nv_bfloat16* __restrict__ Alo0,
                     const __nv_bfloat16* __restrict__ Ahi1, const __nv_bfloat16* __restrict__ Alo1,
                     const __nv_bfloat16* __restrict__ Whi, const __nv_bfloat16* __restrict__ Wlo,
                     const float* __restrict__ bias,
                     float* __restrict__ outF,
                     __nv_bfloat16* __restrict__ outHi, __nv_bfloat16* __restrict__ outLo)
{
    extern __shared__ __align__(1024) char smem[];
    constexpr int AROWS = 258;                    // 256 pixels + dx slide of 2
    constexpr int ABUF  = AROWS * 128;            // 33024 per precision
    constexpr int BBUF  = NT * 128;
    constexpr int OFF_A = 1024;                   // [AH0][AL0][AH1][AL1]
    constexpr int OFF_B = OFF_A + 4 * ABUF;       // [BH0][BL0][BH1][BL1][BH2][BL2]
    constexpr int NB  = NT / 8;
    constexpr int NBP = NB / 2;
    constexpr bool NBODD = (NB & 1) != 0;
    constexpr int NSS = 3 * SEGS;                 // superstages (dy, seg)
    constexpr int NST = 9 * SEGS;                 // tap stages

    float* sBias = (float*)smem;                  // [0,1024)
    const uint32_t sb = smem_u32(smem);

    const int tid  = threadIdx.x;
    const int lane = tid & 31;
    const int warp = tid >> 5;
    const int ocb  = blockIdx.y;
    const long m0  = (long)blockIdx.x * 256;

    for (int i = tid; i < NT; i += 256) sBias[i] = bias[ocb * NT + i];

    float acc[2][NB][4];
#pragma unroll
    for (int mt = 0; mt < 2; ++mt)
#pragma unroll
        for (int nb = 0; nb < NB; ++nb)
#pragma unroll
            for (int j = 0; j < 4; ++j) acc[mt][nb][j] = 0.f;

    const int l7 = lane & 7;
    const uint32_t aRow = (uint32_t)(warp * 32 + ((lane >> 3) & 1) * 8 + l7);
    const int aU = (lane >> 4) & 1;
    const int bKh = (lane >> 3) & 1;
    const int bNs = (lane >> 4) & 1;

    // ---- A panel loader: superstage ss=(dy,seg), half in {0,1} (129 rows each) ----
    auto load_A = [&](int ss, int buf, int half) {
        const int dy  = ss / SEGS;
        const int seg = ss % SEGS;
        const __nv_bfloat16* ah = (seg == 0) ? Ahi0 : Ahi1;
        const __nv_bfloat16* al = (seg == 0) ? Alo0 : Alo1;
        const long base = (long)GUARD + m0 + (long)(dy - 1) * PW - 1;  // row r -> base + r
        const uint32_t dAH = sb + OFF_A + buf * 2 * ABUF;
        const uint32_t dAL = dAH + ABUF;
        for (int r = half * 129 + tid; r < half * 129 + 129; r += 256) {
            const char* srch = (const char*)(ah + (size_t)(base + r) * 64);
            const char* srcl = (const char*)(al + (size_t)(base + r) * 64);
            uint32_t ro = (uint32_t)r * 128;
            uint32_t sx = ((uint32_t)r & 7) * 16;
#pragma unroll
            for (int i = 0; i < 8; ++i) {
                uint32_t o = ro + (((uint32_t)i * 16) ^ sx);
                cpasync16(dAH + o, srch + i * 16);
                cpasync16(dAL + o, srcl + i * 16);
            }
        }
    };
    // ---- B loader: tap stage s -> (tap, seg), into bbuf ----
    auto load_B = [&](int s, int bbuf) {
        const int ss = s / 3, dxi = s % 3;
        const int dy = ss / SEGS, seg = ss % SEGS;
        const int tap = dy * 3 + dxi;
        const size_t wbase = (((size_t)tap * SEGS + seg) * NTOT + (size_t)ocb * NT);
        const uint32_t dBH = sb + OFF_B + bbuf * 2 * BBUF;
        const uint32_t dBL = dBH + BBUF;
        for (int n = tid; n < NT; n += 256) {
            const char* swh = (const char*)(Whi + (wbase + n) * 64);
            const char* swl = (const char*)(Wlo + (wbase + n) * 64);
            uint32_t ro = (uint32_t)n * 128;
            uint32_t sx = ((uint32_t)n & 7) * 16;
#pragma unroll
            for (int i = 0; i < 8; ++i) {
                uint32_t o = ro + (((uint32_t)i * 16) ^ sx);
                cpasync16(dBH + o, swh + i * 16);
                cpasync16(dBL + o, swl + i * 16);
            }
        }
    };

    // ---- preamble: A(0) full + B(0) in group0; B(1) in group1 ----
    load_A(0, 0, 0); load_A(0, 0, 1); load_B(0, 0); cpcommit();
    if (NST > 1) load_B(1, 1); cpcommit();

    for (int s = 0; s < NST; ++s) {
        const int ss = s / 3, dxi = s % 3;
        cpwait1();
        __syncthreads();    // stage data visible; prior-stage reads complete

        // prefetches for this stage (exactly one commit per stage)
        if (s + 2 < NST) load_B(s + 2, (s + 2) % 3);
        if (dxi < 2 && ss + 1 < NSS) load_A(ss + 1, (ss + 1) & 1, dxi);
        cpcommit();

        const uint32_t aH = sb + OFF_A + (ss & 1) * 2 * ABUF;
        const uint32_t aL = aH + ABUF;
        const uint32_t bH = sb + OFF_B + (s % 3) * 2 * BBUF;
        const uint32_t bL = bH + BBUF;
        const uint32_t krow = (uint32_t)((l7 + dxi) & 7);

#pragma unroll
        for (int c = 0; c < 4; ++c) {
            uint32_t ahf[2][4], alf[2][4];
#pragma unroll
            for (int mt = 0; mt < 2; ++mt) {
                uint32_t row = aRow + mt * 16 + dxi;
                uint32_t off = row * 128 + ((uint32_t)((2 * c + aU)) ^ krow) * 16;
                ldsm_x4(ahf[mt], aH + off);
                ldsm_x4(alf[mt], aL + off);
            }
#pragma unroll
            for (int nbp = 0; nbp < NBP; ++nbp) {
                uint32_t row = (uint32_t)((nbp * 2 + bNs) * 8 + l7);
                uint32_t offb = row * 128 + ((uint32_t)((2 * c + bKh) ^ l7)) * 16;
                uint32_t bh[4], bl[4];
                ldsm_x4(bh, bH + offb);
                ldsm_x4(bl, bL + offb);
#pragma unroll
                for (int half = 0; half < 2; ++half) {
                    const int nb = nbp * 2 + half;
                    mma_bf16(acc[0][nb], ahf[0], bh + 2 * half);
                    mma_bf16(acc[1][nb], ahf[1], bh + 2 * half);
                    mma_bf16(acc[0][nb], ahf[0], bl + 2 * half);
                    mma_bf16(acc[1][nb], ahf[1], bl + 2 * half);
                    mma_bf16(acc[0][nb], alf[0], bh + 2 * half);
                    mma_bf16(acc[1][nb], alf[1], bh + 2 * half);
                }
            }
            if (NBODD) {
                const int nb = NB - 1;
                uint32_t row = (uint32_t)(nb * 8 + l7);
                uint32_t offb = row * 128 + ((uint32_t)((2 * c + bKh) ^ l7)) * 16;
                uint32_t bh[2], bl[2];
                ldsm_x2(bh, bH + offb);
                ldsm_x2(bl, bL + offb);
                mma_bf16(acc[0][nb], ahf[0], bh);
                mma_bf16(acc[1][nb], ahf[1], bh);
                mma_bf16(acc[0][nb], ahf[0], bl);
                mma_bf16(acc[1][nb], ahf[1], bl);
                mma_bf16(acc[0][nb], alf[0], bh);
                mma_bf16(acc[1][nb], alf[1], bh);
            }
        }
    }

    // ---- epilogue: c-frag rows lane/4 (+8), cols 2*(lane%4)+{0,1} ----
    const long gbase = m0 + warp * 32;
    const int ncol0 = 2 * (lane & 3);
#pragma unroll
    for (int mt = 0; mt < 2; ++mt) {
#pragma unroll
        for (int half = 0; half < 2; ++half) {
            long g = gbase + mt * 16 + (lane >> 2) + half * 8;
            bool valid = (g < MROWS);
            if (valid) {
                long q = g % PIMG;
                int py = (int)(q / PW), px = (int)(q % PW);
                valid = (py >= 1) && (py < PW - 1) && (px >= 1) && (px < PW - 1);
            }
            if (!valid) continue;
            const size_t orow = (size_t)(GUARD + g);
#pragma unroll
            for (int nb = 0; nb < NB; ++nb) {
                float v0 = acc[mt][nb][half * 2 + 0] + sBias[nb * 8 + ncol0];
                float v1 = acc[mt][nb][half * 2 + 1] + sBias[nb * 8 + ncol0 + 1];
                if (LRELU) {
                    v0 = (v0 >= 0.f) ? v0 : 0.1f * v0;
                    v1 = (v1 >= 0.f) ? v1 : 0.1f * v1;
                }
                const size_t col = (size_t)ocb * NT + nb * 8 + ncol0;
                if (EPI_F32) {
                    outF[orow * NTOT + col]     = v0;
                    outF[orow * NTOT + col + 1] = v1;
                }
                if (EPI_BF16) {
                    __nv_bfloat16 h0 = __float2bfloat16(v0);
                    __nv_bfloat16 h1 = __float2bfloat16(v1);
                    outHi[orow * NTOT + col]     = h0;
                    outHi[orow * NTOT + col + 1] = h1;
                    outLo[orow * NTOT + col]     = __float2bfloat16(v0 - __bfloat162float(h0));
                    outLo[orow * NTOT + col + 1] = __float2bfloat16(v1 - __bfloat162float(h1));
                }
            }
        }
    }
}

// ---------------- modulated deformable conv (DCNv2), NHWC in/out ----------------
template<bool LRELU, bool NCHW_OUT>
__global__ __launch_bounds__(256, 2)
void dcn_kernel(const float* __restrict__ xf,
                const float* __restrict__ off,
                const float* __restrict__ wgt,
                const float* __restrict__ bias,
                float* __restrict__ outF,
                __nv_bfloat16* __restrict__ outHi, __nv_bfloat16* __restrict__ outLo)
{
    __shared__ __align__(16) float sW[2][CG * 9 * 64];

    const int tid = threadIdx.x;
    const int tx  = tid % 32;
    const int ty  = tid / 32;
    const int b   = blockIdx.z;
    const int gx  = blockIdx.x * 32 + tx;
    const int gy  = blockIdx.y * 8 + ty;

    float acc[64];
#pragma unroll
    for (int i = 0; i < 64; ++i) acc[i] = 0.f;

    const size_t prow = (size_t)GUARD + (size_t)b * PIMG + (size_t)(gy + 1) * PW + (gx + 1);
    const float* offP = off + prow * 216;

    auto load_w = [&](int dg, int sel) {
        for (int i = tid; i < CG * 9 * 64; i += 256) {
            int oc = i % 64;
            int r  = i / 64;
            int k  = r % 9;
            int cg = r / 9;
            sW[sel][i] = wgt[(size_t)oc * (CC * 9) + (dg * CG + cg) * 9 + k];
        }
    };

    load_w(0, 0);
    __syncthreads();

    int sel = 0;
    for (int dg = 0; dg < DG; ++dg) {
        if (dg + 1 < DG) load_w(dg + 1, sel ^ 1);
        const float* cW = sW[sel];

        for (int k = 0; k < 9; ++k) {
            float dy = offP[dg * 18 + 2 * k + 0];
            float dx = offP[dg * 18 + 2 * k + 1];
            float ml = offP[144 + dg * 9 + k];
            float m  = 1.f / (1.f + __expf(-ml));

            float py = (float)gy - 1.f + (float)(k / 3) + dy;
            float px = (float)gx - 1.f + (float)(k % 3) + dx;
            float y0f = floorf(py), x0f = floorf(px);
            float wy = py - y0f, wx = px - x0f;
            int y0 = (int)y0f, x0 = (int)x0f;

            float cw00 = (1.f - wy) * (1.f - wx);
            float cw01 = (1.f - wy) * wx;
            float cw10 = wy * (1.f - wx);
            float cw11 = wy * wx;

            float sv[8];
#pragma unroll
            for (int i = 0; i < 8; ++i) sv[i] = 0.f;

#pragma unroll
            for (int cy = 0; cy < 2; ++cy) {
#pragma unroll
                for (int cx = 0; cx < 2; ++cx) {
                    int yy = y0 + cy, xx = x0 + cx;
                    float cwv = (cy == 0) ? ((cx == 0) ? cw00 : cw01)
                                          : ((cx == 0) ? cw10 : cw11);
                    if (yy >= 0 && yy < HH && xx >= 0 && xx < WW) {
                        const float4* p = reinterpret_cast<const float4*>(
                            xf + ((size_t)GUARD + (size_t)b * PIMG
                                  + (size_t)(yy + 1) * PW + (xx + 1)) * 64 + dg * 8);
                        float4 a = __ldg(&p[0]);
                        float4 c = __ldg(&p[1]);
                        sv[0] += cwv * a.x; sv[1] += cwv * a.y;
                        sv[2] += cwv * a.z; sv[3] += cwv * a.w;
                        sv[4] += cwv * c.x; sv[5] += cwv * c.y;
                        sv[6] += cwv * c.z; sv[7] += cwv * c.w;
                    }
                }
            }

#pragma unroll
            for (int cg = 0; cg < CG; ++cg) {
                float s = sv[cg] * m;
                const float4* wr = reinterpret_cast<const float4*>(cW + (cg * 9 + k) * 64);
#pragma unroll
                for (int o4 = 0; o4 < 16; ++o4) {
                    float4 w = wr[o4];
                    acc[o4 * 4 + 0] += w.x * s;
                    acc[o4 * 4 + 1] += w.y * s;
                    acc[o4 * 4 + 2] += w.z * s;
                    acc[o4 * 4 + 3] += w.w * s;
                }
            }
        }
        __syncthreads();
        sel ^= 1;
    }

#pragma unroll
    for (int oc = 0; oc < 64; ++oc) {
        float v = acc[oc] + __ldg(&bias[oc]);
        if (LRELU) v = (v >= 0.f) ? v : 0.1f * v;
        if (NCHW_OUT) {
            outF[((size_t)(b * CC + oc)) * HWW + (size_t)gy * WW + gx] = v;
        } else {
            __nv_bfloat16 h = __float2bfloat16(v);
            outHi[prow * 64 + oc] = h;
            outLo[prow * 64 + oc] = __float2bfloat16(v - __bfloat162float(h));
        }
    }
}

// ---------------- launch ----------------
extern "C" void kernel_launch(void* const* d_in, const int* in_sizes, int n_in,
                              void* d_out, int out_size)
{
    const float* nbr     = (const float*)d_in[0];
    const float* ref     = (const float*)d_in[1];
    const float* oc1_w   = (const float*)d_in[2];
    const float* oc1_b   = (const float*)d_in[3];
    const float* oc2_w   = (const float*)d_in[4];
    const float* oc2_b   = (const float*)d_in[5];
    const float* d1off_w = (const float*)d_in[6];
    const float* d1off_b = (const float*)d_in[7];
    const float* dcn1_w  = (const float*)d_in[8];
    const float* dcn1_b  = (const float*)d_in[9];
    const float* fc_w    = (const float*)d_in[10];
    const float* fc_b    = (const float*)d_in[11];
    const float* cas1_w  = (const float*)d_in[12];
    const float* cas1_b  = (const float*)d_in[13];
    const float* cas2_w  = (const float*)d_in[14];
    const float* cas2_b  = (const float*)d_in[15];
    const float* cdoff_w = (const float*)d_in[16];
    const float* cdoff_b = (const float*)d_in[17];
    const float* casd_w  = (const float*)d_in[18];
    const float* casd_b  = (const float*)d_in[19];
    float* outp = (float*)d_out;

    float *xnbr, *xfc, *offb;
    __nv_bfloat16 *nh, *nl, *rh, *rl, *b1h, *b1l, *b2h, *b2l, *b3h, *b3l, *b4h, *b4l, *wh, *wl;
    cudaGetSymbolAddress((void**)&xnbr, g_xnbr);
    cudaGetSymbolAddress((void**)&xfc,  g_xfc);
    cudaGetSymbolAddress((void**)&offb, g_offb);
    cudaGetSymbolAddress((void**)&nh,  g_nbr_h); cudaGetSymbolAddress((void**)&nl, g_nbr_l);
    cudaGetSymbolAddress((void**)&rh,  g_ref_h); cudaGetSymbolAddress((void**)&rl, g_ref_l);
    cudaGetSymbolAddress((void**)&b1h, g_b1_h);  cudaGetSymbolAddress((void**)&b1l, g_b1_l);
    cudaGetSymbolAddress((void**)&b2h, g_b2_h);  cudaGetSymbolAddress((void**)&b2l, g_b2_l);
    cudaGetSymbolAddress((void**)&b3h, g_b3_h);  cudaGetSymbolAddress((void**)&b3l, g_b3_l);
    cudaGetSymbolAddress((void**)&b4h, g_b4_h);  cudaGetSymbolAddress((void**)&b4l, g_b4_l);
    cudaGetSymbolAddress((void**)&wh,  g_w_h);   cudaGetSymbolAddress((void**)&wl,  g_w_l);

    auto C64S2 = conv_mma_kernel<64, 64, 2, false, true,  true >;   // oc1, cas1 (Cin=128)
    auto C64S1 = conv_mma_kernel<64, 64, 1, false, true,  true >;   // oc2, cas2
    auto C216  = conv_mma_kernel<72, 216, 1, true,  false, false>;  // offset convs (3 ch-tiles)
    auto CFC   = conv_mma_kernel<64, 64, 1, true,  true,  false>;   // fc

    const int smem64 = 1024 + 4 * (258 * 128) + 6 * 64 * 128;   // 182272
    const int smem72 = 1024 + 4 * (258 * 128) + 6 * 72 * 128;   // 188416
    cudaFuncSetAttribute(C64S2, cudaFuncAttributeMaxDynamicSharedMemorySize, smem64);
    cudaFuncSetAttribute(C64S1, cudaFuncAttributeMaxDynamicSharedMemorySize, smem64);
    cudaFuncSetAttribute(CFC,   cudaFuncAttributeMaxDynamicSharedMemorySize, smem64);
    cudaFuncSetAttribute(C216,  cudaFuncAttributeMaxDynamicSharedMemorySize, smem72);

    const int cvtGrid = (BB * HWW + 255) / 256;
    dim3 g64(NTIL256, 1), g216(NTIL256, 3);
    dim3 gDcn(WW / 32, HH / 8, BB);

    // 0) conversions + ALL weight preps up front
    convert_in_kernel<true ><<<cvtGrid, 256>>>(nbr, xnbr, nh, nl);
    convert_in_kernel<false><<<cvtGrid, 256>>>(ref, nullptr, rh, rl);
    weight_prep_kernel<<<(64 * 128 * 9 + 255) / 256, 256>>>(oc1_w,   64, 128, WOFF_OC1,   wh, wl);
    weight_prep_kernel<<<(64 * 64 * 9 + 255) / 256, 256>>>(oc2_w,    64, 64,  WOFF_OC2,   wh, wl);
    weight_prep_kernel<<<(216 * 64 * 9 + 255) / 256, 256>>>(d1off_w, 216, 64, WOFF_D1OFF, wh, wl);
    weight_prep_kernel<<<(64 * 64 * 9 + 255) / 256, 256>>>(fc_w,     64, 64,  WOFF_FC,    wh, wl);
    weight_prep_kernel<<<(64 * 128 * 9 + 255) / 256, 256>>>(cas1_w,  64, 128, WOFF_CAS1,  wh, wl);
    weight_prep_kernel<<<(64 * 64 * 9 + 255) / 256, 256>>>(cas2_w,   64, 64,  WOFF_CAS2,  wh, wl);
    weight_prep_kernel<<<(216 * 64 * 9 + 255) / 256, 256>>>(cdoff_w, 216, 64, WOFF_CDOFF, wh, wl);

    // 1) offset = lrelu(conv(cat(nbr, ref), oc1))
    C64S2<<<g64, 256, smem64>>>(nh, nl, rh, rl, wh + WOFF_OC1, wl + WOFF_OC1, oc1_b, nullptr, b1h, b1l);
    // 2) offset = lrelu(conv(offset, oc2))
    C64S1<<<g64, 256, smem64>>>(b1h, b1l, nullptr, nullptr, wh + WOFF_OC2, wl + WOFF_OC2, oc2_b, nullptr, b2h, b2l);
    // 3) dcn1 offset/mask conv (216 ch, raw)
    C216<<<g216, 256, smem72>>>(b2h, b2l, nullptr, nullptr, wh + WOFF_D1OFF, wl + WOFF_D1OFF, d1off_b, offb, nullptr, nullptr);
    // 4) feat = dcn(nbr, off)  -> bf16 hi/lo NHWC
    dcn_kernel<false, false><<<gDcn, 256>>>(xnbr, offb, dcn1_w, dcn1_b, nullptr, b3h, b3l);
    // 5) feat = conv(feat, fc) -> fp32 NHWC (gather src) + bf16 hi/lo
    CFC<<<g64, 256, smem64>>>(b3h, b3l, nullptr, nullptr, wh + WOFF_FC, wl + WOFF_FC, fc_b, xfc, b4h, b4l);
    // 6) offset = lrelu(conv(cat(feat, ref), cas1))
    C64S2<<<g64, 256, smem64>>>(b4h, b4l, rh, rl, wh + WOFF_CAS1, wl + WOFF_CAS1, cas1_b, nullptr, b1h, b1l);
    // 7) offset = lrelu(conv(offset, cas2))
    C64S1<<<g64, 256, smem64>>>(b1h, b1l, nullptr, nullptr, wh + WOFF_CAS2, wl + WOFF_CAS2, cas2_b, nullptr, b2h, b2l);
    // 8) casd offset/mask conv
    C216<<<g216, 256, smem72>>>(b2h, b2l, nullptr, nullptr, wh + WOFF_CDOFF, wl + WOFF_CDOFF, cdoff_b, offb, nullptr, nullptr);
    // 9) out = lrelu(dcn(feat, off)) -> NCHW fp32
    dcn_kernel<true, true><<<gDcn, 256>>>(xfc, offb, casd_w, casd_b, outp, nullptr, nullptr);

    (void)in_sizes; (void)n_in; (void)out_size;
}

// round 9
// speedup vs baseline: 3.0640x; 1.0366x over previous
#include <cuda_runtime.h>
#include <cuda_bf16.h>
#include <cstdint>

// ---------------- problem constants ----------------
#define BB 4
#define CC 64
#define HH 192
#define WW 192
#define HWW (HH*WW)
#define DG 8
#define CG 8
#define PW 194                      // padded width/height (H+2)
#define PIMG (PW*PW)                // 37636 padded pixels per image
#define MROWS (BB*PIMG)             // 150544 total padded pixels
#define GUARD 512                   // zero guard rows front
#define ROWSA (GUARD + MROWS + 1024)
#define NTIL256 ((MROWS + 255)/256) // 589

// ---------------- scratch (static device globals; zero-initialized) ----------------
__device__ __align__(256) float g_xnbr[(size_t)ROWSA * 64];          // padded NHWC fp32 (dcn1 gather)
__device__ __align__(256) float g_xfc [(size_t)ROWSA * 64];          // fc out fp32 (dcn2 gather)
__device__ __align__(256) float g_offb[(size_t)ROWSA * 216];         // offset conv out (NHWC)
__device__ __align__(256) __nv_bfloat16 g_nbr_h[(size_t)ROWSA*64], g_nbr_l[(size_t)ROWSA*64];
__device__ __align__(256) __nv_bfloat16 g_ref_h[(size_t)ROWSA*64], g_ref_l[(size_t)ROWSA*64];
__device__ __align__(256) __nv_bfloat16 g_b1_h [(size_t)ROWSA*64], g_b1_l [(size_t)ROWSA*64];
__device__ __align__(256) __nv_bfloat16 g_b2_h [(size_t)ROWSA*64], g_b2_l [(size_t)ROWSA*64];
__device__ __align__(256) __nv_bfloat16 g_b3_h [(size_t)ROWSA*64], g_b3_l [(size_t)ROWSA*64];
__device__ __align__(256) __nv_bfloat16 g_b4_h [(size_t)ROWSA*64], g_b4_l [(size_t)ROWSA*64];
// per-conv prepped weights (hi/lo), laid out back-to-back
#define WOFF_OC1   0
#define WOFF_OC2   (WOFF_OC1 + 9*2*64*64)
#define WOFF_D1OFF (WOFF_OC2 + 9*1*64*64)
#define WOFF_FC    (WOFF_D1OFF + 9*1*216*64)
#define WOFF_CAS1  (WOFF_FC + 9*1*64*64)
#define WOFF_CAS2  (WOFF_CAS1 + 9*2*64*64)
#define WOFF_CDOFF (WOFF_CAS2 + 9*1*64*64)
#define WTOT       (WOFF_CDOFF + 9*1*216*64)
__device__ __align__(256) __nv_bfloat16 g_w_h[WTOT], g_w_l[WTOT];

// ---------------- PTX helpers (baseline ISA, compute_103-legal) ----------------
__device__ __forceinline__ uint32_t smem_u32(const void* p) {
    uint32_t a;
    asm("{ .reg .u64 t; cvta.to.shared.u64 t, %1; cvt.u32.u64 %0, t; }" : "=r"(a) : "l"(p));
    return a;
}
__device__ __forceinline__ void ldsm_x4(uint32_t* r, uint32_t a) {
    asm volatile("ldmatrix.sync.aligned.m8n8.x4.shared.b16 {%0,%1,%2,%3}, [%4];"
        : "=r"(r[0]), "=r"(r[1]), "=r"(r[2]), "=r"(r[3]) : "r"(a));
}
__device__ __forceinline__ void ldsm_x2(uint32_t* r, uint32_t a) {
    asm volatile("ldmatrix.sync.aligned.m8n8.x2.shared.b16 {%0,%1}, [%2];"
        : "=r"(r[0]), "=r"(r[1]) : "r"(a));
}
__device__ __forceinline__ void mma_bf16(float* c, const uint32_t* a, const uint32_t* b) {
    asm volatile(
        "mma.sync.aligned.m16n8k16.row.col.f32.bf16.bf16.f32 "
        "{%0,%1,%2,%3}, {%4,%5,%6,%7}, {%8,%9}, {%0,%1,%2,%3};"
        : "+f"(c[0]), "+f"(c[1]), "+f"(c[2]), "+f"(c[3])
        : "r"(a[0]), "r"(a[1]), "r"(a[2]), "r"(a[3]), "r"(b[0]), "r"(b[1]));
}
__device__ __forceinline__ void cpasync16(uint32_t dst, const void* src) {
    asm volatile("cp.async.cg.shared.global [%0], [%1], 16;" :: "r"(dst), "l"(src));
}
__device__ __forceinline__ void cpcommit() { asm volatile("cp.async.commit_group;" ::: "memory"); }
__device__ __forceinline__ void cpwait1()  { asm volatile("cp.async.wait_group 1;" ::: "memory"); }

// ---------------- input conversion: NCHW fp32 -> padded NHWC (fp32 opt + bf16 hi/lo) ----------------
template<bool F32OUT>
__global__ void convert_in_kernel(const float* __restrict__ in, float* __restrict__ outF,
                                  __nv_bfloat16* __restrict__ hi, __nv_bfloat16* __restrict__ lo)
{
    int p = blockIdx.x * blockDim.x + threadIdx.x;
    if (p >= BB * HWW) return;
    int x = p % WW; int t = p / WW; int y = t % HH; int b = t / HH;
    size_t g = (size_t)GUARD + (size_t)b * PIMG + (size_t)(y + 1) * PW + (x + 1);
#pragma unroll
    for (int c = 0; c < 64; ++c) {
        float v = in[((size_t)(b * 64 + c)) * HWW + (size_t)y * WW + x];
        if (F32OUT) outF[g * 64 + c] = v;
        __nv_bfloat16 h = __float2bfloat16(v);
        hi[g * 64 + c] = h;
        lo[g * 64 + c] = __float2bfloat16(v - __bfloat162float(h));
    }
}

// ---------------- weight prep: OIHW fp32 -> [tap][seg][n][64k] bf16 hi/lo at offset ----------------
__global__ void weight_prep_kernel(const float* __restrict__ w, int O, int Cin, size_t woff,
                                   __nv_bfloat16* __restrict__ whi, __nv_bfloat16* __restrict__ wlo)
{
    int idx = blockIdx.x * blockDim.x + threadIdx.x;
    if (idx >= O * Cin * 9) return;
    int tap = idx % 9; int t = idx / 9; int ci = t % Cin; int o = t / Cin;
    float v = w[idx];
    int seg = ci >> 6, k = ci & 63;
    size_t dst = woff + (((size_t)tap * (Cin >> 6) + seg) * O + o) * 64 + k;
    __nv_bfloat16 h = __float2bfloat16(v);
    whi[dst] = h;
    wlo[dst] = __float2bfloat16(v - __bfloat162float(h));
}

// ---------------- conv as shifted-window implicit GEMM (bf16 3-term) ----------------
// One CTA: M=256 pixel rows, 8 warps (m=32 each), NT channels (blockIdx.y = ch tile).
// A panel (258 rows) SINGLE-buffered, staged once per (dy,seg) superstage; three dx taps
// read it via +dx ldmatrix row offset. B double-buffered, prefetch distance 1.
// smem < 104KB -> 2 CTAs/SM (4 warps/SMSP) to cover latency.
template<int NT, int NTOT, int SEGS, bool EPI_F32, bool EPI_BF16, bool LRELU>
__global__ __launch_bounds__(256, 2)
void conv_mma_kernel(const __nv_bfloat16* __restrict__ Ahi0, const __nv_bfloat16* __restrict__ Alo0,
                     const __nv_bfloat16* __restrict__ Ahi1, const __nv_bfloat16* __restrict__ Alo1,
                     const __nv_bfloat16* __restrict__ Whi, const __nv_bfloat16* __restrict__ Wlo,
                     const float* __restrict__ bias,
                     float* __restrict__ outF,
                     __nv_bfloat16* __restrict__ outHi, __nv_bfloat16* __restrict__ outLo)
{
    extern __shared__ __align__(1024) char smem[];
    constexpr int AROWS = 258;                    // 256 pixels + dx slide of 2
    constexpr int ABUF  = AROWS * 128;            // 33024 per precision
    constexpr int BBUF  = NT * 128;
    constexpr int OFF_A = 1024;                   // [AH][AL] single-buffered
    constexpr int OFF_B = OFF_A + 2 * ABUF;       // [BH0][BL0][BH1][BL1]
    constexpr int NB  = NT / 8;
    constexpr int NBP = NB / 2;
    constexpr bool NBODD = (NB & 1) != 0;
    constexpr int NSS = 3 * SEGS;                 // superstages (dy, seg)
    constexpr int NST = 9 * SEGS;                 // tap stages

    float* sBias = (float*)smem;                  // [0,1024)
    const uint32_t sb = smem_u32(smem);

    const int tid  = threadIdx.x;
    const int lane = tid & 31;
    const int warp = tid >> 5;
    const int ocb  = blockIdx.y;
    const long m0  = (long)blockIdx.x * 256;

    for (int i = tid; i < NT; i += 256) sBias[i] = bias[ocb * NT + i];

    float acc[2][NB][4];
#pragma unroll
    for (int mt = 0; mt < 2; ++mt)
#pragma unroll
        for (int nb = 0; nb < NB; ++nb)
#pragma unroll
            for (int j = 0; j < 4; ++j) acc[mt][nb][j] = 0.f;

    const int l7 = lane & 7;
    const uint32_t aRow = (uint32_t)(warp * 32 + ((lane >> 3) & 1) * 8 + l7);
    const int aU = (lane >> 4) & 1;
    const int bKh = (lane >> 3) & 1;
    const int bNs = (lane >> 4) & 1;

    // ---- A panel loader: full 258 rows into the single buffer ----
    auto load_A = [&](int ss) {
        const int dy  = ss / SEGS;
        const int seg = ss % SEGS;
        const __nv_bfloat16* ah = (seg == 0) ? Ahi0 : Ahi1;
        const __nv_bfloat16* al = (seg == 0) ? Alo0 : Alo1;
        const long base = (long)GUARD + m0 + (long)(dy - 1) * PW - 1;  // row r -> base + r
        const uint32_t dAH = sb + OFF_A;
        const uint32_t dAL = dAH + ABUF;
        for (int r = tid; r < AROWS; r += 256) {
            const char* srch = (const char*)(ah + (size_t)(base + r) * 64);
            const char* srcl = (const char*)(al + (size_t)(base + r) * 64);
            uint32_t ro = (uint32_t)r * 128;
            uint32_t sx = ((uint32_t)r & 7) * 16;
#pragma unroll
            for (int i = 0; i < 8; ++i) {
                uint32_t o = ro + (((uint32_t)i * 16) ^ sx);
                cpasync16(dAH + o, srch + i * 16);
                cpasync16(dAL + o, srcl + i * 16);
            }
        }
    };
    // ---- B loader: tap stage s -> (tap, seg), into bbuf = s&1 ----
    auto load_B = [&](int s) {
        const int ss = s / 3, dxi = s % 3;
        const int dy = ss / SEGS, seg = ss % SEGS;
        const int tap = dy * 3 + dxi;
        const size_t wbase = (((size_t)tap * SEGS + seg) * NTOT + (size_t)ocb * NT);
        const uint32_t dBH = sb + OFF_B + (s & 1) * 2 * BBUF;
        const uint32_t dBL = dBH + BBUF;
        for (int n = tid; n < NT; n += 256) {
            const char* swh = (const char*)(Whi + (wbase + n) * 64);
            const char* swl = (const char*)(Wlo + (wbase + n) * 64);
            uint32_t ro = (uint32_t)n * 128;
            uint32_t sx = ((uint32_t)n & 7) * 16;
#pragma unroll
            for (int i = 0; i < 8; ++i) {
                uint32_t o = ro + (((uint32_t)i * 16) ^ sx);
                cpasync16(dBH + o, swh + i * 16);
                cpasync16(dBL + o, swl + i * 16);
            }
        }
    };

    // ---- preamble: group0 = {A(0), B(0)} ----
    load_A(0); load_B(0); cpcommit();

    for (int s = 0; s < NST; ++s) {
        const int ss = s / 3, dxi = s % 3;

        __syncthreads();                 // all warps done with buffers we are about to overwrite
        if (s + 1 < NST) load_B(s + 1);  // into buf (s+1)&1 (read last at stage s-1)
        cpcommit();                      // one group per stage (may be empty)
        cpwait1();                       // everything except the just-committed group is done
        __syncthreads();                 // staged data visible to all warps

        const uint32_t aH = sb + OFF_A;
        const uint32_t aL = aH + ABUF;
        const uint32_t bH = sb + OFF_B + (s & 1) * 2 * BBUF;
        const uint32_t bL = bH + BBUF;
        const uint32_t krow = (uint32_t)((l7 + dxi) & 7);

#pragma unroll
        for (int c = 0; c < 4; ++c) {
            uint32_t ahf[2][4], alf[2][4];
#pragma unroll
            for (int mt = 0; mt < 2; ++mt) {
                uint32_t row = aRow + mt * 16 + dxi;
                uint32_t off = row * 128 + ((uint32_t)((2 * c + aU)) ^ krow) * 16;
                ldsm_x4(ahf[mt], aH + off);
                ldsm_x4(alf[mt], aL + off);
            }
#pragma unroll
            for (int nbp = 0; nbp < NBP; ++nbp) {
                uint32_t row = (uint32_t)((nbp * 2 + bNs) * 8 + l7);
                uint32_t offb = row * 128 + ((uint32_t)((2 * c + bKh) ^ l7)) * 16;
                uint32_t bh[4], bl[4];
                ldsm_x4(bh, bH + offb);
                ldsm_x4(bl, bL + offb);
#pragma unroll
                for (int half = 0; half < 2; ++half) {
                    const int nb = nbp * 2 + half;
                    mma_bf16(acc[0][nb], ahf[0], bh + 2 * half);
                    mma_bf16(acc[1][nb], ahf[1], bh + 2 * half);
                    mma_bf16(acc[0][nb], ahf[0], bl + 2 * half);
                    mma_bf16(acc[1][nb], ahf[1], bl + 2 * half);
                    mma_bf16(acc[0][nb], alf[0], bh + 2 * half);
                    mma_bf16(acc[1][nb], alf[1], bh + 2 * half);
                }
            }
            if (NBODD) {
                const int nb = NB - 1;
                uint32_t row = (uint32_t)(nb * 8 + l7);
                uint32_t offb = row * 128 + ((uint32_t)((2 * c + bKh) ^ l7)) * 16;
                uint32_t bh[2], bl[2];
                ldsm_x2(bh, bH + offb);
                ldsm_x2(bl, bL + offb);
                mma_bf16(acc[0][nb], ahf[0], bh);
                mma_bf16(acc[1][nb], ahf[1], bh);
                mma_bf16(acc[0][nb], ahf[0], bl);
                mma_bf16(acc[1][nb], ahf[1], bl);
                mma_bf16(acc[0][nb], alf[0], bh);
                mma_bf16(acc[1][nb], alf[1], bh);
            }
        }

        // at the last dx of a superstage, reload the (single-buffered) A panel
        if (dxi == 2 && ss + 1 < NSS) {
            __syncthreads();             // all warps done reading A(ss)
            load_A(ss + 1);
            cpcommit();                  // drained by the wait1 of stage s+1 (2 groups back)
        }
    }

    // ---- epilogue: c-frag rows lane/4 (+8), cols 2*(lane%4)+{0,1} ----
    const long gbase = m0 + warp * 32;
    const int ncol0 = 2 * (lane & 3);
#pragma unroll
    for (int mt = 0; mt < 2; ++mt) {
#pragma unroll
        for (int half = 0; half < 2; ++half) {
            long g = gbase + mt * 16 + (lane >> 2) + half * 8;
            bool valid = (g < MROWS);
            if (valid) {
                long q = g % PIMG;
                int py = (int)(q / PW), px = (int)(q % PW);
                valid = (py >= 1) && (py < PW - 1) && (px >= 1) && (px < PW - 1);
            }
            if (!valid) continue;
            const size_t orow = (size_t)(GUARD + g);
#pragma unroll
            for (int nb = 0; nb < NB; ++nb) {
                float v0 = acc[mt][nb][half * 2 + 0] + sBias[nb * 8 + ncol0];
                float v1 = acc[mt][nb][half * 2 + 1] + sBias[nb * 8 + ncol0 + 1];
                if (LRELU) {
                    v0 = (v0 >= 0.f) ? v0 : 0.1f * v0;
                    v1 = (v1 >= 0.f) ? v1 : 0.1f * v1;
                }
                const size_t col = (size_t)ocb * NT + nb * 8 + ncol0;
                if (EPI_F32) {
                    outF[orow * NTOT + col]     = v0;
                    outF[orow * NTOT + col + 1] = v1;
                }
                if (EPI_BF16) {
                    __nv_bfloat16 h0 = __float2bfloat16(v0);
                    __nv_bfloat16 h1 = __float2bfloat16(v1);
                    outHi[orow * NTOT + col]     = h0;
                    outHi[orow * NTOT + col + 1] = h1;
                    outLo[orow * NTOT + col]     = __float2bfloat16(v0 - __bfloat162float(h0));
                    outLo[orow * NTOT + col + 1] = __float2bfloat16(v1 - __bfloat162float(h1));
                }
            }
        }
    }
}

// ---------------- modulated deformable conv (DCNv2), NHWC in/out ----------------
template<bool LRELU, bool NCHW_OUT>
__global__ __launch_bounds__(256, 2)
void dcn_kernel(const float* __restrict__ xf,
                const float* __restrict__ off,
                const float* __restrict__ wgt,
                const float* __restrict__ bias,
                float* __restrict__ outF,
                __nv_bfloat16* __restrict__ outHi, __nv_bfloat16* __restrict__ outLo)
{
    __shared__ __align__(16) float sW[2][CG * 9 * 64];

    const int tid = threadIdx.x;
    const int tx  = tid % 32;
    const int ty  = tid / 32;
    const int b   = blockIdx.z;
    const int gx  = blockIdx.x * 32 + tx;
    const int gy  = blockIdx.y * 8 + ty;

    float acc[64];
#pragma unroll
    for (int i = 0; i < 64; ++i) acc[i] = 0.f;

    const size_t prow = (size_t)GUARD + (size_t)b * PIMG + (size_t)(gy + 1) * PW + (gx + 1);
    const float* offP = off + prow * 216;

    auto load_w = [&](int dg, int sel) {
        for (int i = tid; i < CG * 9 * 64; i += 256) {
            int oc = i % 64;
            int r  = i / 64;
            int k  = r % 9;
            int cg = r / 9;
            sW[sel][i] = wgt[(size_t)oc * (CC * 9) + (dg * CG + cg) * 9 + k];
        }
    };

    load_w(0, 0);
    __syncthreads();

    int sel = 0;
    for (int dg = 0; dg < DG; ++dg) {
        if (dg + 1 < DG) load_w(dg + 1, sel ^ 1);
        const float* cW = sW[sel];

        for (int k = 0; k < 9; ++k) {
            float dy = offP[dg * 18 + 2 * k + 0];
            float dx = offP[dg * 18 + 2 * k + 1];
            float ml = offP[144 + dg * 9 + k];
            float m  = 1.f / (1.f + __expf(-ml));

            float py = (float)gy - 1.f + (float)(k / 3) + dy;
            float px = (float)gx - 1.f + (float)(k % 3) + dx;
            float y0f = floorf(py), x0f = floorf(px);
            float wy = py - y0f, wx = px - x0f;
            int y0 = (int)y0f, x0 = (int)x0f;

            float cw00 = (1.f - wy) * (1.f - wx);
            float cw01 = (1.f - wy) * wx;
            float cw10 = wy * (1.f - wx);
            float cw11 = wy * wx;

            float sv[8];
#pragma unroll
            for (int i = 0; i < 8; ++i) sv[i] = 0.f;

#pragma unroll
            for (int cy = 0; cy < 2; ++cy) {
#pragma unroll
                for (int cx = 0; cx < 2; ++cx) {
                    int yy = y0 + cy, xx = x0 + cx;
                    float cwv = (cy == 0) ? ((cx == 0) ? cw00 : cw01)
                                          : ((cx == 0) ? cw10 : cw11);
                    if (yy >= 0 && yy < HH && xx >= 0 && xx < WW) {
                        const float4* p = reinterpret_cast<const float4*>(
                            xf + ((size_t)GUARD + (size_t)b * PIMG
                                  + (size_t)(yy + 1) * PW + (xx + 1)) * 64 + dg * 8);
                        float4 a = __ldg(&p[0]);
                        float4 c = __ldg(&p[1]);
                        sv[0] += cwv * a.x; sv[1] += cwv * a.y;
                        sv[2] += cwv * a.z; sv[3] += cwv * a.w;
                        sv[4] += cwv * c.x; sv[5] += cwv * c.y;
                        sv[6] += cwv * c.z; sv[7] += cwv * c.w;
                    }
                }
            }

#pragma unroll
            for (int cg = 0; cg < CG; ++cg) {
                float s = sv[cg] * m;
                const float4* wr = reinterpret_cast<const float4*>(cW + (cg * 9 + k) * 64);
#pragma unroll
                for (int o4 = 0; o4 < 16; ++o4) {
                    float4 w = wr[o4];
                    acc[o4 * 4 + 0] += w.x * s;
                    acc[o4 * 4 + 1] += w.y * s;
                    acc[o4 * 4 + 2] += w.z * s;
                    acc[o4 * 4 + 3] += w.w * s;
                }
            }
        }
        __syncthreads();
        sel ^= 1;
    }

#pragma unroll
    for (int oc = 0; oc < 64; ++oc) {
        float v = acc[oc] + __ldg(&bias[oc]);
        if (LRELU) v = (v >= 0.f) ? v : 0.1f * v;
        if (NCHW_OUT) {
            outF[((size_t)(b * CC + oc)) * HWW + (size_t)gy * WW + gx] = v;
        } else {
            __nv_bfloat16 h = __float2bfloat16(v);
            outHi[prow * 64 + oc] = h;
            outLo[prow * 64 + oc] = __float2bfloat16(v - __bfloat162float(h));
        }
    }
}

// ---------------- launch ----------------
extern "C" void kernel_launch(void* const* d_in, const int* in_sizes, int n_in,
                              void* d_out, int out_size)
{
    const float* nbr     = (const float*)d_in[0];
    const float* ref     = (const float*)d_in[1];
    const float* oc1_w   = (const float*)d_in[2];
    const float* oc1_b   = (const float*)d_in[3];
    const float* oc2_w   = (const float*)d_in[4];
    const float* oc2_b   = (const float*)d_in[5];
    const float* d1off_w = (const float*)d_in[6];
    const float* d1off_b = (const float*)d_in[7];
    const float* dcn1_w  = (const float*)d_in[8];
    const float* dcn1_b  = (const float*)d_in[9];
    const float* fc_w    = (const float*)d_in[10];
    const float* fc_b    = (const float*)d_in[11];
    const float* cas1_w  = (const float*)d_in[12];
    const float* cas1_b  = (const float*)d_in[13];
    const float* cas2_w  = (const float*)d_in[14];
    const float* cas2_b  = (const float*)d_in[15];
    const float* cdoff_w = (const float*)d_in[16];
    const float* cdoff_b = (const float*)d_in[17];
    const float* casd_w  = (const float*)d_in[18];
    const float* casd_b  = (const float*)d_in[19];
    float* outp = (float*)d_out;

    float *xnbr, *xfc, *offb;
    __nv_bfloat16 *nh, *nl, *rh, *rl, *b1h, *b1l, *b2h, *b2l, *b3h, *b3l, *b4h, *b4l, *wh, *wl;
    cudaGetSymbolAddress((void**)&xnbr, g_xnbr);
    cudaGetSymbolAddress((void**)&xfc,  g_xfc);
    cudaGetSymbolAddress((void**)&offb, g_offb);
    cudaGetSymbolAddress((void**)&nh,  g_nbr_h); cudaGetSymbolAddress((void**)&nl, g_nbr_l);
    cudaGetSymbolAddress((void**)&rh,  g_ref_h); cudaGetSymbolAddress((void**)&rl, g_ref_l);
    cudaGetSymbolAddress((void**)&b1h, g_b1_h);  cudaGetSymbolAddress((void**)&b1l, g_b1_l);
    cudaGetSymbolAddress((void**)&b2h, g_b2_h);  cudaGetSymbolAddress((void**)&b2l, g_b2_l);
    cudaGetSymbolAddress((void**)&b3h, g_b3_h);  cudaGetSymbolAddress((void**)&b3l, g_b3_l);
    cudaGetSymbolAddress((void**)&b4h, g_b4_h);  cudaGetSymbolAddress((void**)&b4l, g_b4_l);
    cudaGetSymbolAddress((void**)&wh,  g_w_h);   cudaGetSymbolAddress((void**)&wl,  g_w_l);

    auto C64S2 = conv_mma_kernel<64, 64, 2, false, true,  true >;   // oc1, cas1 (Cin=128)
    auto C64S1 = conv_mma_kernel<64, 64, 1, false, true,  true >;   // oc2, cas2
    auto C216  = conv_mma_kernel<72, 216, 1, true,  false, false>;  // offset convs (3 ch-tiles)
    auto CFC   = conv_mma_kernel<64, 64, 1, true,  true,  false>;   // fc

    const int smem64 = 1024 + 2 * (258 * 128) + 4 * 64 * 128;   // 99840
    const int smem72 = 1024 + 2 * (258 * 128) + 4 * 72 * 128;   // 103936
    cudaFuncSetAttribute(C64S2, cudaFuncAttributeMaxDynamicSharedMemorySize, smem64);
    cudaFuncSetAttribute(C64S1, cudaFuncAttributeMaxDynamicSharedMemorySize, smem64);
    cudaFuncSetAttribute(CFC,   cudaFuncAttributeMaxDynamicSharedMemorySize, smem64);
    cudaFuncSetAttribute(C216,  cudaFuncAttributeMaxDynamicSharedMemorySize, smem72);

    const int cvtGrid = (BB * HWW + 255) / 256;
    dim3 g64(NTIL256, 1), g216(NTIL256, 3);
    dim3 gDcn(WW / 32, HH / 8, BB);

    // 0) conversions + ALL weight preps up front
    convert_in_kernel<true ><<<cvtGrid, 256>>>(nbr, xnbr, nh, nl);
    convert_in_kernel<false><<<cvtGrid, 256>>>(ref, nullptr, rh, rl);
    weight_prep_kernel<<<(64 * 128 * 9 + 255) / 256, 256>>>(oc1_w,   64, 128, WOFF_OC1,   wh, wl);
    weight_prep_kernel<<<(64 * 64 * 9 + 255) / 256, 256>>>(oc2_w,    64, 64,  WOFF_OC2,   wh, wl);
    weight_prep_kernel<<<(216 * 64 * 9 + 255) / 256, 256>>>(d1off_w, 216, 64, WOFF_D1OFF, wh, wl);
    weight_prep_kernel<<<(64 * 64 * 9 + 255) / 256, 256>>>(fc_w,     64, 64,  WOFF_FC,    wh, wl);
    weight_prep_kernel<<<(64 * 128 * 9 + 255) / 256, 256>>>(cas1_w,  64, 128, WOFF_CAS1,  wh, wl);
    weight_prep_kernel<<<(64 * 64 * 9 + 255) / 256, 256>>>(cas2_w,   64, 64,  WOFF_CAS2,  wh, wl);
    weight_prep_kernel<<<(216 * 64 * 9 + 255) / 256, 256>>>(cdoff_w, 216, 64, WOFF_CDOFF, wh, wl);

    // 1) offset = lrelu(conv(cat(nbr, ref), oc1))
    C64S2<<<g64, 256, smem64>>>(nh, nl, rh, rl, wh + WOFF_OC1, wl + WOFF_OC1, oc1_b, nullptr, b1h, b1l);
    // 2) offset = lrelu(conv(offset, oc2))
    C64S1<<<g64, 256, smem64>>>(b1h, b1l, nullptr, nullptr, wh + WOFF_OC2, wl + WOFF_OC2, oc2_b, nullptr, b2h, b2l);
    // 3) dcn1 offset/mask conv (216 ch, raw)
    C216<<<g216, 256, smem72>>>(b2h, b2l, nullptr, nullptr, wh + WOFF_D1OFF, wl + WOFF_D1OFF, d1off_b, offb, nullptr, nullptr);
    // 4) feat = dcn(nbr, off)  -> bf16 hi/lo NHWC
    dcn_kernel<false, false><<<gDcn, 256>>>(xnbr, offb, dcn1_w, dcn1_b, nullptr, b3h, b3l);
    // 5) feat = conv(feat, fc) -> fp32 NHWC (gather src) + bf16 hi/lo
    CFC<<<g64, 256, smem64>>>(b3h, b3l, nullptr, nullptr, wh + WOFF_FC, wl + WOFF_FC, fc_b, xfc, b4h, b4l);
    // 6) offset = lrelu(conv(cat(feat, ref), cas1))
    C64S2<<<g64, 256, smem64>>>(b4h, b4l, rh, rl, wh + WOFF_CAS1, wl + WOFF_CAS1, cas1_b, nullptr, b1h, b1l);
    // 7) offset = lrelu(conv(offset, cas2))
    C64S1<<<g64, 256, smem64>>>(b1h, b1l, nullptr, nullptr, wh + WOFF_CAS2, wl + WOFF_CAS2, cas2_b, nullptr, b2h, b2l);
    // 8) casd offset/mask conv
    C216<<<g216, 256, smem72>>>(b2h, b2l, nullptr, nullptr, wh + WOFF_CDOFF, wl + WOFF_CDOFF, cdoff_b, offb, nullptr, nullptr);
    // 9) out = lrelu(dcn(feat, off)) -> NCHW fp32
    dcn_kernel<true, true><<<gDcn, 256>>>(xfc, offb, casd_w, casd_b, outp, nullptr, nullptr);

    (void)in_sizes; (void)n_in; (void)out_size;
}

// round 10
// speedup vs baseline: 3.7175x; 1.2133x over previous
#include <cuda_runtime.h>
#include <cuda_bf16.h>
#include <cstdint>

// ---------------- problem constants ----------------
#define BB 4
#define CC 64
#define HH 192
#define WW 192
#define HWW (HH*WW)
#define DG 8
#define CG 8
#define PW 194                      // padded width/height (H+2)
#define PIMG (PW*PW)                // 37636 padded pixels per image
#define MROWS (BB*PIMG)             // 150544 total padded pixels
#define GUARD 512                   // zero guard rows front
#define ROWSA (GUARD + MROWS + 1024)
#define NTIL256 ((MROWS + 255)/256) // 589
#define NTIL128 ((MROWS + 127)/128) // 1177

// ---------------- scratch (static device globals; zero-initialized) ----------------
__device__ __align__(256) float g_xnbr[(size_t)ROWSA * 64];          // padded NHWC fp32 (dcn1 gather)
__device__ __align__(256) float g_xfc [(size_t)ROWSA * 64];          // fc out fp32 (dcn2 gather)
__device__ __align__(256) float g_offb[(size_t)ROWSA * 216];         // offset conv out (NHWC)
__device__ __align__(256) __nv_bfloat16 g_nbr_h[(size_t)ROWSA*64], g_nbr_l[(size_t)ROWSA*64];
__device__ __align__(256) __nv_bfloat16 g_ref_h[(size_t)ROWSA*64], g_ref_l[(size_t)ROWSA*64];
__device__ __align__(256) __nv_bfloat16 g_b1_h [(size_t)ROWSA*64], g_b1_l [(size_t)ROWSA*64];
__device__ __align__(256) __nv_bfloat16 g_b2_h [(size_t)ROWSA*64], g_b2_l [(size_t)ROWSA*64];
__device__ __align__(256) __nv_bfloat16 g_b3_h [(size_t)ROWSA*64], g_b3_l [(size_t)ROWSA*64];
__device__ __align__(256) __nv_bfloat16 g_b4_h [(size_t)ROWSA*64], g_b4_l [(size_t)ROWSA*64];
// per-conv prepped weights (hi/lo), laid out back-to-back
#define WOFF_OC1   0
#define WOFF_OC2   (WOFF_OC1 + 9*2*64*64)
#define WOFF_D1OFF (WOFF_OC2 + 9*1*64*64)
#define WOFF_FC    (WOFF_D1OFF + 9*1*216*64)
#define WOFF_CAS1  (WOFF_FC + 9*1*64*64)
#define WOFF_CAS2  (WOFF_CAS1 + 9*2*64*64)
#define WOFF_CDOFF (WOFF_CAS2 + 9*1*64*64)
#define WOFF_DCN1  (WOFF_CDOFF + 9*1*216*64)
#define WOFF_CASD  (WOFF_DCN1 + 9*1*64*64)
#define WTOT       (WOFF_CASD + 9*1*64*64)
__device__ __align__(256) __nv_bfloat16 g_w_h[WTOT], g_w_l[WTOT];

// ---------------- PTX helpers (baseline ISA, compute_103-legal) ----------------
__device__ __forceinline__ uint32_t smem_u32(const void* p) {
    uint32_t a;
    asm("{ .reg .u64 t; cvta.to.shared.u64 t, %1; cvt.u32.u64 %0, t; }" : "=r"(a) : "l"(p));
    return a;
}
__device__ __forceinline__ void ldsm_x4(uint32_t* r, uint32_t a) {
    asm volatile("ldmatrix.sync.aligned.m8n8.x4.shared.b16 {%0,%1,%2,%3}, [%4];"
        : "=r"(r[0]), "=r"(r[1]), "=r"(r[2]), "=r"(r[3]) : "r"(a));
}
__device__ __forceinline__ void ldsm_x2(uint32_t* r, uint32_t a) {
    asm volatile("ldmatrix.sync.aligned.m8n8.x2.shared.b16 {%0,%1}, [%2];"
        : "=r"(r[0]), "=r"(r[1]) : "r"(a));
}
__device__ __forceinline__ void mma_bf16(float* c, const uint32_t* a, const uint32_t* b) {
    asm volatile(
        "mma.sync.aligned.m16n8k16.row.col.f32.bf16.bf16.f32 "
        "{%0,%1,%2,%3}, {%4,%5,%6,%7}, {%8,%9}, {%0,%1,%2,%3};"
        : "+f"(c[0]), "+f"(c[1]), "+f"(c[2]), "+f"(c[3])
        : "r"(a[0]), "r"(a[1]), "r"(a[2]), "r"(a[3]), "r"(b[0]), "r"(b[1]));
}
// m16n8k16 with only an m16k16 A-half pair (a0,a1 for rows 0-7 k, a2,a3) — full x4 frag needed.
__device__ __forceinline__ void cpasync16(uint32_t dst, const void* src) {
    asm volatile("cp.async.cg.shared.global [%0], [%1], 16;" :: "r"(dst), "l"(src));
}
__device__ __forceinline__ void cpcommit() { asm volatile("cp.async.commit_group;" ::: "memory"); }
__device__ __forceinline__ void cpwait1()  { asm volatile("cp.async.wait_group 1;" ::: "memory"); }

// ---------------- input conversion: NCHW fp32 -> padded NHWC (fp32 opt + bf16 hi/lo) ----------------
template<bool F32OUT>
__global__ void convert_in_kernel(const float* __restrict__ in, float* __restrict__ outF,
                                  __nv_bfloat16* __restrict__ hi, __nv_bfloat16* __restrict__ lo)
{
    int p = blockIdx.x * blockDim.x + threadIdx.x;
    if (p >= BB * HWW) return;
    int x = p % WW; int t = p / WW; int y = t % HH; int b = t / HH;
    size_t g = (size_t)GUARD + (size_t)b * PIMG + (size_t)(y + 1) * PW + (x + 1);
#pragma unroll
    for (int c = 0; c < 64; ++c) {
        float v = in[((size_t)(b * 64 + c)) * HWW + (size_t)y * WW + x];
        if (F32OUT) outF[g * 64 + c] = v;
        __nv_bfloat16 h = __float2bfloat16(v);
        hi[g * 64 + c] = h;
        lo[g * 64 + c] = __float2bfloat16(v - __bfloat162float(h));
    }
}

// ---------------- weight prep: OIHW fp32 -> [tap][seg][n][64k] bf16 hi/lo at offset ----------------
__global__ void weight_prep_kernel(const float* __restrict__ w, int O, int Cin, size_t woff,
                                   __nv_bfloat16* __restrict__ whi, __nv_bfloat16* __restrict__ wlo)
{
    int idx = blockIdx.x * blockDim.x + threadIdx.x;
    if (idx >= O * Cin * 9) return;
    int tap = idx % 9; int t = idx / 9; int ci = t % Cin; int o = t / Cin;
    float v = w[idx];
    int seg = ci >> 6, k = ci & 63;
    size_t dst = woff + (((size_t)tap * (Cin >> 6) + seg) * O + o) * 64 + k;
    __nv_bfloat16 h = __float2bfloat16(v);
    whi[dst] = h;
    wlo[dst] = __float2bfloat16(v - __bfloat162float(h));
}

// ---------------- conv as shifted-window implicit GEMM (bf16 3-term) ----------------
// (R9 winning config: A panel single-buffered per superstage, B double-buffered, 2 CTAs/SM)
template<int NT, int NTOT, int SEGS, bool EPI_F32, bool EPI_BF16, bool LRELU>
__global__ __launch_bounds__(256, 2)
void conv_mma_kernel(const __nv_bfloat16* __restrict__ Ahi0, const __nv_bfloat16* __restrict__ Alo0,
                     const __nv_bfloat16* __restrict__ Ahi1, const __nv_bfloat16* __restrict__ Alo1,
                     const __nv_bfloat16* __restrict__ Whi, const __nv_bfloat16* __restrict__ Wlo,
                     const float* __restrict__ bias,
                     float* __restrict__ outF,
                     __nv_bfloat16* __restrict__ outHi, __nv_bfloat16* __restrict__ outLo)
{
    extern __shared__ __align__(1024) char smem[];
    constexpr int AROWS = 258;
    constexpr int ABUF  = AROWS * 128;
    constexpr int BBUF  = NT * 128;
    constexpr int OFF_A = 1024;
    constexpr int OFF_B = OFF_A + 2 * ABUF;
    constexpr int NB  = NT / 8;
    constexpr int NBP = NB / 2;
    constexpr bool NBODD = (NB & 1) != 0;
    constexpr int NSS = 3 * SEGS;
    constexpr int NST = 9 * SEGS;

    float* sBias = (float*)smem;
    const uint32_t sb = smem_u32(smem);

    const int tid  = threadIdx.x;
    const int lane = tid & 31;
    const int warp = tid >> 5;
    const int ocb  = blockIdx.y;
    const long m0  = (long)blockIdx.x * 256;

    for (int i = tid; i < NT; i += 256) sBias[i] = bias[ocb * NT + i];

    float acc[2][NB][4];
#pragma unroll
    for (int mt = 0; mt < 2; ++mt)
#pragma unroll
        for (int nb = 0; nb < NB; ++nb)
#pragma unroll
            for (int j = 0; j < 4; ++j) acc[mt][nb][j] = 0.f;

    const int l7 = lane & 7;
    const uint32_t aRow = (uint32_t)(warp * 32 + ((lane >> 3) & 1) * 8 + l7);
    const int aU = (lane >> 4) & 1;
    const int bKh = (lane >> 3) & 1;
    const int bNs = (lane >> 4) & 1;

    auto load_A = [&](int ss) {
        const int dy  = ss / SEGS;
        const int seg = ss % SEGS;
        const __nv_bfloat16* ah = (seg == 0) ? Ahi0 : Ahi1;
        const __nv_bfloat16* al = (seg == 0) ? Alo0 : Alo1;
        const long base = (long)GUARD + m0 + (long)(dy - 1) * PW - 1;
        const uint32_t dAH = sb + OFF_A;
        const uint32_t dAL = dAH + ABUF;
        for (int r = tid; r < AROWS; r += 256) {
            const char* srch = (const char*)(ah + (size_t)(base + r) * 64);
            const char* srcl = (const char*)(al + (size_t)(base + r) * 64);
            uint32_t ro = (uint32_t)r * 128;
            uint32_t sx = ((uint32_t)r & 7) * 16;
#pragma unroll
            for (int i = 0; i < 8; ++i) {
                uint32_t o = ro + (((uint32_t)i * 16) ^ sx);
                cpasync16(dAH + o, srch + i * 16);
                cpasync16(dAL + o, srcl + i * 16);
            }
        }
    };
    auto load_B = [&](int s) {
        const int ss = s / 3, dxi = s % 3;
        const int dy = ss / SEGS, seg = ss % SEGS;
        const int tap = dy * 3 + dxi;
        const size_t wbase = (((size_t)tap * SEGS + seg) * NTOT + (size_t)ocb * NT);
        const uint32_t dBH = sb + OFF_B + (s & 1) * 2 * BBUF;
        const uint32_t dBL = dBH + BBUF;
        for (int n = tid; n < NT; n += 256) {
            const char* swh = (const char*)(Whi + (wbase + n) * 64);
            const char* swl = (const char*)(Wlo + (wbase + n) * 64);
            uint32_t ro = (uint32_t)n * 128;
            uint32_t sx = ((uint32_t)n & 7) * 16;
#pragma unroll
            for (int i = 0; i < 8; ++i) {
                uint32_t o = ro + (((uint32_t)i * 16) ^ sx);
                cpasync16(dBH + o, swh + i * 16);
                cpasync16(dBL + o, swl + i * 16);
            }
        }
    };

    load_A(0); load_B(0); cpcommit();

    for (int s = 0; s < NST; ++s) {
        const int ss = s / 3, dxi = s % 3;

        __syncthreads();
        if (s + 1 < NST) load_B(s + 1);
        cpcommit();
        cpwait1();
        __syncthreads();

        const uint32_t aH = sb + OFF_A;
        const uint32_t aL = aH + ABUF;
        const uint32_t bH = sb + OFF_B + (s & 1) * 2 * BBUF;
        const uint32_t bL = bH + BBUF;
        const uint32_t krow = (uint32_t)((l7 + dxi) & 7);

#pragma unroll
        for (int c = 0; c < 4; ++c) {
            uint32_t ahf[2][4], alf[2][4];
#pragma unroll
            for (int mt = 0; mt < 2; ++mt) {
                uint32_t row = aRow + mt * 16 + dxi;
                uint32_t off = row * 128 + ((uint32_t)((2 * c + aU)) ^ krow) * 16;
                ldsm_x4(ahf[mt], aH + off);
                ldsm_x4(alf[mt], aL + off);
            }
#pragma unroll
            for (int nbp = 0; nbp < NBP; ++nbp) {
                uint32_t row = (uint32_t)((nbp * 2 + bNs) * 8 + l7);
                uint32_t offb = row * 128 + ((uint32_t)((2 * c + bKh) ^ l7)) * 16;
                uint32_t bh[4], bl[4];
                ldsm_x4(bh, bH + offb);
                ldsm_x4(bl, bL + offb);
#pragma unroll
                for (int half = 0; half < 2; ++half) {
                    const int nb = nbp * 2 + half;
                    mma_bf16(acc[0][nb], ahf[0], bh + 2 * half);
                    mma_bf16(acc[1][nb], ahf[1], bh + 2 * half);
                    mma_bf16(acc[0][nb], ahf[0], bl + 2 * half);
                    mma_bf16(acc[1][nb], ahf[1], bl + 2 * half);
                    mma_bf16(acc[0][nb], alf[0], bh + 2 * half);
                    mma_bf16(acc[1][nb], alf[1], bh + 2 * half);
                }
            }
            if (NBODD) {
                const int nb = NB - 1;
                uint32_t row = (uint32_t)(nb * 8 + l7);
                uint32_t offb = row * 128 + ((uint32_t)((2 * c + bKh) ^ l7)) * 16;
                uint32_t bh[2], bl[2];
                ldsm_x2(bh, bH + offb);
                ldsm_x2(bl, bL + offb);
                mma_bf16(acc[0][nb], ahf[0], bh);
                mma_bf16(acc[1][nb], ahf[1], bh);
                mma_bf16(acc[0][nb], ahf[0], bl);
                mma_bf16(acc[1][nb], ahf[1], bl);
                mma_bf16(acc[0][nb], alf[0], bh);
                mma_bf16(acc[1][nb], alf[1], bh);
            }
        }

        if (dxi == 2 && ss + 1 < NSS) {
            __syncthreads();
            load_A(ss + 1);
            cpcommit();
        }
    }

    const long gbase = m0 + warp * 32;
    const int ncol0 = 2 * (lane & 3);
#pragma unroll
    for (int mt = 0; mt < 2; ++mt) {
#pragma unroll
        for (int half = 0; half < 2; ++half) {
            long g = gbase + mt * 16 + (lane >> 2) + half * 8;
            bool valid = (g < MROWS);
            if (valid) {
                long q = g % PIMG;
                int py = (int)(q / PW), px = (int)(q % PW);
                valid = (py >= 1) && (py < PW - 1) && (px >= 1) && (px < PW - 1);
            }
            if (!valid) continue;
            const size_t orow = (size_t)(GUARD + g);
#pragma unroll
            for (int nb = 0; nb < NB; ++nb) {
                float v0 = acc[mt][nb][half * 2 + 0] + sBias[nb * 8 + ncol0];
                float v1 = acc[mt][nb][half * 2 + 1] + sBias[nb * 8 + ncol0 + 1];
                if (LRELU) {
                    v0 = (v0 >= 0.f) ? v0 : 0.1f * v0;
                    v1 = (v1 >= 0.f) ? v1 : 0.1f * v1;
                }
                const size_t col = (size_t)ocb * NT + nb * 8 + ncol0;
                if (EPI_F32) {
                    outF[orow * NTOT + col]     = v0;
                    outF[orow * NTOT + col + 1] = v1;
                }
                if (EPI_BF16) {
                    __nv_bfloat16 h0 = __float2bfloat16(v0);
                    __nv_bfloat16 h1 = __float2bfloat16(v1);
                    outHi[orow * NTOT + col]     = h0;
                    outHi[orow * NTOT + col + 1] = h1;
                    outLo[orow * NTOT + col]     = __float2bfloat16(v0 - __bfloat162float(h0));
                    outLo[orow * NTOT + col + 1] = __float2bfloat16(v1 - __bfloat162float(h1));
                }
            }
        }
    }
}

// ---------------- DCNv2 via MMA: sampling (scalar) + channel mix (tensor) ----------------
// One CTA = 128 pixels (padded-linear rows), 8 warps (m=16 each). Per tap-stage s (9):
// each thread samples 4 deform-groups for its pixel (bilinear + mask, fp32), splits to
// bf16 hi/lo, stores the A panel (128 x 64, cols = dg*8+cg) swizzled to smem; then the
// standard ldmatrix + 3-term mma path. Weights via the same prepped layout as convs.
template<bool LRELU, bool NCHW_OUT>
__global__ __launch_bounds__(256, 2)
void dcn_mma_kernel(const float* __restrict__ xf,
                    const float* __restrict__ off,
                    const __nv_bfloat16* __restrict__ Whi, const __nv_bfloat16* __restrict__ Wlo,
                    const float* __restrict__ bias,
                    float* __restrict__ outF,
                    __nv_bfloat16* __restrict__ outHi, __nv_bfloat16* __restrict__ outLo)
{
    extern __shared__ __align__(1024) char smem[];
    constexpr int ABUF  = 128 * 128;              // 128 rows x 128B, per precision
    constexpr int BBUF  = 64 * 128;
    constexpr int OFF_A = 1024;                   // [AH][AL]
    constexpr int OFF_B = OFF_A + 2 * ABUF;       // [BH0][BL0][BH1][BL1]

    float* sBias = (float*)smem;
    const uint32_t sb = smem_u32(smem);

    const int tid  = threadIdx.x;
    const int lane = tid & 31;
    const int warp = tid >> 5;
    const long m0  = (long)blockIdx.x * 128;

    if (tid < 64) sBias[tid] = bias[tid];

    // pixel assignment for sampling: 2 threads per pixel, 4 dg each
    const int p   = tid >> 1;
    const int dg0 = (tid & 1) * 4;
    const long g  = m0 + p;
    const long gcl = (g < MROWS) ? g : 0;
    const int b   = (int)(gcl / PIMG);
    const long q  = gcl % PIMG;
    const int gy  = (int)(q / PW) - 1;
    const int gx  = (int)(q % PW) - 1;
    const size_t prow = (size_t)GUARD + gcl;
    const float* offP = off + prow * 216;
    const float* xfb  = xf + ((size_t)GUARD + (size_t)b * PIMG) * 64;

    float acc[8][4];
#pragma unroll
    for (int nb = 0; nb < 8; ++nb)
#pragma unroll
        for (int j = 0; j < 4; ++j) acc[nb][j] = 0.f;

    const int l7 = lane & 7;
    const uint32_t aRow = (uint32_t)(warp * 16 + ((lane >> 3) & 1) * 8 + l7);
    const int aU = (lane >> 4) & 1;
    const int bKh = (lane >> 3) & 1;
    const int bNs = (lane >> 4) & 1;

    auto load_B = [&](int s) {
        const size_t wbase = (size_t)s * 64;
        const uint32_t dBH = sb + OFF_B + (s & 1) * 2 * BBUF;
        const uint32_t dBL = dBH + BBUF;
        for (int n = tid; n < 64; n += 256) {
            const char* swh = (const char*)(Whi + (wbase + n) * 64);
            const char* swl = (const char*)(Wlo + (wbase + n) * 64);
            uint32_t ro = (uint32_t)n * 128;
            uint32_t sx = ((uint32_t)n & 7) * 16;
#pragma unroll
            for (int i = 0; i < 8; ++i) {
                uint32_t o = ro + (((uint32_t)i * 16) ^ sx);
                cpasync16(dBH + o, swh + i * 16);
                cpasync16(dBL + o, swl + i * 16);
            }
        }
    };

    load_B(0); cpcommit();

    for (int s = 0; s < 9; ++s) {
        __syncthreads();                 // prior stage's A/B reads complete
        if (s + 1 < 9) load_B(s + 1);
        cpcommit();

        // ---- sample A(s): tap s, 4 dg per thread ----
        const int ky = s / 3, kx = s % 3;
        const uint32_t arow_sw = (uint32_t)p * 128;
        const uint32_t asx = ((uint32_t)p & 7) * 16;
#pragma unroll
        for (int d = 0; d < 4; ++d) {
            const int dg = dg0 + d;
            float dy = offP[dg * 18 + 2 * s + 0];
            float dx = offP[dg * 18 + 2 * s + 1];
            float ml = offP[144 + dg * 9 + s];
            float m  = 1.f / (1.f + __expf(-ml));

            float py = (float)gy - 1.f + (float)ky + dy;
            float px = (float)gx - 1.f + (float)kx + dx;
            float y0f = floorf(py), x0f = floorf(px);
            float wy = py - y0f, wx = px - x0f;
            int y0 = (int)y0f, x0 = (int)x0f;

            float cw00 = (1.f - wy) * (1.f - wx);
            float cw01 = (1.f - wy) * wx;
            float cw10 = wy * (1.f - wx);
            float cw11 = wy * wx;

            float sv[8];
#pragma unroll
            for (int i = 0; i < 8; ++i) sv[i] = 0.f;
#pragma unroll
            for (int cy = 0; cy < 2; ++cy) {
#pragma unroll
                for (int cx = 0; cx < 2; ++cx) {
                    int yy = y0 + cy, xx = x0 + cx;
                    float cwv = (cy == 0) ? ((cx == 0) ? cw00 : cw01)
                                          : ((cx == 0) ? cw10 : cw11);
                    if (yy >= 0 && yy < HH && xx >= 0 && xx < WW) {
                        const float4* ptr = reinterpret_cast<const float4*>(
                            xfb + ((size_t)(yy + 1) * PW + (xx + 1)) * 64 + dg * 8);
                        float4 a = __ldg(&ptr[0]);
                        float4 c = __ldg(&ptr[1]);
                        sv[0] += cwv * a.x; sv[1] += cwv * a.y;
                        sv[2] += cwv * a.z; sv[3] += cwv * a.w;
                        sv[4] += cwv * c.x; sv[5] += cwv * c.y;
                        sv[6] += cwv * c.z; sv[7] += cwv * c.w;
                    }
                }
            }
            // fold mask, split hi/lo, pack 8 bf16 = 16B
            uint32_t hp[4], lp[4];
#pragma unroll
            for (int i = 0; i < 4; ++i) {
                float v0 = sv[2 * i] * m, v1 = sv[2 * i + 1] * m;
                __nv_bfloat16 h0 = __float2bfloat16(v0);
                __nv_bfloat16 h1 = __float2bfloat16(v1);
                __nv_bfloat16 e0 = __float2bfloat16(v0 - __bfloat162float(h0));
                __nv_bfloat16 e1 = __float2bfloat16(v1 - __bfloat162float(h1));
                hp[i] = ((uint32_t)*(uint16_t*)&h1 << 16) | (uint32_t)*(uint16_t*)&h0;
                lp[i] = ((uint32_t)*(uint16_t*)&e1 << 16) | (uint32_t)*(uint16_t*)&e0;
            }
            uint32_t o = arow_sw + (((uint32_t)dg * 16) ^ asx);
            *(uint4*)(smem + OFF_A + o)        = make_uint4(hp[0], hp[1], hp[2], hp[3]);
            *(uint4*)(smem + OFF_A + ABUF + o) = make_uint4(lp[0], lp[1], lp[2], lp[3]);
        }

        cpwait1();
        __syncthreads();                 // A stores + B(s) visible

        const uint32_t aH = sb + OFF_A;
        const uint32_t aL = aH + ABUF;
        const uint32_t bH = sb + OFF_B + (s & 1) * 2 * BBUF;
        const uint32_t bL = bH + BBUF;

#pragma unroll
        for (int c = 0; c < 4; ++c) {
            uint32_t ahf[4], alf[4];
            uint32_t offA = aRow * 128 + ((uint32_t)((2 * c + aU) ^ l7)) * 16;
            ldsm_x4(ahf, aH + offA);
            ldsm_x4(alf, aL + offA);
#pragma unroll
            for (int nbp = 0; nbp < 4; ++nbp) {
                uint32_t row = (uint32_t)((nbp * 2 + bNs) * 8 + l7);
                uint32_t offb2 = row * 128 + ((uint32_t)((2 * c + bKh) ^ l7)) * 16;
                uint32_t bh[4], bl[4];
                ldsm_x4(bh, bH + offb2);
                ldsm_x4(bl, bL + offb2);
#pragma unroll
                for (int half = 0; half < 2; ++half) {
                    const int nb = nbp * 2 + half;
                    mma_bf16(acc[nb], ahf, bh + 2 * half);
                    mma_bf16(acc[nb], ahf, bl + 2 * half);
                    mma_bf16(acc[nb], alf, bh + 2 * half);
                }
            }
        }
    }

    // ---- epilogue ----
    const long gbase = m0 + warp * 16;
    const int ncol0 = 2 * (lane & 3);
#pragma unroll
    for (int half = 0; half < 2; ++half) {
        long g2 = gbase + (lane >> 2) + half * 8;
        bool valid = (g2 < MROWS);
        int b2 = 0, gy2 = 0, gx2 = 0;
        if (valid) {
            b2 = (int)(g2 / PIMG);
            long q2 = g2 % PIMG;
            gy2 = (int)(q2 / PW) - 1;
            gx2 = (int)(q2 % PW) - 1;
            valid = (gy2 >= 0) && (gy2 < HH) && (gx2 >= 0) && (gx2 < WW);
        }
        if (!valid) continue;
        const size_t orow = (size_t)(GUARD + g2);
#pragma unroll
        for (int nb = 0; nb < 8; ++nb) {
#pragma unroll
            for (int j = 0; j < 2; ++j) {
                const int oc = nb * 8 + ncol0 + j;
                float v = acc[nb][half * 2 + j] + sBias[oc];
                if (LRELU) v = (v >= 0.f) ? v : 0.1f * v;
                if (NCHW_OUT) {
                    outF[((size_t)(b2 * CC + oc)) * HWW + (size_t)gy2 * WW + gx2] = v;
                } else {
                    __nv_bfloat16 h = __float2bfloat16(v);
                    outHi[orow * 64 + oc] = h;
                    outLo[orow * 64 + oc] = __float2bfloat16(v - __bfloat162float(h));
                }
            }
        }
    }
}

// ---------------- launch ----------------
extern "C" void kernel_launch(void* const* d_in, const int* in_sizes, int n_in,
                              void* d_out, int out_size)
{
    const float* nbr     = (const float*)d_in[0];
    const float* ref     = (const float*)d_in[1];
    const float* oc1_w   = (const float*)d_in[2];
    const float* oc1_b   = (const float*)d_in[3];
    const float* oc2_w   = (const float*)d_in[4];
    const float* oc2_b   = (const float*)d_in[5];
    const float* d1off_w = (const float*)d_in[6];
    const float* d1off_b = (const float*)d_in[7];
    const float* dcn1_w  = (const float*)d_in[8];
    const float* dcn1_b  = (const float*)d_in[9];
    const float* fc_w    = (const float*)d_in[10];
    const float* fc_b    = (const float*)d_in[11];
    const float* cas1_w  = (const float*)d_in[12];
    const float* cas1_b  = (const float*)d_in[13];
    const float* cas2_w  = (const float*)d_in[14];
    const float* cas2_b  = (const float*)d_in[15];
    const float* cdoff_w = (const float*)d_in[16];
    const float* cdoff_b = (const float*)d_in[17];
    const float* casd_w  = (const float*)d_in[18];
    const float* casd_b  = (const float*)d_in[19];
    float* outp = (float*)d_out;

    float *xnbr, *xfc, *offb;
    __nv_bfloat16 *nh, *nl, *rh, *rl, *b1h, *b1l, *b2h, *b2l, *b3h, *b3l, *b4h, *b4l, *wh, *wl;
    cudaGetSymbolAddress((void**)&xnbr, g_xnbr);
    cudaGetSymbolAddress((void**)&xfc,  g_xfc);
    cudaGetSymbolAddress((void**)&offb, g_offb);
    cudaGetSymbolAddress((void**)&nh,  g_nbr_h); cudaGetSymbolAddress((void**)&nl, g_nbr_l);
    cudaGetSymbolAddress((void**)&rh,  g_ref_h); cudaGetSymbolAddress((void**)&rl, g_ref_l);
    cudaGetSymbolAddress((void**)&b1h, g_b1_h);  cudaGetSymbolAddress((void**)&b1l, g_b1_l);
    cudaGetSymbolAddress((void**)&b2h, g_b2_h);  cudaGetSymbolAddress((void**)&b2l, g_b2_l);
    cudaGetSymbolAddress((void**)&b3h, g_b3_h);  cudaGetSymbolAddress((void**)&b3l, g_b3_l);
    cudaGetSymbolAddress((void**)&b4h, g_b4_h);  cudaGetSymbolAddress((void**)&b4l, g_b4_l);
    cudaGetSymbolAddress((void**)&wh,  g_w_h);   cudaGetSymbolAddress((void**)&wl,  g_w_l);

    auto C64S2 = conv_mma_kernel<64, 64, 2, false, true,  true >;
    auto C64S1 = conv_mma_kernel<64, 64, 1, false, true,  true >;
    auto C216  = conv_mma_kernel<72, 216, 1, true,  false, false>;
    auto CFC   = conv_mma_kernel<64, 64, 1, true,  true,  false>;
    auto DCN1  = dcn_mma_kernel<false, false>;
    auto DCNC  = dcn_mma_kernel<true,  true >;

    const int smem64 = 1024 + 2 * (258 * 128) + 4 * 64 * 128;   // 99840
    const int smem72 = 1024 + 2 * (258 * 128) + 4 * 72 * 128;   // 103936
    const int smemD  = 1024 + 2 * (128 * 128) + 4 * 64 * 128;   // 66560
    cudaFuncSetAttribute(C64S2, cudaFuncAttributeMaxDynamicSharedMemorySize, smem64);
    cudaFuncSetAttribute(C64S1, cudaFuncAttributeMaxDynamicSharedMemorySize, smem64);
    cudaFuncSetAttribute(CFC,   cudaFuncAttributeMaxDynamicSharedMemorySize, smem64);
    cudaFuncSetAttribute(C216,  cudaFuncAttributeMaxDynamicSharedMemorySize, smem72);
    cudaFuncSetAttribute(DCN1,  cudaFuncAttributeMaxDynamicSharedMemorySize, smemD);
    cudaFuncSetAttribute(DCNC,  cudaFuncAttributeMaxDynamicSharedMemorySize, smemD);

    const int cvtGrid = (BB * HWW + 255) / 256;
    dim3 g64(NTIL256, 1), g216(NTIL256, 3);

    // 0) conversions + ALL weight preps up front
    convert_in_kernel<true ><<<cvtGrid, 256>>>(nbr, xnbr, nh, nl);
    convert_in_kernel<false><<<cvtGrid, 256>>>(ref, nullptr, rh, rl);
    weight_prep_kernel<<<(64 * 128 * 9 + 255) / 256, 256>>>(oc1_w,   64, 128, WOFF_OC1,   wh, wl);
    weight_prep_kernel<<<(64 * 64 * 9 + 255) / 256, 256>>>(oc2_w,    64, 64,  WOFF_OC2,   wh, wl);
    weight_prep_kernel<<<(216 * 64 * 9 + 255) / 256, 256>>>(d1off_w, 216, 64, WOFF_D1OFF, wh, wl);
    weight_prep_kernel<<<(64 * 64 * 9 + 255) / 256, 256>>>(fc_w,     64, 64,  WOFF_FC,    wh, wl);
    weight_prep_kernel<<<(64 * 128 * 9 + 255) / 256, 256>>>(cas1_w,  64, 128, WOFF_CAS1,  wh, wl);
    weight_prep_kernel<<<(64 * 64 * 9 + 255) / 256, 256>>>(cas2_w,   64, 64,  WOFF_CAS2,  wh, wl);
    weight_prep_kernel<<<(216 * 64 * 9 + 255) / 256, 256>>>(cdoff_w, 216, 64, WOFF_CDOFF, wh, wl);
    weight_prep_kernel<<<(64 * 64 * 9 + 255) / 256, 256>>>(dcn1_w,   64, 64,  WOFF_DCN1,  wh, wl);
    weight_prep_kernel<<<(64 * 64 * 9 + 255) / 256, 256>>>(casd_w,   64, 64,  WOFF_CASD,  wh, wl);

    // 1) offset = lrelu(conv(cat(nbr, ref), oc1))
    C64S2<<<g64, 256, smem64>>>(nh, nl, rh, rl, wh + WOFF_OC1, wl + WOFF_OC1, oc1_b, nullptr, b1h, b1l);
    // 2) offset = lrelu(conv(offset, oc2))
    C64S1<<<g64, 256, smem64>>>(b1h, b1l, nullptr, nullptr, wh + WOFF_OC2, wl + WOFF_OC2, oc2_b, nullptr, b2h, b2l);
    // 3) dcn1 offset/mask conv (216 ch, raw)
    C216<<<g216, 256, smem72>>>(b2h, b2l, nullptr, nullptr, wh + WOFF_D1OFF, wl + WOFF_D1OFF, d1off_b, offb, nullptr, nullptr);
    // 4) feat = dcn(nbr, off)  -> bf16 hi/lo NHWC (tensorized channel mix)
    DCN1<<<NTIL128, 256, smemD>>>(xnbr, offb, wh + WOFF_DCN1, wl + WOFF_DCN1, dcn1_b, nullptr, b3h, b3l);
    // 5) feat = conv(feat, fc) -> fp32 NHWC (gather src) + bf16 hi/lo
    CFC<<<g64, 256, smem64>>>(b3h, b3l, nullptr, nullptr, wh + WOFF_FC, wl + WOFF_FC, fc_b, xfc, b4h, b4l);
    // 6) offset = lrelu(conv(cat(feat, ref), cas1))
    C64S2<<<g64, 256, smem64>>>(b4h, b4l, rh, rl, wh + WOFF_CAS1, wl + WOFF_CAS1, cas1_b, nullptr, b1h, b1l);
    // 7) offset = lrelu(conv(offset, cas2))
    C64S1<<<g64, 256, smem64>>>(b1h, b1l, nullptr, nullptr, wh + WOFF_CAS2, wl + WOFF_CAS2, cas2_b, nullptr, b2h, b2l);
    // 8) casd offset/mask conv
    C216<<<g216, 256, smem72>>>(b2h, b2l, nullptr, nullptr, wh + WOFF_CDOFF, wl + WOFF_CDOFF, cdoff_b, offb, nullptr, nullptr);
    // 9) out = lrelu(dcn(feat, off)) -> NCHW fp32 (tensorized channel mix)
    DCNC<<<NTIL128, 256, smemD>>>(xfc, offb, wh + WOFF_CASD, wl + WOFF_CASD, casd_b, outp, nullptr, nullptr);

    (void)in_sizes; (void)n_in; (void)out_size;
}

// round 11
// speedup vs baseline: 3.8115x; 1.0253x over previous
#include <cuda_runtime.h>
#include <cuda_bf16.h>
#include <cstdint>

// ---------------- problem constants ----------------
#define BB 4
#define CC 64
#define HH 192
#define WW 192
#define HWW (HH*WW)
#define DG 8
#define CG 8
#define PW 194                      // padded width/height (H+2)
#define PIMG (PW*PW)                // 37636 padded pixels per image
#define MROWS (BB*PIMG)             // 150544 total padded pixels
#define GUARD 512                   // zero guard rows front
#define ROWSA (GUARD + MROWS + 1024)
#define NTIL256 ((MROWS + 255)/256) // 589
#define NTIL128 ((MROWS + 127)/128) // 1177

// ---------------- scratch (static device globals; zero-initialized) ----------------
__device__ __align__(256) float g_xnbr[(size_t)ROWSA * 64];          // padded NHWC fp32 (dcn1 gather)
__device__ __align__(256) float g_xfc [(size_t)ROWSA * 64];          // fc out fp32 (dcn2 gather)
__device__ __align__(256) float g_offb[(size_t)ROWSA * 216];         // offset conv out (NHWC)
__device__ __align__(256) __nv_bfloat16 g_nbr_h[(size_t)ROWSA*64], g_nbr_l[(size_t)ROWSA*64];
__device__ __align__(256) __nv_bfloat16 g_ref_h[(size_t)ROWSA*64], g_ref_l[(size_t)ROWSA*64];
__device__ __align__(256) __nv_bfloat16 g_b1_h [(size_t)ROWSA*64], g_b1_l [(size_t)ROWSA*64];
__device__ __align__(256) __nv_bfloat16 g_b2_h [(size_t)ROWSA*64], g_b2_l [(size_t)ROWSA*64];
__device__ __align__(256) __nv_bfloat16 g_b3_h [(size_t)ROWSA*64], g_b3_l [(size_t)ROWSA*64];
__device__ __align__(256) __nv_bfloat16 g_b4_h [(size_t)ROWSA*64], g_b4_l [(size_t)ROWSA*64];
// per-conv prepped weights (hi/lo), laid out back-to-back
#define WOFF_OC1   0
#define WOFF_OC2   (WOFF_OC1 + 9*2*64*64)
#define WOFF_D1OFF (WOFF_OC2 + 9*1*64*64)
#define WOFF_FC    (WOFF_D1OFF + 9*1*216*64)
#define WOFF_CAS1  (WOFF_FC + 9*1*64*64)
#define WOFF_CAS2  (WOFF_CAS1 + 9*2*64*64)
#define WOFF_CDOFF (WOFF_CAS2 + 9*1*64*64)
#define WOFF_DCN1  (WOFF_CDOFF + 9*1*216*64)
#define WOFF_CASD  (WOFF_DCN1 + 9*1*64*64)
#define WTOT       (WOFF_CASD + 9*1*64*64)
__device__ __align__(256) __nv_bfloat16 g_w_h[WTOT], g_w_l[WTOT];

// ---------------- PTX helpers (baseline ISA, compute_103-legal) ----------------
__device__ __forceinline__ uint32_t smem_u32(const void* p) {
    uint32_t a;
    asm("{ .reg .u64 t; cvta.to.shared.u64 t, %1; cvt.u32.u64 %0, t; }" : "=r"(a) : "l"(p));
    return a;
}
__device__ __forceinline__ void ldsm_x4(uint32_t* r, uint32_t a) {
    asm volatile("ldmatrix.sync.aligned.m8n8.x4.shared.b16 {%0,%1,%2,%3}, [%4];"
        : "=r"(r[0]), "=r"(r[1]), "=r"(r[2]), "=r"(r[3]) : "r"(a));
}
__device__ __forceinline__ void ldsm_x2(uint32_t* r, uint32_t a) {
    asm volatile("ldmatrix.sync.aligned.m8n8.x2.shared.b16 {%0,%1}, [%2];"
        : "=r"(r[0]), "=r"(r[1]) : "r"(a));
}
__device__ __forceinline__ void mma_bf16(float* c, const uint32_t* a, const uint32_t* b) {
    asm volatile(
        "mma.sync.aligned.m16n8k16.row.col.f32.bf16.bf16.f32 "
        "{%0,%1,%2,%3}, {%4,%5,%6,%7}, {%8,%9}, {%0,%1,%2,%3};"
        : "+f"(c[0]), "+f"(c[1]), "+f"(c[2]), "+f"(c[3])
        : "r"(a[0]), "r"(a[1]), "r"(a[2]), "r"(a[3]), "r"(b[0]), "r"(b[1]));
}
__device__ __forceinline__ void cpasync16(uint32_t dst, const void* src) {
    asm volatile("cp.async.cg.shared.global [%0], [%1], 16;" :: "r"(dst), "l"(src));
}
__device__ __forceinline__ void cpcommit() { asm volatile("cp.async.commit_group;" ::: "memory"); }
__device__ __forceinline__ void cpwait1()  { asm volatile("cp.async.wait_group 1;" ::: "memory"); }
__device__ __forceinline__ void cpwait0()  { asm volatile("cp.async.wait_group 0;" ::: "memory"); }

// ---------------- input conversion: NCHW fp32 -> padded NHWC (fp32 opt + bf16 hi/lo) ----------------
template<bool F32OUT>
__global__ void convert_in_kernel(const float* __restrict__ in, float* __restrict__ outF,
                                  __nv_bfloat16* __restrict__ hi, __nv_bfloat16* __restrict__ lo)
{
    int p = blockIdx.x * blockDim.x + threadIdx.x;
    if (p >= BB * HWW) return;
    int x = p % WW; int t = p / WW; int y = t % HH; int b = t / HH;
    size_t g = (size_t)GUARD + (size_t)b * PIMG + (size_t)(y + 1) * PW + (x + 1);
#pragma unroll
    for (int c = 0; c < 64; ++c) {
        float v = in[((size_t)(b * 64 + c)) * HWW + (size_t)y * WW + x];
        if (F32OUT) outF[g * 64 + c] = v;
        __nv_bfloat16 h = __float2bfloat16(v);
        hi[g * 64 + c] = h;
        lo[g * 64 + c] = __float2bfloat16(v - __bfloat162float(h));
    }
}

// ---------------- fused weight prep: all 10 convs in ONE launch ----------------
// OIHW fp32 -> [tap][seg][n][64k] bf16 hi/lo at per-conv offset. grid.y = conv idx.
struct WPrepArgs {
    const float* src[10];
    int O[10];
    int Cin[10];
    long woff[10];
};
__global__ void weight_prep_all_kernel(WPrepArgs a,
                                       __nv_bfloat16* __restrict__ whi,
                                       __nv_bfloat16* __restrict__ wlo)
{
    const int ci = blockIdx.y;
    const int O = a.O[ci], Cin = a.Cin[ci];
    const int n = O * Cin * 9;
    const float* __restrict__ w = a.src[ci];
    const long woff = a.woff[ci];
    for (int idx = blockIdx.x * blockDim.x + threadIdx.x; idx < n;
         idx += gridDim.x * blockDim.x) {
        int tap = idx % 9; int t = idx / 9; int cin = t % Cin; int o = t / Cin;
        float v = w[idx];
        int seg = cin >> 6, k = cin & 63;
        size_t dst = (size_t)woff + (((size_t)tap * (Cin >> 6) + seg) * O + o) * 64 + k;
        __nv_bfloat16 h = __float2bfloat16(v);
        whi[dst] = h;
        wlo[dst] = __float2bfloat16(v - __bfloat162float(h));
    }
}

// ---------------- conv as shifted-window implicit GEMM (bf16 3-term) ----------------
// Single-sync stage protocol: [wait0 -> sync -> prefetch B(s+1)+commit -> compute(s)];
// A panel single-buffered per superstage (extra sync only at its 6 reload points).
template<int NT, int NTOT, int SEGS, bool EPI_F32, bool EPI_BF16, bool LRELU>
__global__ __launch_bounds__(256, 2)
void conv_mma_kernel(const __nv_bfloat16* __restrict__ Ahi0, const __nv_bfloat16* __restrict__ Alo0,
                     const __nv_bfloat16* __restrict__ Ahi1, const __nv_bfloat16* __restrict__ Alo1,
                     const __nv_bfloat16* __restrict__ Whi, const __nv_bfloat16* __restrict__ Wlo,
                     const float* __restrict__ bias,
                     float* __restrict__ outF,
                     __nv_bfloat16* __restrict__ outHi, __nv_bfloat16* __restrict__ outLo)
{
    extern __shared__ __align__(1024) char smem[];
    constexpr int AROWS = 258;
    constexpr int ABUF  = AROWS * 128;
    constexpr int BBUF  = NT * 128;
    constexpr int OFF_A = 1024;
    constexpr int OFF_B = OFF_A + 2 * ABUF;
    constexpr int NB  = NT / 8;
    constexpr int NBP = NB / 2;
    constexpr bool NBODD = (NB & 1) != 0;
    constexpr int NSS = 3 * SEGS;
    constexpr int NST = 9 * SEGS;

    float* sBias = (float*)smem;
    const uint32_t sb = smem_u32(smem);

    const int tid  = threadIdx.x;
    const int lane = tid & 31;
    const int warp = tid >> 5;
    const int ocb  = blockIdx.y;
    const long m0  = (long)blockIdx.x * 256;

    for (int i = tid; i < NT; i += 256) sBias[i] = bias[ocb * NT + i];

    float acc[2][NB][4];
#pragma unroll
    for (int mt = 0; mt < 2; ++mt)
#pragma unroll
        for (int nb = 0; nb < NB; ++nb)
#pragma unroll
            for (int j = 0; j < 4; ++j) acc[mt][nb][j] = 0.f;

    const int l7 = lane & 7;
    const uint32_t aRow = (uint32_t)(warp * 32 + ((lane >> 3) & 1) * 8 + l7);
    const int aU = (lane >> 4) & 1;
    const int bKh = (lane >> 3) & 1;
    const int bNs = (lane >> 4) & 1;

    auto load_A = [&](int ss) {
        const int dy  = ss / SEGS;
        const int seg = ss % SEGS;
        const __nv_bfloat16* ah = (seg == 0) ? Ahi0 : Ahi1;
        const __nv_bfloat16* al = (seg == 0) ? Alo0 : Alo1;
        const long base = (long)GUARD + m0 + (long)(dy - 1) * PW - 1;
        const uint32_t dAH = sb + OFF_A;
        const uint32_t dAL = dAH + ABUF;
        for (int r = tid; r < AROWS; r += 256) {
            const char* srch = (const char*)(ah + (size_t)(base + r) * 64);
            const char* srcl = (const char*)(al + (size_t)(base + r) * 64);
            uint32_t ro = (uint32_t)r * 128;
            uint32_t sx = ((uint32_t)r & 7) * 16;
#pragma unroll
            for (int i = 0; i < 8; ++i) {
                uint32_t o = ro + (((uint32_t)i * 16) ^ sx);
                cpasync16(dAH + o, srch + i * 16);
                cpasync16(dAL + o, srcl + i * 16);
            }
        }
    };
    auto load_B = [&](int s) {
        const int ss = s / 3, dxi = s % 3;
        const int dy = ss / SEGS, seg = ss % SEGS;
        const int tap = dy * 3 + dxi;
        const size_t wbase = (((size_t)tap * SEGS + seg) * NTOT + (size_t)ocb * NT);
        const uint32_t dBH = sb + OFF_B + (s & 1) * 2 * BBUF;
        const uint32_t dBL = dBH + BBUF;
        for (int n = tid; n < NT; n += 256) {
            const char* swh = (const char*)(Whi + (wbase + n) * 64);
            const char* swl = (const char*)(Wlo + (wbase + n) * 64);
            uint32_t ro = (uint32_t)n * 128;
            uint32_t sx = ((uint32_t)n & 7) * 16;
#pragma unroll
            for (int i = 0; i < 8; ++i) {
                uint32_t o = ro + (((uint32_t)i * 16) ^ sx);
                cpasync16(dBH + o, swh + i * 16);
                cpasync16(dBL + o, swl + i * 16);
            }
        }
    };

    // preamble: group0 = {A(0), B(0)}
    load_A(0); load_B(0); cpcommit();

    for (int s = 0; s < NST; ++s) {
        const int ss = s / 3, dxi = s % 3;

        cpwait0();          // drain B(s) (+ A(ss) if just reloaded) — committed >=1 stage ago
        __syncthreads();    // data visible; all warps past compute(s-1)

        if (s + 1 < NST) load_B(s + 1);   // target buffer (s+1)&1 dead: read at s-1, all warps synced
        cpcommit();

        const uint32_t aH = sb + OFF_A;
        const uint32_t aL = aH + ABUF;
        const uint32_t bH = sb + OFF_B + (s & 1) * 2 * BBUF;
        const uint32_t bL = bH + BBUF;
        const uint32_t krow = (uint32_t)((l7 + dxi) & 7);

#pragma unroll
        for (int c = 0; c < 4; ++c) {
            uint32_t ahf[2][4], alf[2][4];
#pragma unroll
            for (int mt = 0; mt < 2; ++mt) {
                uint32_t row = aRow + mt * 16 + dxi;
                uint32_t off = row * 128 + ((uint32_t)((2 * c + aU)) ^ krow) * 16;
                ldsm_x4(ahf[mt], aH + off);
                ldsm_x4(alf[mt], aL + off);
            }
#pragma unroll
            for (int nbp = 0; nbp < NBP; ++nbp) {
                uint32_t row = (uint32_t)((nbp * 2 + bNs) * 8 + l7);
                uint32_t offb = row * 128 + ((uint32_t)((2 * c + bKh) ^ l7)) * 16;
                uint32_t bh[4], bl[4];
                ldsm_x4(bh, bH + offb);
                ldsm_x4(bl, bL + offb);
#pragma unroll
                for (int half = 0; half < 2; ++half) {
                    const int nb = nbp * 2 + half;
                    mma_bf16(acc[0][nb], ahf[0], bh + 2 * half);
                    mma_bf16(acc[1][nb], ahf[1], bh + 2 * half);
                    mma_bf16(acc[0][nb], ahf[0], bl + 2 * half);
                    mma_bf16(acc[1][nb], ahf[1], bl + 2 * half);
                    mma_bf16(acc[0][nb], alf[0], bh + 2 * half);
                    mma_bf16(acc[1][nb], alf[1], bh + 2 * half);
                }
            }
            if (NBODD) {
                const int nb = NB - 1;
                uint32_t row = (uint32_t)(nb * 8 + l7);
                uint32_t offb = row * 128 + ((uint32_t)((2 * c + bKh) ^ l7)) * 16;
                uint32_t bh[2], bl[2];
                ldsm_x2(bh, bH + offb);
                ldsm_x2(bl, bL + offb);
                mma_bf16(acc[0][nb], ahf[0], bh);
                mma_bf16(acc[1][nb], ahf[1], bh);
                mma_bf16(acc[0][nb], ahf[0], bl);
                mma_bf16(acc[1][nb], ahf[1], bl);
                mma_bf16(acc[0][nb], alf[0], bh);
                mma_bf16(acc[1][nb], alf[1], bh);
            }
        }

        // reload single-buffered A at superstage boundary (guarded by its own sync)
        if (dxi == 2 && ss + 1 < NSS) {
            __syncthreads();    // all warps done reading A(ss)
            load_A(ss + 1);
            cpcommit();         // drained by wait0 of next stage
        }
    }

    // ---- epilogue ----
    const long gbase = m0 + warp * 32;
    const int ncol0 = 2 * (lane & 3);
#pragma unroll
    for (int mt = 0; mt < 2; ++mt) {
#pragma unroll
        for (int half = 0; half < 2; ++half) {
            long g = gbase + mt * 16 + (lane >> 2) + half * 8;
            bool valid = (g < MROWS);
            if (valid) {
                long q = g % PIMG;
                int py = (int)(q / PW), px = (int)(q % PW);
                valid = (py >= 1) && (py < PW - 1) && (px >= 1) && (px < PW - 1);
            }
            if (!valid) continue;
            const size_t orow = (size_t)(GUARD + g);
#pragma unroll
            for (int nb = 0; nb < NB; ++nb) {
                float v0 = acc[mt][nb][half * 2 + 0] + sBias[nb * 8 + ncol0];
                float v1 = acc[mt][nb][half * 2 + 1] + sBias[nb * 8 + ncol0 + 1];
                if (LRELU) {
                    v0 = (v0 >= 0.f) ? v0 : 0.1f * v0;
                    v1 = (v1 >= 0.f) ? v1 : 0.1f * v1;
                }
                const size_t col = (size_t)ocb * NT + nb * 8 + ncol0;
                if (EPI_F32) {
                    outF[orow * NTOT + col]     = v0;
                    outF[orow * NTOT + col + 1] = v1;
                }
                if (EPI_BF16) {
                    __nv_bfloat16 h0 = __float2bfloat16(v0);
                    __nv_bfloat16 h1 = __float2bfloat16(v1);
                    outHi[orow * NTOT + col]     = h0;
                    outHi[orow * NTOT + col + 1] = h1;
                    outLo[orow * NTOT + col]     = __float2bfloat16(v0 - __bfloat162float(h0));
                    outLo[orow * NTOT + col + 1] = __float2bfloat16(v1 - __bfloat162float(h1));
                }
            }
        }
    }
}

// ---------------- DCNv2 via MMA: sampling (scalar) + channel mix (tensor) ----------------
template<bool LRELU, bool NCHW_OUT>
__global__ __launch_bounds__(256, 2)
void dcn_mma_kernel(const float* __restrict__ xf,
                    const float* __restrict__ off,
                    const __nv_bfloat16* __restrict__ Whi, const __nv_bfloat16* __restrict__ Wlo,
                    const float* __restrict__ bias,
                    float* __restrict__ outF,
                    __nv_bfloat16* __restrict__ outHi, __nv_bfloat16* __restrict__ outLo)
{
    extern __shared__ __align__(1024) char smem[];
    constexpr int ABUF  = 128 * 128;
    constexpr int BBUF  = 64 * 128;
    constexpr int OFF_A = 1024;
    constexpr int OFF_B = OFF_A + 2 * ABUF;

    float* sBias = (float*)smem;
    const uint32_t sb = smem_u32(smem);

    const int tid  = threadIdx.x;
    const int lane = tid & 31;
    const int warp = tid >> 5;
    const long m0  = (long)blockIdx.x * 128;

    if (tid < 64) sBias[tid] = bias[tid];

    const int p   = tid >> 1;
    const int dg0 = (tid & 1) * 4;
    const long g  = m0 + p;
    const long gcl = (g < MROWS) ? g : 0;
    const int b   = (int)(gcl / PIMG);
    const long q  = gcl % PIMG;
    const int gy  = (int)(q / PW) - 1;
    const int gx  = (int)(q % PW) - 1;
    const size_t prow = (size_t)GUARD + gcl;
    const float* offP = off + prow * 216;
    const float* xfb  = xf + ((size_t)GUARD + (size_t)b * PIMG) * 64;

    float acc[8][4];
#pragma unroll
    for (int nb = 0; nb < 8; ++nb)
#pragma unroll
        for (int j = 0; j < 4; ++j) acc[nb][j] = 0.f;

    const int l7 = lane & 7;
    const uint32_t aRow = (uint32_t)(warp * 16 + ((lane >> 3) & 1) * 8 + l7);
    const int aU = (lane >> 4) & 1;
    const int bKh = (lane >> 3) & 1;
    const int bNs = (lane >> 4) & 1;

    auto load_B = [&](int s) {
        const size_t wbase = (size_t)s * 64;
        const uint32_t dBH = sb + OFF_B + (s & 1) * 2 * BBUF;
        const uint32_t dBL = dBH + BBUF;
        for (int n = tid; n < 64; n += 256) {
            const char* swh = (const char*)(Whi + (wbase + n) * 64);
            const char* swl = (const char*)(Wlo + (wbase + n) * 64);
            uint32_t ro = (uint32_t)n * 128;
            uint32_t sx = ((uint32_t)n & 7) * 16;
#pragma unroll
            for (int i = 0; i < 8; ++i) {
                uint32_t o = ro + (((uint32_t)i * 16) ^ sx);
                cpasync16(dBH + o, swh + i * 16);
                cpasync16(dBL + o, swl + i * 16);
            }
        }
    };

    load_B(0); cpcommit();

    for (int s = 0; s < 9; ++s) {
        __syncthreads();
        if (s + 1 < 9) load_B(s + 1);
        cpcommit();

        const int ky = s / 3, kx = s % 3;
        const uint32_t arow_sw = (uint32_t)p * 128;
        const uint32_t asx = ((uint32_t)p & 7) * 16;
#pragma unroll
        for (int d = 0; d < 4; ++d) {
            const int dg = dg0 + d;
            float dy = offP[dg * 18 + 2 * s + 0];
            float dx = offP[dg * 18 + 2 * s + 1];
            float ml = offP[144 + dg * 9 + s];
            float m  = 1.f / (1.f + __expf(-ml));

            float py = (float)gy - 1.f + (float)ky + dy;
            float px = (float)gx - 1.f + (float)kx + dx;
            float y0f = floorf(py), x0f = floorf(px);
            float wy = py - y0f, wx = px - x0f;
            int y0 = (int)y0f, x0 = (int)x0f;

            float cw00 = (1.f - wy) * (1.f - wx);
            float cw01 = (1.f - wy) * wx;
            float cw10 = wy * (1.f - wx);
            float cw11 = wy * wx;

            float sv[8];
#pragma unroll
            for (int i = 0; i < 8; ++i) sv[i] = 0.f;
#pragma unroll
            for (int cy = 0; cy < 2; ++cy) {
#pragma unroll
                for (int cx = 0; cx < 2; ++cx) {
                    int yy = y0 + cy, xx = x0 + cx;
                    float cwv = (cy == 0) ? ((cx == 0) ? cw00 : cw01)
                                          : ((cx == 0) ? cw10 : cw11);
                    if (yy >= 0 && yy < HH && xx >= 0 && xx < WW) {
                        const float4* ptr = reinterpret_cast<const float4*>(
                            xfb + ((size_t)(yy + 1) * PW + (xx + 1)) * 64 + dg * 8);
                        float4 a = __ldg(&ptr[0]);
                        float4 c = __ldg(&ptr[1]);
                        sv[0] += cwv * a.x; sv[1] += cwv * a.y;
                        sv[2] += cwv * a.z; sv[3] += cwv * a.w;
                        sv[4] += cwv * c.x; sv[5] += cwv * c.y;
                        sv[6] += cwv * c.z; sv[7] += cwv * c.w;
                    }
                }
            }
            uint32_t hp[4], lp[4];
#pragma unroll
            for (int i = 0; i < 4; ++i) {
                float v0 = sv[2 * i] * m, v1 = sv[2 * i + 1] * m;
                __nv_bfloat16 h0 = __float2bfloat16(v0);
                __nv_bfloat16 h1 = __float2bfloat16(v1);
                __nv_bfloat16 e0 = __float2bfloat16(v0 - __bfloat162float(h0));
                __nv_bfloat16 e1 = __float2bfloat16(v1 - __bfloat162float(h1));
                hp[i] = ((uint32_t)*(uint16_t*)&h1 << 16) | (uint32_t)*(uint16_t*)&h0;
                lp[i] = ((uint32_t)*(uint16_t*)&e1 << 16) | (uint32_t)*(uint16_t*)&e0;
            }
            uint32_t o = arow_sw + (((uint32_t)dg * 16) ^ asx);
            *(uint4*)(smem + OFF_A + o)        = make_uint4(hp[0], hp[1], hp[2], hp[3]);
            *(uint4*)(smem + OFF_A + ABUF + o) = make_uint4(lp[0], lp[1], lp[2], lp[3]);
        }

        cpwait1();
        __syncthreads();

        const uint32_t aH = sb + OFF_A;
        const uint32_t aL = aH + ABUF;
        const uint32_t bH = sb + OFF_B + (s & 1) * 2 * BBUF;
        const uint32_t bL = bH + BBUF;

#pragma unroll
        for (int c = 0; c < 4; ++c) {
            uint32_t ahf[4], alf[4];
            uint32_t offA = aRow * 128 + ((uint32_t)((2 * c + aU) ^ l7)) * 16;
            ldsm_x4(ahf, aH + offA);
            ldsm_x4(alf, aL + offA);
#pragma unroll
            for (int nbp = 0; nbp < 4; ++nbp) {
                uint32_t row = (uint32_t)((nbp * 2 + bNs) * 8 + l7);
                uint32_t offb2 = row * 128 + ((uint32_t)((2 * c + bKh) ^ l7)) * 16;
                uint32_t bh[4], bl[4];
                ldsm_x4(bh, bH + offb2);
                ldsm_x4(bl, bL + offb2);
#pragma unroll
                for (int half = 0; half < 2; ++half) {
                    const int nb = nbp * 2 + half;
                    mma_bf16(acc[nb], ahf, bh + 2 * half);
                    mma_bf16(acc[nb], ahf, bl + 2 * half);
                    mma_bf16(acc[nb], alf, bh + 2 * half);
                }
            }
        }
    }

    const long gbase = m0 + warp * 16;
    const int ncol0 = 2 * (lane & 3);
#pragma unroll
    for (int half = 0; half < 2; ++half) {
        long g2 = gbase + (lane >> 2) + half * 8;
        bool valid = (g2 < MROWS);
        int b2 = 0, gy2 = 0, gx2 = 0;
        if (valid) {
            b2 = (int)(g2 / PIMG);
            long q2 = g2 % PIMG;
            gy2 = (int)(q2 / PW) - 1;
            gx2 = (int)(q2 % PW) - 1;
            valid = (gy2 >= 0) && (gy2 < HH) && (gx2 >= 0) && (gx2 < WW);
        }
        if (!valid) continue;
        const size_t orow = (size_t)(GUARD + g2);
#pragma unroll
        for (int nb = 0; nb < 8; ++nb) {
#pragma unroll
            for (int j = 0; j < 2; ++j) {
                const int oc = nb * 8 + ncol0 + j;
                float v = acc[nb][half * 2 + j] + sBias[oc];
                if (LRELU) v = (v >= 0.f) ? v : 0.1f * v;
                if (NCHW_OUT) {
                    outF[((size_t)(b2 * CC + oc)) * HWW + (size_t)gy2 * WW + gx2] = v;
                } else {
                    __nv_bfloat16 h = __float2bfloat16(v);
                    outHi[orow * 64 + oc] = h;
                    outLo[orow * 64 + oc] = __float2bfloat16(v - __bfloat162float(h));
                }
            }
        }
    }
}

// ---------------- launch ----------------
extern "C" void kernel_launch(void* const* d_in, const int* in_sizes, int n_in,
                              void* d_out, int out_size)
{
    const float* nbr     = (const float*)d_in[0];
    const float* ref     = (const float*)d_in[1];
    const float* oc1_w   = (const float*)d_in[2];
    const float* oc1_b   = (const float*)d_in[3];
    const float* oc2_w   = (const float*)d_in[4];
    const float* oc2_b   = (const float*)d_in[5];
    const float* d1off_w = (const float*)d_in[6];
    const float* d1off_b = (const float*)d_in[7];
    const float* dcn1_w  = (const float*)d_in[8];
    const float* dcn1_b  = (const float*)d_in[9];
    const float* fc_w    = (const float*)d_in[10];
    const float* fc_b    = (const float*)d_in[11];
    const float* cas1_w  = (const float*)d_in[12];
    const float* cas1_b  = (const float*)d_in[13];
    const float* cas2_w  = (const float*)d_in[14];
    const float* cas2_b  = (const float*)d_in[15];
    const float* cdoff_w = (const float*)d_in[16];
    const float* cdoff_b = (const float*)d_in[17];
    const float* casd_w  = (const float*)d_in[18];
    const float* casd_b  = (const float*)d_in[19];
    float* outp = (float*)d_out;

    float *xnbr, *xfc, *offb;
    __nv_bfloat16 *nh, *nl, *rh, *rl, *b1h, *b1l, *b2h, *b2l, *b3h, *b3l, *b4h, *b4l, *wh, *wl;
    cudaGetSymbolAddress((void**)&xnbr, g_xnbr);
    cudaGetSymbolAddress((void**)&xfc,  g_xfc);
    cudaGetSymbolAddress((void**)&offb, g_offb);
    cudaGetSymbolAddress((void**)&nh,  g_nbr_h); cudaGetSymbolAddress((void**)&nl, g_nbr_l);
    cudaGetSymbolAddress((void**)&rh,  g_ref_h); cudaGetSymbolAddress((void**)&rl, g_ref_l);
    cudaGetSymbolAddress((void**)&b1h, g_b1_h);  cudaGetSymbolAddress((void**)&b1l, g_b1_l);
    cudaGetSymbolAddress((void**)&b2h, g_b2_h);  cudaGetSymbolAddress((void**)&b2l, g_b2_l);
    cudaGetSymbolAddress((void**)&b3h, g_b3_h);  cudaGetSymbolAddress((void**)&b3l, g_b3_l);
    cudaGetSymbolAddress((void**)&b4h, g_b4_h);  cudaGetSymbolAddress((void**)&b4l, g_b4_l);
    cudaGetSymbolAddress((void**)&wh,  g_w_h);   cudaGetSymbolAddress((void**)&wl,  g_w_l);

    auto C64S2 = conv_mma_kernel<64, 64, 2, false, true,  true >;
    auto C64S1 = conv_mma_kernel<64, 64, 1, false, true,  true >;
    auto C216  = conv_mma_kernel<72, 216, 1, true,  false, false>;
    auto CFC   = conv_mma_kernel<64, 64, 1, true,  true,  false>;
    auto DCN1  = dcn_mma_kernel<false, false>;
    auto DCNC  = dcn_mma_kernel<true,  true >;

    const int smem64 = 1024 + 2 * (258 * 128) + 4 * 64 * 128;   // 99840
    const int smem72 = 1024 + 2 * (258 * 128) + 4 * 72 * 128;   // 103936
    const int smemD  = 1024 + 2 * (128 * 128) + 4 * 64 * 128;   // 66560
    cudaFuncSetAttribute(C64S2, cudaFuncAttributeMaxDynamicSharedMemorySize, smem64);
    cudaFuncSetAttribute(C64S1, cudaFuncAttributeMaxDynamicSharedMemorySize, smem64);
    cudaFuncSetAttribute(CFC,   cudaFuncAttributeMaxDynamicSharedMemorySize, smem64);
    cudaFuncSetAttribute(C216,  cudaFuncAttributeMaxDynamicSharedMemorySize, smem72);
    cudaFuncSetAttribute(DCN1,  cudaFuncAttributeMaxDynamicSharedMemorySize, smemD);
    cudaFuncSetAttribute(DCNC,  cudaFuncAttributeMaxDynamicSharedMemorySize, smemD);

    const int cvtGrid = (BB * HWW + 255) / 256;
    dim3 g64(NTIL256, 1), g216(NTIL256, 3);

    // 0) conversions + fused weight prep (one launch for all 10 weight sets)
    convert_in_kernel<true ><<<cvtGrid, 256>>>(nbr, xnbr, nh, nl);
    convert_in_kernel<false><<<cvtGrid, 256>>>(ref, nullptr, rh, rl);
    {
        WPrepArgs a;
        a.src[0] = oc1_w;   a.O[0] = 64;  a.Cin[0] = 128; a.woff[0] = WOFF_OC1;
        a.src[1] = oc2_w;   a.O[1] = 64;  a.Cin[1] = 64;  a.woff[1] = WOFF_OC2;
        a.src[2] = d1off_w; a.O[2] = 216; a.Cin[2] = 64;  a.woff[2] = WOFF_D1OFF;
        a.src[3] = fc_w;    a.O[3] = 64;  a.Cin[3] = 64;  a.woff[3] = WOFF_FC;
        a.src[4] = cas1_w;  a.O[4] = 64;  a.Cin[4] = 128; a.woff[4] = WOFF_CAS1;
        a.src[5] = cas2_w;  a.O[5] = 64;  a.Cin[5] = 64;  a.woff[5] = WOFF_CAS2;
        a.src[6] = cdoff_w; a.O[6] = 216; a.Cin[6] = 64;  a.woff[6] = WOFF_CDOFF;
        a.src[7] = dcn1_w;  a.O[7] = 64;  a.Cin[7] = 64;  a.woff[7] = WOFF_DCN1;
        a.src[8] = casd_w;  a.O[8] = 64;  a.Cin[8] = 64;  a.woff[8] = WOFF_CASD;
        a.src[9] = casd_w;  a.O[9] = 0;   a.Cin[9] = 64;  a.woff[9] = WOFF_CASD; // unused slot
        dim3 gW(64, 10);
        weight_prep_all_kernel<<<gW, 256>>>(a, wh, wl);
    }

    // 1) offset = lrelu(conv(cat(nbr, ref), oc1))
    C64S2<<<g64, 256, smem64>>>(nh, nl, rh, rl, wh + WOFF_OC1, wl + WOFF_OC1, oc1_b, nullptr, b1h, b1l);
    // 2) offset = lrelu(conv(offset, oc2))
    C64S1<<<g64, 256, smem64>>>(b1h, b1l, nullptr, nullptr, wh + WOFF_OC2, wl + WOFF_OC2, oc2_b, nullptr, b2h, b2l);
    // 3) dcn1 offset/mask conv (216 ch, raw)
    C216<<<g216, 256, smem72>>>(b2h, b2l, nullptr, nullptr, wh + WOFF_D1OFF, wl + WOFF_D1OFF, d1off_b, offb, nullptr, nullptr);
    // 4) feat = dcn(nbr, off)  -> bf16 hi/lo NHWC (tensorized channel mix)
    DCN1<<<NTIL128, 256, smemD>>>(xnbr, offb, wh + WOFF_DCN1, wl + WOFF_DCN1, dcn1_b, nullptr, b3h, b3l);
    // 5) feat = conv(feat, fc) -> fp32 NHWC (gather src) + bf16 hi/lo
    CFC<<<g64, 256, smem64>>>(b3h, b3l, nullptr, nullptr, wh + WOFF_FC, wl + WOFF_FC, fc_b, xfc, b4h, b4l);
    // 6) offset = lrelu(conv(cat(feat, ref), cas1))
    C64S2<<<g64, 256, smem64>>>(b4h, b4l, rh, rl, wh + WOFF_CAS1, wl + WOFF_CAS1, cas1_b, nullptr, b1h, b1l);
    // 7) offset = lrelu(conv(offset, cas2))
    C64S1<<<g64, 256, smem64>>>(b1h, b1l, nullptr, nullptr, wh + WOFF_CAS2, wl + WOFF_CAS2, cas2_b, nullptr, b2h, b2l);
    // 8) casd offset/mask conv
    C216<<<g216, 256, smem72>>>(b2h, b2l, nullptr, nullptr, wh + WOFF_CDOFF, wl + WOFF_CDOFF, cdoff_b, offb, nullptr, nullptr);
    // 9) out = lrelu(dcn(feat, off)) -> NCHW fp32 (tensorized channel mix)
    DCNC<<<NTIL128, 256, smemD>>>(xfc, offb, wh + WOFF_CASD, wl + WOFF_CASD, casd_b, outp, nullptr, nullptr);

    (void)in_sizes; (void)n_in; (void)out_size;
}